// round 1
// baseline (speedup 1.0000x reference)
#include <cuda_runtime.h>
#include <math.h>

// ---------------- problem constants ----------------
#define NN   8192   // nodes
#define FF   128    // in features
#define HH   256    // hidden
#define GG   256    // graphs
#define NPG  32     // nodes per graph
#define EPSB 1e-5f

// ---------------- scratch (device globals; no allocs allowed) ----------------
__device__ float g_ax   [NN * FF];   // adj @ x
__device__ float g_tmp1 [NN * HH];   // x@Ws1 + b1
__device__ float g_pre1 [NN * HH];   // relu(ax@W1 + tmp1) -> in-place BN -> h1
__device__ float g_g2in [NN * HH];   // h1 @ W2
__device__ float g_tmp2 [NN * HH];   // h1@Ws2 + b2
__device__ float g_pre2 [NN * HH];   // relu(adj@g2in + tmp2) -> in-place BN -> h2
__device__ float g_pool [GG * 1024];
__device__ float g_bnp  [GG * 1024];
__device__ float g_l1   [GG * 512];
__device__ float g_bn1  [GG * 512];
__device__ float g_l2   [GG * 256];
__device__ float g_psum [64 * HH];
__device__ float g_psq  [64 * HH];
__device__ float g_scale[HH];
__device__ float g_shift[HH];

// ---------------- generic fp32 SGEMM: C = op(A[M,K] @ B[K,N] (+Add) (+bias)) ----------------
// BM=128, BN=64, BK=16, TM=8, TN=4, 256 threads. All dims must divide the tiles
// (true for every GEMM here: M in {8192,256}, N in {64..512 multiples of 64}, K mult of 16).
template <bool BIAS, bool ADD, bool RELU>
__global__ void __launch_bounds__(256, 3)
sgemm_k(const float* __restrict__ A, const float* __restrict__ B,
        float* __restrict__ C, const float* __restrict__ bias,
        const float* __restrict__ Add, int M, int N, int K)
{
    constexpr int BM = 128, BN = 64, BK = 16, TM = 8, TN = 4;
    __shared__ float As[BK][BM];
    __shared__ float Bs[BK][BN];

    const int tid = threadIdx.x;
    const int bx  = blockIdx.x;   // N tiles
    const int by  = blockIdx.y;   // M tiles

    // A loader: 2 float4 per thread (row = tid/2, col half = (tid%2)*8)
    const int aRow = tid >> 1;
    const int aCol = (tid & 1) * 8;
    const float* Ag = A + (size_t)(by * BM + aRow) * K + aCol;
    // B loader: 1 float4 per thread
    const int bRow = tid >> 4;
    const int bCol = (tid & 15) * 4;
    const float* Bg = B + (size_t)bRow * N + bx * BN + bCol;

    const int tr = (tid >> 4) * TM;   // 0..120
    const int tc = (tid & 15) * TN;   // 0..60

    float acc[TM][TN];
#pragma unroll
    for (int i = 0; i < TM; i++)
#pragma unroll
        for (int j = 0; j < TN; j++) acc[i][j] = 0.f;

    for (int k0 = 0; k0 < K; k0 += BK) {
        float4 a0 = *(const float4*)(Ag + k0);
        float4 a1 = *(const float4*)(Ag + k0 + 4);
        As[aCol + 0][aRow] = a0.x;  As[aCol + 1][aRow] = a0.y;
        As[aCol + 2][aRow] = a0.z;  As[aCol + 3][aRow] = a0.w;
        As[aCol + 4][aRow] = a1.x;  As[aCol + 5][aRow] = a1.y;
        As[aCol + 6][aRow] = a1.z;  As[aCol + 7][aRow] = a1.w;
        *(float4*)&Bs[bRow][bCol] = *(const float4*)(Bg + (size_t)k0 * N);
        __syncthreads();

#pragma unroll
        for (int k = 0; k < BK; k++) {
            float ra[TM], rb[TN];
#pragma unroll
            for (int i = 0; i < TM; i++) ra[i] = As[k][tr + i];
#pragma unroll
            for (int j = 0; j < TN; j++) rb[j] = Bs[k][tc + j];
#pragma unroll
            for (int i = 0; i < TM; i++)
#pragma unroll
                for (int j = 0; j < TN; j++) acc[i][j] = fmaf(ra[i], rb[j], acc[i][j]);
        }
        __syncthreads();
    }

    // epilogue
    float4 bv = make_float4(0.f, 0.f, 0.f, 0.f);
    if (BIAS) bv = *(const float4*)(bias + bx * BN + tc);
#pragma unroll
    for (int i = 0; i < TM; i++) {
        const size_t off = (size_t)(by * BM + tr + i) * N + bx * BN + tc;
        float4 v = make_float4(acc[i][0], acc[i][1], acc[i][2], acc[i][3]);
        if (ADD) {
            float4 ad = *(const float4*)(Add + off);
            v.x += ad.x; v.y += ad.y; v.z += ad.z; v.w += ad.w;
        }
        if (BIAS) { v.x += bv.x; v.y += bv.y; v.z += bv.z; v.w += bv.w; }
        if (RELU) {
            v.x = fmaxf(v.x, 0.f); v.y = fmaxf(v.y, 0.f);
            v.z = fmaxf(v.z, 0.f); v.w = fmaxf(v.w, 0.f);
        }
        *(float4*)(C + off) = v;
    }
}

// ---------------- BatchNorm over 8192 rows x 256 cols (training-mode stats) ----------------
__global__ void bn_partial_k(const float* __restrict__ x, float* __restrict__ psum,
                             float* __restrict__ psq)
{
    const int t = threadIdx.x;                // column (256)
    const float* p = x + (size_t)blockIdx.x * 128 * HH + t;
    float s = 0.f, q = 0.f;
#pragma unroll 4
    for (int r = 0; r < 128; r++) { float v = p[(size_t)r * HH]; s += v; q += v * v; }
    psum[blockIdx.x * HH + t] = s;
    psq [blockIdx.x * HH + t] = q;
}

__global__ void bn_finalize_k(const float* __restrict__ psum, const float* __restrict__ psq,
                              const float* __restrict__ gamma, const float* __restrict__ beta,
                              float* __restrict__ scale, float* __restrict__ shift)
{
    const int t = threadIdx.x;
    float s = 0.f, q = 0.f;
#pragma unroll
    for (int b = 0; b < 64; b++) { s += psum[b * HH + t]; q += psq[b * HH + t]; }
    const float invn = 1.f / (float)NN;
    const float m = s * invn;
    const float var = q * invn - m * m;
    const float sc = gamma[t] * rsqrtf(var + EPSB);
    scale[t] = sc;
    shift[t] = beta[t] - m * sc;
}

__global__ void bn_apply_k(float* __restrict__ x, const float* __restrict__ scale,
                           const float* __restrict__ shift)
{
    const int i = blockIdx.x * blockDim.x + threadIdx.x;   // over total/4
    const int c = (i * 4) & (HH - 1);
    float4 v = ((float4*)x)[i];
    v.x = fmaf(v.x, scale[c + 0], shift[c + 0]);
    v.y = fmaf(v.y, scale[c + 1], shift[c + 1]);
    v.z = fmaf(v.z, scale[c + 2], shift[c + 2]);
    v.w = fmaf(v.w, scale[c + 3], shift[c + 3]);
    ((float4*)x)[i] = v;
}

// ---------------- per-graph max/mean pooling (32 consecutive nodes per graph) ----------------
__global__ void pool_k(const float* __restrict__ h1, const float* __restrict__ h2,
                       float* __restrict__ pooled)
{
    const int g = blockIdx.x;       // 256 graphs
    const int t = threadIdx.x;      // 256 cols
    const size_t r0 = (size_t)g * NPG;
    float mx1 = -1e30f, mx2 = -1e30f, s1 = 0.f, s2 = 0.f;
#pragma unroll 4
    for (int r = 0; r < NPG; r++) {
        float v1 = h1[(r0 + r) * HH + t];
        float v2 = h2[(r0 + r) * HH + t];
        mx1 = fmaxf(mx1, v1); s1 += v1;
        mx2 = fmaxf(mx2, v2); s2 += v2;
    }
    float* out = pooled + (size_t)g * 1024;
    out[t]        = mx1;
    out[256 + t]  = mx2;
    out[512 + t]  = s1 * (1.f / NPG);
    out[768 + t]  = s2 * (1.f / NPG);
}

// ---------------- small BN (256 rows, one thread per column) ----------------
__global__ void bn_small_k(const float* __restrict__ in, const float* __restrict__ gamma,
                           const float* __restrict__ beta, float* __restrict__ out, int C)
{
    const int c = blockIdx.x * blockDim.x + threadIdx.x;
    if (c >= C) return;
    float s = 0.f, q = 0.f;
    for (int r = 0; r < GG; r++) { float v = in[(size_t)r * C + c]; s += v; q += v * v; }
    const float m = s * (1.f / GG);
    const float var = q * (1.f / GG) - m * m;
    const float sc = gamma[c] * rsqrtf(var + EPSB);
    const float sh = beta[c] - m * sc;
    for (int r = 0; r < GG; r++) out[(size_t)r * C + c] = fmaf(in[(size_t)r * C + c], sc, sh);
}

// ---------------- tiny dense: C[M,N] = A[M,K]@W[K,N] + b ----------------
__global__ void dense_small_k(const float* __restrict__ A, const float* __restrict__ W,
                              const float* __restrict__ b, float* __restrict__ C,
                              int M, int N, int K)
{
    const int idx = blockIdx.x * blockDim.x + threadIdx.x;
    if (idx >= M * N) return;
    const int m = idx / N, n = idx - m * N;
    float acc = b[n];
    const float* a = A + (size_t)m * K;
    for (int k = 0; k < K; k++) acc = fmaf(a[k], W[(size_t)k * N + n], acc);
    C[idx] = acc;
}

// ---------------- launcher ----------------
extern "C" void kernel_launch(void* const* d_in, const int* in_sizes, int n_in,
                              void* d_out, int out_size)
{
    const float* x    = (const float*)d_in[0];
    const float* adj  = (const float*)d_in[1];
    // d_in[2] = seg (int32) — structure is fixed (32 consecutive nodes/graph), unused
    const float* W1   = (const float*)d_in[3];
    const float* Ws1  = (const float*)d_in[4];
    const float* b1   = (const float*)d_in[5];
    const float* g1   = (const float*)d_in[6];
    const float* be1  = (const float*)d_in[7];
    const float* W2   = (const float*)d_in[8];
    const float* Ws2  = (const float*)d_in[9];
    const float* b2   = (const float*)d_in[10];
    const float* g2   = (const float*)d_in[11];
    const float* be2  = (const float*)d_in[12];
    const float* bn0g = (const float*)d_in[13];
    const float* bn0b = (const float*)d_in[14];
    const float* L1W  = (const float*)d_in[15];
    const float* L1b  = (const float*)d_in[16];
    const float* bn1g = (const float*)d_in[17];
    const float* bn1b = (const float*)d_in[18];
    const float* L2W  = (const float*)d_in[19];
    const float* L2b  = (const float*)d_in[20];
    const float* bn2g = (const float*)d_in[21];
    const float* bn2b = (const float*)d_in[22];
    const float* L3W  = (const float*)d_in[23];
    const float* L3b  = (const float*)d_in[24];
    const float* catW = (const float*)d_in[25];
    const float* catb = (const float*)d_in[26];

    float* out = (float*)d_out;
    float* out_main  = out;                    // [256,128]
    float* out_class = out + 256 * 128;        // [256,12]
    float* out_fp    = out + 256 * 128 + 256 * 12;  // [256,256]

    float *ax, *tmp1, *pre1, *g2in, *tmp2, *pre2, *pool, *bnp, *l1, *bn1, *l2;
    float *psum, *psq, *scale, *shift;
    cudaGetSymbolAddress((void**)&ax,    g_ax);
    cudaGetSymbolAddress((void**)&tmp1,  g_tmp1);
    cudaGetSymbolAddress((void**)&pre1,  g_pre1);
    cudaGetSymbolAddress((void**)&g2in,  g_g2in);
    cudaGetSymbolAddress((void**)&tmp2,  g_tmp2);
    cudaGetSymbolAddress((void**)&pre2,  g_pre2);
    cudaGetSymbolAddress((void**)&pool,  g_pool);
    cudaGetSymbolAddress((void**)&bnp,   g_bnp);
    cudaGetSymbolAddress((void**)&l1,    g_l1);
    cudaGetSymbolAddress((void**)&bn1,   g_bn1);
    cudaGetSymbolAddress((void**)&l2,    g_l2);
    cudaGetSymbolAddress((void**)&psum,  g_psum);
    cudaGetSymbolAddress((void**)&psq,   g_psq);
    cudaGetSymbolAddress((void**)&scale, g_scale);
    cudaGetSymbolAddress((void**)&shift, g_shift);

    // ---- layer 1 ----
    // ax = adj @ x  [8192,128]  (re-associated: (adj@x)@W1 == adj@(x@W1))
    sgemm_k<false, false, false><<<dim3(FF / 64, NN / 128), 256>>>(adj, x, ax, nullptr, nullptr, NN, FF, NN);
    // tmp1 = x @ Ws1 + b1
    sgemm_k<true, false, false><<<dim3(HH / 64, NN / 128), 256>>>(x, Ws1, tmp1, b1, nullptr, NN, HH, FF);
    // pre1 = relu(ax @ W1 + tmp1)
    sgemm_k<false, true, true><<<dim3(HH / 64, NN / 128), 256>>>(ax, W1, pre1, nullptr, tmp1, NN, HH, FF);
    // BN -> h1 (in place)
    bn_partial_k<<<64, 256>>>(pre1, psum, psq);
    bn_finalize_k<<<1, 256>>>(psum, psq, g1, be1, scale, shift);
    bn_apply_k<<<(NN * HH / 4) / 256, 256>>>(pre1, scale, shift);

    // ---- layer 2 ----
    // g2in = h1 @ W2
    sgemm_k<false, false, false><<<dim3(HH / 64, NN / 128), 256>>>(pre1, W2, g2in, nullptr, nullptr, NN, HH, HH);
    // tmp2 = h1 @ Ws2 + b2
    sgemm_k<true, false, false><<<dim3(HH / 64, NN / 128), 256>>>(pre1, Ws2, tmp2, b2, nullptr, NN, HH, HH);
    // pre2 = relu(adj @ g2in + tmp2)   (the big one)
    sgemm_k<false, true, true><<<dim3(HH / 64, NN / 128), 256>>>(adj, g2in, pre2, nullptr, tmp2, NN, HH, NN);
    // BN -> h2 (in place)
    bn_partial_k<<<64, 256>>>(pre2, psum, psq);
    bn_finalize_k<<<1, 256>>>(psum, psq, g2, be2, scale, shift);
    bn_apply_k<<<(NN * HH / 4) / 256, 256>>>(pre2, scale, shift);

    // ---- pooling ----
    pool_k<<<GG, 256>>>(pre1, pre2, pool);

    // ---- MLP head ----
    bn_small_k<<<8, 128>>>(pool, bn0g, bn0b, bnp, 1024);
    sgemm_k<true, false, true><<<dim3(512 / 64, GG / 128), 256>>>(bnp, L1W, l1, L1b, nullptr, GG, 512, 1024);
    bn_small_k<<<4, 128>>>(l1, bn1g, bn1b, bn1, 512);
    sgemm_k<true, false, true><<<dim3(256 / 64, GG / 128), 256>>>(bn1, L2W, l2, L2b, nullptr, GG, 256, 512);
    bn_small_k<<<2, 128>>>(l2, bn2g, bn2b, out_fp, 256);   // fingerprint straight into d_out

    // out = fp @ L3W + L3b ; out_class = fp @ catW + catb
    dense_small_k<<<(256 * 128 + 255) / 256, 256>>>(out_fp, L3W, L3b, out_main, 256, 128, 256);
    dense_small_k<<<(256 * 12 + 255) / 256, 256>>>(out_fp, catW, catb, out_class, 256, 12, 256);

    (void)in_sizes; (void)n_in; (void)out_size;
}

// round 3
// speedup vs baseline: 1.8075x; 1.8075x over previous
#include <cuda_runtime.h>
#include <cuda_bf16.h>
#include <math.h>
#include <stdint.h>

// ---------------- problem constants ----------------
#define NN   8192
#define FF   128
#define HH   256
#define GG   256
#define NPG  32
#define EPSB 1e-5f

// ---------------- scratch ----------------
__device__ float g_ax   [NN * FF];
__device__ float g_tmp1 [NN * HH];
__device__ float g_pre1 [NN * HH];
__device__ float g_g2in [NN * HH];
__device__ float g_tmp2 [NN * HH];
__device__ float g_pre2 [NN * HH];
__device__ float g_pool [GG * 1024];
__device__ float g_bnp  [GG * 1024];
__device__ float g_l1   [GG * 512];
__device__ float g_bn1  [GG * 512];
__device__ float g_l2   [GG * 256];
__device__ float g_psum [64 * HH];
__device__ float g_psq  [64 * HH];
__device__ float g_scale[HH];
__device__ float g_shift[HH];
__device__ __nv_bfloat16 g_xT_hi [FF * NN];
__device__ __nv_bfloat16 g_xT_lo [FF * NN];
__device__ __nv_bfloat16 g_g2T_hi[HH * NN];
__device__ __nv_bfloat16 g_g2T_lo[HH * NN];

__device__ __forceinline__ uint32_t smem_u32(const void* p) {
    uint32_t a;
    asm("{ .reg .u64 t; cvta.to.shared.u64 t, %1; cvt.u32.u64 %0, t; }" : "=r"(a) : "l"(p));
    return a;
}

__device__ __forceinline__ void ldsm4(uint32_t& r0, uint32_t& r1, uint32_t& r2, uint32_t& r3, uint32_t addr) {
    asm volatile("ldmatrix.sync.aligned.m8n8.x4.shared.b16 {%0,%1,%2,%3}, [%4];"
        : "=r"(r0), "=r"(r1), "=r"(r2), "=r"(r3) : "r"(addr));
}
__device__ __forceinline__ void mma16816(float* d, const uint32_t* a, uint32_t b0, uint32_t b1) {
    asm volatile("mma.sync.aligned.m16n8k16.row.col.f32.bf16.bf16.f32 "
        "{%0,%1,%2,%3}, {%4,%5,%6,%7}, {%8,%9}, {%0,%1,%2,%3};"
        : "+f"(d[0]), "+f"(d[1]), "+f"(d[2]), "+f"(d[3])
        : "r"(a[0]), "r"(a[1]), "r"(a[2]), "r"(a[3]), "r"(b0), "r"(b1));
}
#define CP_ASYNC16(dst, src) asm volatile("cp.async.cg.shared.global [%0], [%1], 16;" :: "r"(dst), "l"(src))
#define CP_COMMIT()          asm volatile("cp.async.commit_group;" ::: "memory")
#define CP_WAIT0()           asm volatile("cp.async.wait_group 0;" ::: "memory")

// ============ split-bf16 tensor-core GEMM ============
// C[M, Ntot] = A[M,K] (fp32, row-major) @ Bt^T, Bt = hi/lo bf16 [Ntot][K] (K-major).
// CTA tile 128x128, BK=32, 8 warps (4M x 2N).
// smem stage (bf16 elems): AH 128*40, AL 128*40, BH 128*40, BL 128*40 (stride 40 = conflict-free)
#define STG_E 20480
#define AH_O  0
#define AL_O  5120
#define BH_O  10240
#define BL_O  15360

template <bool ADD, bool RELU>
__global__ void __launch_bounds__(256, 1)
mma_gemm_k(const float* __restrict__ A,
           const __nv_bfloat16* __restrict__ Bth, const __nv_bfloat16* __restrict__ Btl,
           float* __restrict__ C, const float* __restrict__ Add, int Ntot, int K)
{
    extern __shared__ __align__(16) __nv_bfloat16 sm[];
    const int tid  = threadIdx.x;
    const int wid  = tid >> 5;
    const int lane = tid & 31;
    const int m0 = blockIdx.y * 128;
    const int n0 = blockIdx.x * 128;
    const int wm = (wid & 3) * 32;
    const int wn = (wid >> 2) * 64;

    float acc[2][8][4];
#pragma unroll
    for (int i = 0; i < 2; i++)
#pragma unroll
        for (int j = 0; j < 8; j++)
#pragma unroll
            for (int v = 0; v < 4; v++) acc[i][j][v] = 0.f;

    const int nch = K / 32;
    float4 aPre[4];

    // ---- loaders ----
    auto ldgA = [&](int ck) {
#pragma unroll
        for (int it = 0; it < 4; it++) {
            const int i = tid + it * 256;
            const int r = i >> 3, c4 = i & 7;
            aPre[it] = *(const float4*)(A + (size_t)(m0 + r) * K + ck * 32 + c4 * 4);
        }
    };
    auto cvtstA = [&](int stg) {
        __nv_bfloat16* ah = sm + stg * STG_E + AH_O;
        __nv_bfloat16* al = sm + stg * STG_E + AL_O;
#pragma unroll
        for (int it = 0; it < 4; it++) {
            const int i = tid + it * 256;
            const int r = i >> 3, c4 = i & 7;
            const float4 v = aPre[it];
            __nv_bfloat16 h0 = __float2bfloat16_rn(v.x);
            __nv_bfloat16 h1 = __float2bfloat16_rn(v.y);
            __nv_bfloat16 h2 = __float2bfloat16_rn(v.z);
            __nv_bfloat16 h3 = __float2bfloat16_rn(v.w);
            __nv_bfloat16 l0 = __float2bfloat16_rn(v.x - __bfloat162float(h0));
            __nv_bfloat16 l1 = __float2bfloat16_rn(v.y - __bfloat162float(h1));
            __nv_bfloat16 l2 = __float2bfloat16_rn(v.z - __bfloat162float(h2));
            __nv_bfloat16 l3 = __float2bfloat16_rn(v.w - __bfloat162float(h3));
            uint2 hp, lp;
            hp.x = (uint32_t)__bfloat16_as_ushort(h0) | ((uint32_t)__bfloat16_as_ushort(h1) << 16);
            hp.y = (uint32_t)__bfloat16_as_ushort(h2) | ((uint32_t)__bfloat16_as_ushort(h3) << 16);
            lp.x = (uint32_t)__bfloat16_as_ushort(l0) | ((uint32_t)__bfloat16_as_ushort(l1) << 16);
            lp.y = (uint32_t)__bfloat16_as_ushort(l2) | ((uint32_t)__bfloat16_as_ushort(l3) << 16);
            *(uint2*)(ah + r * 40 + c4 * 4) = hp;
            *(uint2*)(al + r * 40 + c4 * 4) = lp;
        }
    };
    auto cpB = [&](int ck, int stg) {
        const uint32_t bh = smem_u32(sm + stg * STG_E + BH_O);
        const uint32_t bl = smem_u32(sm + stg * STG_E + BL_O);
#pragma unroll
        for (int it = 0; it < 2; it++) {
            const int i = tid + it * 256;
            const int r = i >> 2, c = i & 3;
            const size_t g = (size_t)(n0 + r) * K + ck * 32 + c * 8;
            CP_ASYNC16(bh + (r * 40 + c * 8) * 2, Bth + g);
            CP_ASYNC16(bl + (r * 40 + c * 8) * 2, Btl + g);
        }
        CP_COMMIT();
    };

    // ---- prologue ----
    ldgA(0);
    cvtstA(0);
    cpB(0, 0);
    CP_WAIT0();
    __syncthreads();

    for (int ck = 0; ck < nch; ck++) {
        const int cur = ck & 1;
        const int nxt = cur ^ 1;
        const bool more = (ck + 1) < nch;
        if (more) { ldgA(ck + 1); cpB(ck + 1, nxt); }

        // ---- compute on stage cur ----
        const uint32_t sA_h = smem_u32(sm + cur * STG_E + AH_O);
        const uint32_t sA_l = smem_u32(sm + cur * STG_E + AL_O);
        const uint32_t sB_h = smem_u32(sm + cur * STG_E + BH_O);
        const uint32_t sB_l = smem_u32(sm + cur * STG_E + BL_O);
#pragma unroll
        for (int ks = 0; ks < 2; ks++) {
            uint32_t ahf[2][4], alf[2][4];
#pragma unroll
            for (int i = 0; i < 2; i++) {
                const int row = wm + i * 16 + (lane & 15);
                const int colb = ks * 16 + (lane >> 4) * 8;
                const uint32_t off = (uint32_t)(row * 40 + colb) * 2;
                ldsm4(ahf[i][0], ahf[i][1], ahf[i][2], ahf[i][3], sA_h + off);
                ldsm4(alf[i][0], alf[i][1], alf[i][2], alf[i][3], sA_l + off);
            }
#pragma unroll
            for (int jp = 0; jp < 4; jp++) {
                // lanes: g=lane>>3; tile jp*2 + (g>>1); k-half g&1
                const int g = lane >> 3;
                const int row = wn + (jp * 2 + (g >> 1)) * 8 + (lane & 7);
                const int col = ks * 16 + (g & 1) * 8;
                const uint32_t off = (uint32_t)(row * 40 + col) * 2;
                uint32_t bh[4], bl[4];
                ldsm4(bh[0], bh[1], bh[2], bh[3], sB_h + off);
                ldsm4(bl[0], bl[1], bl[2], bl[3], sB_l + off);
#pragma unroll
                for (int i = 0; i < 2; i++) {
#pragma unroll
                    for (int jj = 0; jj < 2; jj++) {
                        float* d = acc[i][jp * 2 + jj];
                        mma16816(d, ahf[i], bh[jj * 2], bh[jj * 2 + 1]);
                        mma16816(d, ahf[i], bl[jj * 2], bl[jj * 2 + 1]);
                        mma16816(d, alf[i], bh[jj * 2], bh[jj * 2 + 1]);
                    }
                }
            }
        }

        if (more) { cvtstA(nxt); CP_WAIT0(); }
        __syncthreads();
    }

    // ---- epilogue ----
#pragma unroll
    for (int i = 0; i < 2; i++) {
        const int r0 = m0 + wm + i * 16 + (lane >> 2);
#pragma unroll
        for (int j = 0; j < 8; j++) {
            const int cc = n0 + wn + j * 8 + (lane & 3) * 2;
            const size_t o0 = (size_t)r0 * Ntot + cc;
            const size_t o1 = (size_t)(r0 + 8) * Ntot + cc;
            float2 v0 = make_float2(acc[i][j][0], acc[i][j][1]);
            float2 v1 = make_float2(acc[i][j][2], acc[i][j][3]);
            if (ADD) {
                const float2 a0 = *(const float2*)(Add + o0);
                const float2 a1 = *(const float2*)(Add + o1);
                v0.x += a0.x; v0.y += a0.y; v1.x += a1.x; v1.y += a1.y;
            }
            if (RELU) {
                v0.x = fmaxf(v0.x, 0.f); v0.y = fmaxf(v0.y, 0.f);
                v1.x = fmaxf(v1.x, 0.f); v1.y = fmaxf(v1.y, 0.f);
            }
            *(float2*)(C + o0) = v0;
            *(float2*)(C + o1) = v1;
        }
    }
}

// ---------------- transpose + split-bf16 convert ----------------
__global__ void transconv_k(const float* __restrict__ in, __nv_bfloat16* __restrict__ oh,
                            __nv_bfloat16* __restrict__ ol, int R, int C)
{
    __shared__ float t[32][33];
    const int c0 = blockIdx.x * 32, r0 = blockIdx.y * 32;
    const int tx = threadIdx.x, ty = threadIdx.y;
#pragma unroll
    for (int j = 0; j < 4; j++)
        t[ty + j * 8][tx] = in[(size_t)(r0 + ty + j * 8) * C + c0 + tx];
    __syncthreads();
#pragma unroll
    for (int j = 0; j < 4; j++) {
        const float v = t[tx][ty + j * 8];
        const __nv_bfloat16 h = __float2bfloat16_rn(v);
        const __nv_bfloat16 l = __float2bfloat16_rn(v - __bfloat162float(h));
        const size_t o = (size_t)(c0 + ty + j * 8) * R + r0 + tx;
        oh[o] = h; ol[o] = l;
    }
}

// ---------------- fp32 SGEMM (small GEMMs) ----------------
template <bool BIAS, bool ADD, bool RELU>
__global__ void __launch_bounds__(256, 3)
sgemm_k(const float* __restrict__ A, const float* __restrict__ B,
        float* __restrict__ C, const float* __restrict__ bias,
        const float* __restrict__ Add, int M, int N, int K)
{
    constexpr int BM = 128, BN = 64, BK = 16, TM = 8, TN = 4;
    __shared__ float As[BK][BM];
    __shared__ float Bs[BK][BN];

    const int tid = threadIdx.x;
    const int bx = blockIdx.x, by = blockIdx.y;
    const int aRow = tid >> 1, aCol = (tid & 1) * 8;
    const float* Ag = A + (size_t)(by * BM + aRow) * K + aCol;
    const int bRow = tid >> 4, bCol = (tid & 15) * 4;
    const float* Bg = B + (size_t)bRow * N + bx * BN + bCol;
    const int tr = (tid >> 4) * TM, tc = (tid & 15) * TN;

    float acc[TM][TN];
#pragma unroll
    for (int i = 0; i < TM; i++)
#pragma unroll
        for (int j = 0; j < TN; j++) acc[i][j] = 0.f;

    for (int k0 = 0; k0 < K; k0 += BK) {
        float4 a0 = *(const float4*)(Ag + k0);
        float4 a1 = *(const float4*)(Ag + k0 + 4);
        As[aCol + 0][aRow] = a0.x;  As[aCol + 1][aRow] = a0.y;
        As[aCol + 2][aRow] = a0.z;  As[aCol + 3][aRow] = a0.w;
        As[aCol + 4][aRow] = a1.x;  As[aCol + 5][aRow] = a1.y;
        As[aCol + 6][aRow] = a1.z;  As[aCol + 7][aRow] = a1.w;
        *(float4*)&Bs[bRow][bCol] = *(const float4*)(Bg + (size_t)k0 * N);
        __syncthreads();
#pragma unroll
        for (int k = 0; k < BK; k++) {
            float ra[TM], rb[TN];
#pragma unroll
            for (int i = 0; i < TM; i++) ra[i] = As[k][tr + i];
#pragma unroll
            for (int j = 0; j < TN; j++) rb[j] = Bs[k][tc + j];
#pragma unroll
            for (int i = 0; i < TM; i++)
#pragma unroll
                for (int j = 0; j < TN; j++) acc[i][j] = fmaf(ra[i], rb[j], acc[i][j]);
        }
        __syncthreads();
    }

    float4 bv = make_float4(0.f, 0.f, 0.f, 0.f);
    if (BIAS) bv = *(const float4*)(bias + bx * BN + tc);
#pragma unroll
    for (int i = 0; i < TM; i++) {
        const size_t off = (size_t)(by * BM + tr + i) * N + bx * BN + tc;
        float4 v = make_float4(acc[i][0], acc[i][1], acc[i][2], acc[i][3]);
        if (ADD) {
            float4 ad = *(const float4*)(Add + off);
            v.x += ad.x; v.y += ad.y; v.z += ad.z; v.w += ad.w;
        }
        if (BIAS) { v.x += bv.x; v.y += bv.y; v.z += bv.z; v.w += bv.w; }
        if (RELU) {
            v.x = fmaxf(v.x, 0.f); v.y = fmaxf(v.y, 0.f);
            v.z = fmaxf(v.z, 0.f); v.w = fmaxf(v.w, 0.f);
        }
        *(float4*)(C + off) = v;
    }
}

// ---------------- BatchNorm (8192 x 256) ----------------
__global__ void bn_partial_k(const float* __restrict__ x, float* __restrict__ psum,
                             float* __restrict__ psq)
{
    const int t = threadIdx.x;
    const float* p = x + (size_t)blockIdx.x * 128 * HH + t;
    float s = 0.f, q = 0.f;
#pragma unroll 4
    for (int r = 0; r < 128; r++) { float v = p[(size_t)r * HH]; s += v; q += v * v; }
    psum[blockIdx.x * HH + t] = s;
    psq [blockIdx.x * HH + t] = q;
}

__global__ void bn_finalize_k(const float* __restrict__ psum, const float* __restrict__ psq,
                              const float* __restrict__ gamma, const float* __restrict__ beta,
                              float* __restrict__ scale, float* __restrict__ shift)
{
    const int t = threadIdx.x;
    float s = 0.f, q = 0.f;
#pragma unroll
    for (int b = 0; b < 64; b++) { s += psum[b * HH + t]; q += psq[b * HH + t]; }
    const float invn = 1.f / (float)NN;
    const float m = s * invn;
    const float var = q * invn - m * m;
    const float sc = gamma[t] * rsqrtf(var + EPSB);
    scale[t] = sc;
    shift[t] = beta[t] - m * sc;
}

__global__ void bn_apply_k(float* __restrict__ x, const float* __restrict__ scale,
                           const float* __restrict__ shift)
{
    const int i = blockIdx.x * blockDim.x + threadIdx.x;
    const int c = (i * 4) & (HH - 1);
    float4 v = ((float4*)x)[i];
    v.x = fmaf(v.x, scale[c + 0], shift[c + 0]);
    v.y = fmaf(v.y, scale[c + 1], shift[c + 1]);
    v.z = fmaf(v.z, scale[c + 2], shift[c + 2]);
    v.w = fmaf(v.w, scale[c + 3], shift[c + 3]);
    ((float4*)x)[i] = v;
}

// ---------------- pooling ----------------
__global__ void pool_k(const float* __restrict__ h1, const float* __restrict__ h2,
                       float* __restrict__ pooled)
{
    const int g = blockIdx.x, t = threadIdx.x;
    const size_t r0 = (size_t)g * NPG;
    float mx1 = -1e30f, mx2 = -1e30f, s1 = 0.f, s2 = 0.f;
#pragma unroll 4
    for (int r = 0; r < NPG; r++) {
        float v1 = h1[(r0 + r) * HH + t];
        float v2 = h2[(r0 + r) * HH + t];
        mx1 = fmaxf(mx1, v1); s1 += v1;
        mx2 = fmaxf(mx2, v2); s2 += v2;
    }
    float* out = pooled + (size_t)g * 1024;
    out[t]       = mx1;
    out[256 + t] = mx2;
    out[512 + t] = s1 * (1.f / NPG);
    out[768 + t] = s2 * (1.f / NPG);
}

// ---------------- small BN (256 rows) ----------------
__global__ void bn_small_k(const float* __restrict__ in, const float* __restrict__ gamma,
                           const float* __restrict__ beta, float* __restrict__ out, int C)
{
    const int c = blockIdx.x * blockDim.x + threadIdx.x;
    if (c >= C) return;
    float s = 0.f, q = 0.f;
    for (int r = 0; r < GG; r++) { float v = in[(size_t)r * C + c]; s += v; q += v * v; }
    const float m = s * (1.f / GG);
    const float var = q * (1.f / GG) - m * m;
    const float sc = gamma[c] * rsqrtf(var + EPSB);
    const float sh = beta[c] - m * sc;
    for (int r = 0; r < GG; r++) out[(size_t)r * C + c] = fmaf(in[(size_t)r * C + c], sc, sh);
}

// ---------------- tiny dense ----------------
__global__ void dense_small_k(const float* __restrict__ A, const float* __restrict__ W,
                              const float* __restrict__ b, float* __restrict__ C,
                              int M, int N, int K)
{
    const int idx = blockIdx.x * blockDim.x + threadIdx.x;
    if (idx >= M * N) return;
    const int m = idx / N, n = idx - m * N;
    float acc = b[n];
    const float* a = A + (size_t)m * K;
    for (int k = 0; k < K; k++) acc = fmaf(a[k], W[(size_t)k * N + n], acc);
    C[idx] = acc;
}

// ---------------- launcher ----------------
extern "C" void kernel_launch(void* const* d_in, const int* in_sizes, int n_in,
                              void* d_out, int out_size)
{
    const float* x    = (const float*)d_in[0];
    const float* adj  = (const float*)d_in[1];
    const float* W1   = (const float*)d_in[3];
    const float* Ws1  = (const float*)d_in[4];
    const float* b1   = (const float*)d_in[5];
    const float* g1   = (const float*)d_in[6];
    const float* be1  = (const float*)d_in[7];
    const float* W2   = (const float*)d_in[8];
    const float* Ws2  = (const float*)d_in[9];
    const float* b2   = (const float*)d_in[10];
    const float* g2   = (const float*)d_in[11];
    const float* be2  = (const float*)d_in[12];
    const float* bn0g = (const float*)d_in[13];
    const float* bn0b = (const float*)d_in[14];
    const float* L1W  = (const float*)d_in[15];
    const float* L1b  = (const float*)d_in[16];
    const float* bn1g = (const float*)d_in[17];
    const float* bn1b = (const float*)d_in[18];
    const float* L2W  = (const float*)d_in[19];
    const float* L2b  = (const float*)d_in[20];
    const float* bn2g = (const float*)d_in[21];
    const float* bn2b = (const float*)d_in[22];
    const float* L3W  = (const float*)d_in[23];
    const float* L3b  = (const float*)d_in[24];
    const float* catW = (const float*)d_in[25];
    const float* catb = (const float*)d_in[26];

    float* out = (float*)d_out;
    float* out_main  = out;
    float* out_class = out + 256 * 128;
    float* out_fp    = out + 256 * 128 + 256 * 12;

    float *ax, *tmp1, *pre1, *g2in, *tmp2, *pre2, *pool, *bnp, *l1, *bn1, *l2;
    float *psum, *psq, *scale, *shift;
    __nv_bfloat16 *xTh, *xTl, *g2Th, *g2Tl;
    cudaGetSymbolAddress((void**)&ax,    g_ax);
    cudaGetSymbolAddress((void**)&tmp1,  g_tmp1);
    cudaGetSymbolAddress((void**)&pre1,  g_pre1);
    cudaGetSymbolAddress((void**)&g2in,  g_g2in);
    cudaGetSymbolAddress((void**)&tmp2,  g_tmp2);
    cudaGetSymbolAddress((void**)&pre2,  g_pre2);
    cudaGetSymbolAddress((void**)&pool,  g_pool);
    cudaGetSymbolAddress((void**)&bnp,   g_bnp);
    cudaGetSymbolAddress((void**)&l1,    g_l1);
    cudaGetSymbolAddress((void**)&bn1,   g_bn1);
    cudaGetSymbolAddress((void**)&l2,    g_l2);
    cudaGetSymbolAddress((void**)&psum,  g_psum);
    cudaGetSymbolAddress((void**)&psq,   g_psq);
    cudaGetSymbolAddress((void**)&scale, g_scale);
    cudaGetSymbolAddress((void**)&shift, g_shift);
    cudaGetSymbolAddress((void**)&xTh,   g_xT_hi);
    cudaGetSymbolAddress((void**)&xTl,   g_xT_lo);
    cudaGetSymbolAddress((void**)&g2Th,  g_g2T_hi);
    cudaGetSymbolAddress((void**)&g2Tl,  g_g2T_lo);

    static bool attr_done = false;
    if (!attr_done) {
        cudaFuncSetAttribute(mma_gemm_k<false, false>, cudaFuncAttributeMaxDynamicSharedMemorySize, 81920);
        cudaFuncSetAttribute(mma_gemm_k<true, true>,   cudaFuncAttributeMaxDynamicSharedMemorySize, 81920);
        attr_done = true;
    }

    // ---- layer 1 ----
    transconv_k<<<dim3(FF / 32, NN / 32), dim3(32, 8)>>>(x, xTh, xTl, NN, FF);
    // ax = adj @ x via tensor cores (re-associated (adj@x)@W1)
    mma_gemm_k<false, false><<<dim3(1, NN / 128), 256, 81920>>>(adj, xTh, xTl, ax, nullptr, FF, NN);
    sgemm_k<true, false, false><<<dim3(HH / 64, NN / 128), 256>>>(x, Ws1, tmp1, b1, nullptr, NN, HH, FF);
    sgemm_k<false, true, true><<<dim3(HH / 64, NN / 128), 256>>>(ax, W1, pre1, nullptr, tmp1, NN, HH, FF);
    bn_partial_k<<<64, 256>>>(pre1, psum, psq);
    bn_finalize_k<<<1, 256>>>(psum, psq, g1, be1, scale, shift);
    bn_apply_k<<<(NN * HH / 4) / 256, 256>>>(pre1, scale, shift);

    // ---- layer 2 ----
    sgemm_k<false, false, false><<<dim3(HH / 64, NN / 128), 256>>>(pre1, W2, g2in, nullptr, nullptr, NN, HH, HH);
    transconv_k<<<dim3(HH / 32, NN / 32), dim3(32, 8)>>>(g2in, g2Th, g2Tl, NN, HH);
    sgemm_k<true, false, false><<<dim3(HH / 64, NN / 128), 256>>>(pre1, Ws2, tmp2, b2, nullptr, NN, HH, HH);
    // pre2 = relu(adj @ g2in + tmp2) via tensor cores
    mma_gemm_k<true, true><<<dim3(2, NN / 128), 256, 81920>>>(adj, g2Th, g2Tl, pre2, tmp2, HH, NN);
    bn_partial_k<<<64, 256>>>(pre2, psum, psq);
    bn_finalize_k<<<1, 256>>>(psum, psq, g2, be2, scale, shift);
    bn_apply_k<<<(NN * HH / 4) / 256, 256>>>(pre2, scale, shift);

    // ---- pooling ----
    pool_k<<<GG, 256>>>(pre1, pre2, pool);

    // ---- MLP head ----
    bn_small_k<<<8, 128>>>(pool, bn0g, bn0b, bnp, 1024);
    sgemm_k<true, false, true><<<dim3(512 / 64, GG / 128), 256>>>(bnp, L1W, l1, L1b, nullptr, GG, 512, 1024);
    bn_small_k<<<4, 128>>>(l1, bn1g, bn1b, bn1, 512);
    sgemm_k<true, false, true><<<dim3(256 / 64, GG / 128), 256>>>(bn1, L2W, l2, L2b, nullptr, GG, 256, 512);
    bn_small_k<<<2, 128>>>(l2, bn2g, bn2b, out_fp, 256);

    dense_small_k<<<(256 * 128 + 255) / 256, 256>>>(out_fp, L3W, L3b, out_main, 256, 128, 256);
    dense_small_k<<<(256 * 12 + 255) / 256, 256>>>(out_fp, catW, catb, out_class, 256, 12, 256);

    (void)in_sizes; (void)n_in; (void)out_size;
}

// round 7
// speedup vs baseline: 2.0304x; 1.1234x over previous
#include <cuda_runtime.h>
#include <cuda_bf16.h>
#include <math.h>
#include <stdint.h>

#define NN   8192
#define FF   128
#define HH   256
#define GG   256
#define NPG  32
#define EPSB 1e-5f
#define K2TOT (NN + HH)
#define BIGK (1 << 30)

__device__ __nv_bfloat16 g_adj_h[NN * NN];
__device__ __nv_bfloat16 g_adj_l[NN * NN];
__device__ __nv_bfloat16 g_xT_h [FF * NN];
__device__ __nv_bfloat16 g_xT_l [FF * NN];
__device__ float g_axp  [2 * NN * FF];
__device__ __nv_bfloat16 g_A1_h [NN * HH];
__device__ __nv_bfloat16 g_A1_l [NN * HH];
__device__ __nv_bfloat16 g_B1_h [HH * HH];
__device__ __nv_bfloat16 g_B1_l [HH * HH];
__device__ float g_pre1 [NN * HH];
__device__ __nv_bfloat16 g_h1_h [NN * HH];
__device__ __nv_bfloat16 g_h1_l [NN * HH];
__device__ __nv_bfloat16 g_W2T_h[HH * HH];
__device__ __nv_bfloat16 g_W2T_l[HH * HH];
__device__ float g_g2in [NN * HH];
__device__ __nv_bfloat16 g_B2_h [HH * K2TOT];
__device__ __nv_bfloat16 g_B2_l [HH * K2TOT];
__device__ float g_pre2 [NN * HH];
__device__ float g_pool [GG * 1024];
__device__ float g_bnp  [GG * 1024];
__device__ float g_l1   [GG * 512];
__device__ float g_bn1  [GG * 512];
__device__ float g_l2   [GG * 256];
__device__ float g_psum [64 * HH];
__device__ float g_psq  [64 * HH];
__device__ float g_scale[HH];
__device__ float g_shift[HH];

__device__ __forceinline__ uint32_t smem_u32(const void* p) {
    uint32_t a;
    asm("{ .reg .u64 t; cvta.to.shared.u64 t, %1; cvt.u32.u64 %0, t; }" : "=r"(a) : "l"(p));
    return a;
}
__device__ __forceinline__ void ldsm4(uint32_t* r, uint32_t addr) {
    asm volatile("ldmatrix.sync.aligned.m8n8.x4.shared.b16 {%0,%1,%2,%3}, [%4];"
        : "=r"(r[0]), "=r"(r[1]), "=r"(r[2]), "=r"(r[3]) : "r"(addr));
}
__device__ __forceinline__ void mma16816(float* d, const uint32_t* a, uint32_t b0, uint32_t b1) {
    asm volatile("mma.sync.aligned.m16n8k16.row.col.f32.bf16.bf16.f32 "
        "{%0,%1,%2,%3}, {%4,%5,%6,%7}, {%8,%9}, {%0,%1,%2,%3};"
        : "+f"(d[0]), "+f"(d[1]), "+f"(d[2]), "+f"(d[3])
        : "r"(a[0]), "r"(a[1]), "r"(a[2]), "r"(a[3]), "r"(b0), "r"(b1));
}
#define CP_ASYNC16(dst, src) asm volatile("cp.async.cg.shared.global [%0], [%1], 16;" :: "r"(dst), "l"(src))
#define CP_COMMIT()          asm volatile("cp.async.commit_group;" ::: "memory")
#define CP_WAIT1()           asm volatile("cp.async.wait_group 1;" ::: "memory")

__device__ __forceinline__ void split2(float v, __nv_bfloat16& h, __nv_bfloat16& l) {
    h = __float2bfloat16_rn(v);
    l = __float2bfloat16_rn(v - __bfloat162float(h));
}

// split-bf16 tensor-core GEMM, 3-stage cp.async pipeline.
// C[128,128] per CTA = A[M,K] @ B^T. A/B pre-split hi/lo bf16, K-major.
// A may concatenate two sources along K (first nck1 chunks from A1, rest from A2).
// Processes chunks [ck0, ck0+nck).
#define STG_E 20480
#define AH_O  0
#define AL_O  5120
#define BH_O  10240
#define BL_O  15360

template <bool BIAS, bool RELU>
__global__ void __launch_bounds__(256, 1)
mma2_k(const __nv_bfloat16* __restrict__ A1h, const __nv_bfloat16* __restrict__ A1l, int strA1, int nck1,
       const __nv_bfloat16* __restrict__ A2h, const __nv_bfloat16* __restrict__ A2l, int strA2,
       const __nv_bfloat16* __restrict__ Bh,  const __nv_bfloat16* __restrict__ Bl,  int strB,
       float* __restrict__ C, const float* __restrict__ bias, int Ntot,
       int nck, int ck0)
{
    extern __shared__ __align__(16) __nv_bfloat16 sm[];
    const int tid  = threadIdx.x;
    const int wid  = tid >> 5;
    const int lane = tid & 31;
    const int m0 = blockIdx.y * 128;
    const int n0 = blockIdx.x * 128;
    const int wm = (wid & 3) * 32;
    const int wn = (wid >> 2) * 64;

    float acc[2][8][4];
#pragma unroll
    for (int i = 0; i < 2; i++)
#pragma unroll
        for (int j = 0; j < 8; j++)
#pragma unroll
            for (int v = 0; v < 4; v++) acc[i][j][v] = 0.f;

    auto loadStage = [&](int lck, int stg) {
        const int g = ck0 + lck;
        const __nv_bfloat16 *ah, *al;
        int kloc, strA;
        if (g < nck1) { ah = A1h; al = A1l; strA = strA1; kloc = g * 32; }
        else          { ah = A2h; al = A2l; strA = strA2; kloc = (g - nck1) * 32; }
        const uint32_t sAh = smem_u32(sm + stg * STG_E + AH_O);
        const uint32_t sAl = smem_u32(sm + stg * STG_E + AL_O);
        const uint32_t sBh = smem_u32(sm + stg * STG_E + BH_O);
        const uint32_t sBl = smem_u32(sm + stg * STG_E + BL_O);
        const int kb = g * 32;
#pragma unroll
        for (int it = 0; it < 2; it++) {
            const int i = tid + it * 256;
            const int r = i >> 2, c = i & 3;
            const uint32_t so = (uint32_t)(r * 40 + c * 8) * 2;
            CP_ASYNC16(sAh + so, ah + (size_t)(m0 + r) * strA + kloc + c * 8);
            CP_ASYNC16(sAl + so, al + (size_t)(m0 + r) * strA + kloc + c * 8);
            CP_ASYNC16(sBh + so, Bh + (size_t)(n0 + r) * strB + kb + c * 8);
            CP_ASYNC16(sBl + so, Bl + (size_t)(n0 + r) * strB + kb + c * 8);
        }
        CP_COMMIT();
    };

    loadStage(0, 0);
    if (nck > 1) loadStage(1, 1); else CP_COMMIT();
    CP_WAIT1();
    __syncthreads();

    for (int ck = 0; ck < nck; ck++) {
        const int stg = ck % 3;
        const uint32_t sAh = smem_u32(sm + stg * STG_E + AH_O);
        const uint32_t sAl = smem_u32(sm + stg * STG_E + AL_O);
        const uint32_t sBh = smem_u32(sm + stg * STG_E + BH_O);
        const uint32_t sBl = smem_u32(sm + stg * STG_E + BL_O);

#pragma unroll
        for (int ks = 0; ks < 2; ks++) {
            uint32_t ah[2][4], al[2][4];
#pragma unroll
            for (int i = 0; i < 2; i++) {
                const int row = wm + i * 16 + (lane & 15);
                const int col = ks * 16 + (lane >> 4) * 8;
                const uint32_t off = (uint32_t)(row * 40 + col) * 2;
                ldsm4(ah[i], sAh + off);
                ldsm4(al[i], sAl + off);
            }
#pragma unroll
            for (int half = 0; half < 2; half++) {
                uint32_t bh[8], bl[8];
#pragma unroll
                for (int jp = 0; jp < 2; jp++) {
                    const int g = lane >> 3;
                    const int row = wn + (half * 4 + jp * 2 + (g >> 1)) * 8 + (lane & 7);
                    const int col = ks * 16 + (g & 1) * 8;
                    const uint32_t off = (uint32_t)(row * 40 + col) * 2;
                    ldsm4(&bh[jp * 4], sBh + off);
                    ldsm4(&bl[jp * 4], sBl + off);
                }
#pragma unroll
                for (int i = 0; i < 2; i++)
#pragma unroll
                    for (int t = 0; t < 4; t++)
                        mma16816(acc[i][half * 4 + t], ah[i], bh[t * 2], bh[t * 2 + 1]);
#pragma unroll
                for (int i = 0; i < 2; i++)
#pragma unroll
                    for (int t = 0; t < 4; t++)
                        mma16816(acc[i][half * 4 + t], ah[i], bl[t * 2], bl[t * 2 + 1]);
#pragma unroll
                for (int i = 0; i < 2; i++)
#pragma unroll
                    for (int t = 0; t < 4; t++)
                        mma16816(acc[i][half * 4 + t], al[i], bh[t * 2], bh[t * 2 + 1]);
            }
        }

        if (ck + 2 < nck) loadStage(ck + 2, (ck + 2) % 3); else CP_COMMIT();
        CP_WAIT1();
        __syncthreads();
    }

#pragma unroll
    for (int i = 0; i < 2; i++) {
        const int r0 = m0 + wm + i * 16 + (lane >> 2);
#pragma unroll
        for (int j = 0; j < 8; j++) {
            const int cc = n0 + wn + j * 8 + (lane & 3) * 2;
            const size_t o0 = (size_t)r0 * Ntot + cc;
            const size_t o1 = (size_t)(r0 + 8) * Ntot + cc;
            float2 v0 = make_float2(acc[i][j][0], acc[i][j][1]);
            float2 v1 = make_float2(acc[i][j][2], acc[i][j][3]);
            if (BIAS) {
                const float2 bv = *(const float2*)(bias + cc);
                v0.x += bv.x; v0.y += bv.y; v1.x += bv.x; v1.y += bv.y;
            }
            if (RELU) {
                v0.x = fmaxf(v0.x, 0.f); v0.y = fmaxf(v0.y, 0.f);
                v1.x = fmaxf(v1.x, 0.f); v1.y = fmaxf(v1.y, 0.f);
            }
            *(float2*)(C + o0) = v0;
            *(float2*)(C + o1) = v1;
        }
    }
}

__global__ void split_k(const float* __restrict__ in, __nv_bfloat16* __restrict__ oh,
                        __nv_bfloat16* __restrict__ ol)
{
    const int i = blockIdx.x * blockDim.x + threadIdx.x;
    const float4 v = ((const float4*)in)[i];
    __nv_bfloat16 h0, h1, h2, h3, l0, l1, l2, l3;
    split2(v.x, h0, l0); split2(v.y, h1, l1); split2(v.z, h2, l2); split2(v.w, h3, l3);
    uint2 hp, lp;
    hp.x = (uint32_t)__bfloat16_as_ushort(h0) | ((uint32_t)__bfloat16_as_ushort(h1) << 16);
    hp.y = (uint32_t)__bfloat16_as_ushort(h2) | ((uint32_t)__bfloat16_as_ushort(h3) << 16);
    lp.x = (uint32_t)__bfloat16_as_ushort(l0) | ((uint32_t)__bfloat16_as_ushort(l1) << 16);
    lp.y = (uint32_t)__bfloat16_as_ushort(l2) | ((uint32_t)__bfloat16_as_ushort(l3) << 16);
    ((uint2*)oh)[i] = hp;
    ((uint2*)ol)[i] = lp;
}

__global__ void split_into_k(const float* __restrict__ in, __nv_bfloat16* __restrict__ oh,
                             __nv_bfloat16* __restrict__ ol, int C, int ostr, int ooff)
{
    const int idx = blockIdx.x * blockDim.x + threadIdx.x;
    const int r = idx / C, c = idx - r * C;
    __nv_bfloat16 h, l;
    split2(in[idx], h, l);
    oh[(size_t)r * ostr + ooff + c] = h;
    ol[(size_t)r * ostr + ooff + c] = l;
}

__global__ void combine_ax_k(const float* __restrict__ a0, const float* __restrict__ a1,
                             __nv_bfloat16* __restrict__ oh, __nv_bfloat16* __restrict__ ol)
{
    const int idx = blockIdx.x * blockDim.x + threadIdx.x;
    const int r = idx >> 7, c = idx & 127;
    __nv_bfloat16 h, l;
    split2(a0[idx] + a1[idx], h, l);
    oh[(size_t)r * HH + c] = h;
    ol[(size_t)r * HH + c] = l;
}

__global__ void transconv_k(const float* __restrict__ in, __nv_bfloat16* __restrict__ oh,
                            __nv_bfloat16* __restrict__ ol, int C, int ostr, int koff)
{
    __shared__ float t[32][33];
    const int c0 = blockIdx.x * 32, r0 = blockIdx.y * 32;
    const int tx = threadIdx.x, ty = threadIdx.y;
#pragma unroll
    for (int j = 0; j < 4; j++)
        t[ty + j * 8][tx] = in[(size_t)(r0 + ty + j * 8) * C + c0 + tx];
    __syncthreads();
#pragma unroll
    for (int j = 0; j < 4; j++) {
        const float v = t[tx][ty + j * 8];
        __nv_bfloat16 h, l;
        split2(v, h, l);
        const size_t o = (size_t)(c0 + ty + j * 8) * ostr + koff + r0 + tx;
        oh[o] = h; ol[o] = l;
    }
}

template <bool BIAS, bool RELU>
__global__ void __launch_bounds__(256, 3)
sgemm_k(const float* __restrict__ A, const float* __restrict__ B,
        float* __restrict__ C, const float* __restrict__ bias, int M, int N, int K)
{
    constexpr int BM = 128, BN = 64, BK = 16, TM = 8, TN = 4;
    __shared__ float As[BK][BM];
    __shared__ float Bs[BK][BN];
    const int tid = threadIdx.x;
    const int bx = blockIdx.x, by = blockIdx.y;
    const int aRow = tid >> 1, aCol = (tid & 1) * 8;
    const float* Ag = A + (size_t)(by * BM + aRow) * K + aCol;
    const int bRow = tid >> 4, bCol = (tid & 15) * 4;
    const float* Bg = B + (size_t)bRow * N + bx * BN + bCol;
    const int tr = (tid >> 4) * TM, tc = (tid & 15) * TN;

    float acc[TM][TN];
#pragma unroll
    for (int i = 0; i < TM; i++)
#pragma unroll
        for (int j = 0; j < TN; j++) acc[i][j] = 0.f;

    for (int k0 = 0; k0 < K; k0 += BK) {
        float4 a0 = *(const float4*)(Ag + k0);
        float4 a1 = *(const float4*)(Ag + k0 + 4);
        As[aCol + 0][aRow] = a0.x;  As[aCol + 1][aRow] = a0.y;
        As[aCol + 2][aRow] = a0.z;  As[aCol + 3][aRow] = a0.w;
        As[aCol + 4][aRow] = a1.x;  As[aCol + 5][aRow] = a1.y;
        As[aCol + 6][aRow] = a1.z;  As[aCol + 7][aRow] = a1.w;
        *(float4*)&Bs[bRow][bCol] = *(const float4*)(Bg + (size_t)k0 * N);
        __syncthreads();
#pragma unroll
        for (int k = 0; k < BK; k++) {
            float ra[TM], rb[TN];
#pragma unroll
            for (int i = 0; i < TM; i++) ra[i] = As[k][tr + i];
#pragma unroll
            for (int j = 0; j < TN; j++) rb[j] = Bs[k][tc + j];
#pragma unroll
            for (int i = 0; i < TM; i++)
#pragma unroll
                for (int j = 0; j < TN; j++) acc[i][j] = fmaf(ra[i], rb[j], acc[i][j]);
        }
        __syncthreads();
    }
    float4 bv = make_float4(0.f, 0.f, 0.f, 0.f);
    if (BIAS) bv = *(const float4*)(bias + bx * BN + tc);
#pragma unroll
    for (int i = 0; i < TM; i++) {
        const size_t off = (size_t)(by * BM + tr + i) * N + bx * BN + tc;
        float4 v = make_float4(acc[i][0], acc[i][1], acc[i][2], acc[i][3]);
        if (BIAS) { v.x += bv.x; v.y += bv.y; v.z += bv.z; v.w += bv.w; }
        if (RELU) {
            v.x = fmaxf(v.x, 0.f); v.y = fmaxf(v.y, 0.f);
            v.z = fmaxf(v.z, 0.f); v.w = fmaxf(v.w, 0.f);
        }
        *(float4*)(C + off) = v;
    }
}

__global__ void bn_partial_k(const float* __restrict__ x, float* __restrict__ psum,
                             float* __restrict__ psq)
{
    const int t = threadIdx.x;
    const float* p = x + (size_t)blockIdx.x * 128 * HH + t;
    float s = 0.f, q = 0.f;
#pragma unroll 4
    for (int r = 0; r < 128; r++) { float v = p[(size_t)r * HH]; s += v; q += v * v; }
    psum[blockIdx.x * HH + t] = s;
    psq [blockIdx.x * HH + t] = q;
}

__global__ void bn_finalize_k(const float* __restrict__ psum, const float* __restrict__ psq,
                              const float* __restrict__ gamma, const float* __restrict__ beta,
                              float* __restrict__ scale, float* __restrict__ shift)
{
    const int t = threadIdx.x;
    float s = 0.f, q = 0.f;
#pragma unroll
    for (int b = 0; b < 64; b++) { s += psum[b * HH + t]; q += psq[b * HH + t]; }
    const float invn = 1.f / (float)NN;
    const float m = s * invn;
    const float var = q * invn - m * m;
    const float sc = gamma[t] * rsqrtf(var + EPSB);
    scale[t] = sc;
    shift[t] = beta[t] - m * sc;
}

template <bool SPLIT>
__global__ void bn_apply_k(float* __restrict__ x, const float* __restrict__ scale,
                           const float* __restrict__ shift,
                           __nv_bfloat16* __restrict__ oh, __nv_bfloat16* __restrict__ ol)
{
    const int i = blockIdx.x * blockDim.x + threadIdx.x;
    const int c = (i * 4) & (HH - 1);
    float4 v = ((float4*)x)[i];
    v.x = fmaf(v.x, scale[c + 0], shift[c + 0]);
    v.y = fmaf(v.y, scale[c + 1], shift[c + 1]);
    v.z = fmaf(v.z, scale[c + 2], shift[c + 2]);
    v.w = fmaf(v.w, scale[c + 3], shift[c + 3]);
    ((float4*)x)[i] = v;
    if (SPLIT) {
        __nv_bfloat16 h0, h1, h2, h3, l0, l1, l2, l3;
        split2(v.x, h0, l0); split2(v.y, h1, l1); split2(v.z, h2, l2); split2(v.w, h3, l3);
        uint2 hp, lp;
        hp.x = (uint32_t)__bfloat16_as_ushort(h0) | ((uint32_t)__bfloat16_as_ushort(h1) << 16);
        hp.y = (uint32_t)__bfloat16_as_ushort(h2) | ((uint32_t)__bfloat16_as_ushort(h3) << 16);
        lp.x = (uint32_t)__bfloat16_as_ushort(l0) | ((uint32_t)__bfloat16_as_ushort(l1) << 16);
        lp.y = (uint32_t)__bfloat16_as_ushort(l2) | ((uint32_t)__bfloat16_as_ushort(l3) << 16);
        ((uint2*)oh)[i] = hp;
        ((uint2*)ol)[i] = lp;
    }
}

__global__ void pool_k(const float* __restrict__ h1, const float* __restrict__ h2,
                       float* __restrict__ pooled)
{
    const int g = blockIdx.x, t = threadIdx.x;
    const size_t r0 = (size_t)g * NPG;
    float mx1 = -1e30f, mx2 = -1e30f, s1 = 0.f, s2 = 0.f;
#pragma unroll 4
    for (int r = 0; r < NPG; r++) {
        float v1 = h1[(r0 + r) * HH + t];
        float v2 = h2[(r0 + r) * HH + t];
        mx1 = fmaxf(mx1, v1); s1 += v1;
        mx2 = fmaxf(mx2, v2); s2 += v2;
    }
    float* out = pooled + (size_t)g * 1024;
    out[t]       = mx1;
    out[256 + t] = mx2;
    out[512 + t] = s1 * (1.f / NPG);
    out[768 + t] = s2 * (1.f / NPG);
}

__global__ void bn_small_k(const float* __restrict__ in, const float* __restrict__ gamma,
                           const float* __restrict__ beta, float* __restrict__ out, int C)
{
    const int c = blockIdx.x * blockDim.x + threadIdx.x;
    if (c >= C) return;
    float s = 0.f, q = 0.f;
    for (int r = 0; r < GG; r++) { float v = in[(size_t)r * C + c]; s += v; q += v * v; }
    const float m = s * (1.f / GG);
    const float var = q * (1.f / GG) - m * m;
    const float sc = gamma[c] * rsqrtf(var + EPSB);
    const float sh = beta[c] - m * sc;
    for (int r = 0; r < GG; r++) out[(size_t)r * C + c] = fmaf(in[(size_t)r * C + c], sc, sh);
}

__global__ void dense_small_k(const float* __restrict__ A, const float* __restrict__ W,
                              const float* __restrict__ b, float* __restrict__ C,
                              int M, int N, int K)
{
    const int idx = blockIdx.x * blockDim.x + threadIdx.x;
    if (idx >= M * N) return;
    const int m = idx / N, n = idx - m * N;
    float acc = b[n];
    const float* a = A + (size_t)m * K;
    for (int k = 0; k < K; k++) acc = fmaf(a[k], W[(size_t)k * N + n], acc);
    C[idx] = acc;
}

extern "C" void kernel_launch(void* const* d_in, const int* in_sizes, int n_in,
                              void* d_out, int out_size)
{
    const float* x    = (const float*)d_in[0];
    const float* adj  = (const float*)d_in[1];
    const float* W1   = (const float*)d_in[3];
    const float* Ws1  = (const float*)d_in[4];
    const float* b1   = (const float*)d_in[5];
    const float* g1   = (const float*)d_in[6];
    const float* be1  = (const float*)d_in[7];
    const float* W2   = (const float*)d_in[8];
    const float* Ws2  = (const float*)d_in[9];
    const float* b2   = (const float*)d_in[10];
    const float* g2   = (const float*)d_in[11];
    const float* be2  = (const float*)d_in[12];
    const float* bn0g = (const float*)d_in[13];
    const float* bn0b = (const float*)d_in[14];
    const float* L1W  = (const float*)d_in[15];
    const float* L1b  = (const float*)d_in[16];
    const float* bn1g = (const float*)d_in[17];
    const float* bn1b = (const float*)d_in[18];
    const float* L2W  = (const float*)d_in[19];
    const float* L2b  = (const float*)d_in[20];
    const float* bn2g = (const float*)d_in[21];
    const float* bn2b = (const float*)d_in[22];
    const float* L3W  = (const float*)d_in[23];
    const float* L3b  = (const float*)d_in[24];
    const float* catW = (const float*)d_in[25];
    const float* catb = (const float*)d_in[26];

    float* out = (float*)d_out;
    float* out_main  = out;
    float* out_class = out + 256 * 128;
    float* out_fp    = out + 256 * 128 + 256 * 12;

    __nv_bfloat16 *adjh, *adjl, *xTh, *xTl, *A1h, *A1l, *B1h, *B1l;
    __nv_bfloat16 *h1h, *h1l, *W2Th, *W2Tl, *B2h, *B2l;
    float *axp, *pre1, *g2in, *pre2, *pool, *bnp, *l1, *bn1, *l2, *psum, *psq, *scale, *shift;
    cudaGetSymbolAddress((void**)&adjh, g_adj_h);
    cudaGetSymbolAddress((void**)&adjl, g_adj_l);
    cudaGetSymbolAddress((void**)&xTh,  g_xT_h);
    cudaGetSymbolAddress((void**)&xTl,  g_xT_l);
    cudaGetSymbolAddress((void**)&axp,  g_axp);
    cudaGetSymbolAddress((void**)&A1h,  g_A1_h);
    cudaGetSymbolAddress((void**)&A1l,  g_A1_l);
    cudaGetSymbolAddress((void**)&B1h,  g_B1_h);
    cudaGetSymbolAddress((void**)&B1l,  g_B1_l);
    cudaGetSymbolAddress((void**)&pre1, g_pre1);
    cudaGetSymbolAddress((void**)&h1h,  g_h1_h);
    cudaGetSymbolAddress((void**)&h1l,  g_h1_l);
    cudaGetSymbolAddress((void**)&W2Th, g_W2T_h);
    cudaGetSymbolAddress((void**)&W2Tl, g_W2T_l);
    cudaGetSymbolAddress((void**)&g2in, g_g2in);
    cudaGetSymbolAddress((void**)&B2h,  g_B2_h);
    cudaGetSymbolAddress((void**)&B2l,  g_B2_l);
    cudaGetSymbolAddress((void**)&pre2, g_pre2);
    cudaGetSymbolAddress((void**)&pool, g_pool);
    cudaGetSymbolAddress((void**)&bnp,  g_bnp);
    cudaGetSymbolAddress((void**)&l1,   g_l1);
    cudaGetSymbolAddress((void**)&bn1,  g_bn1);
    cudaGetSymbolAddress((void**)&l2,   g_l2);
    cudaGetSymbolAddress((void**)&psum, g_psum);
    cudaGetSymbolAddress((void**)&psq,  g_psq);
    cudaGetSymbolAddress((void**)&scale,g_scale);
    cudaGetSymbolAddress((void**)&shift,g_shift);

    static bool attr_done = false;
    if (!attr_done) {
        cudaFuncSetAttribute(mma2_k<false, false>, cudaFuncAttributeMaxDynamicSharedMemorySize, 122880);
        cudaFuncSetAttribute(mma2_k<true, true>,   cudaFuncAttributeMaxDynamicSharedMemorySize, 122880);
        attr_done = true;
    }

    // prep
    split_k<<<NN * NN / 4 / 256, 256>>>(adj, adjh, adjl);
    transconv_k<<<dim3(FF / 32, NN / 32), dim3(32, 8)>>>(x, xTh, xTl, FF, NN, 0);
    split_into_k<<<NN * FF / 256, 256>>>(x, A1h, A1l, FF, HH, FF);
    transconv_k<<<dim3(HH / 32, FF / 32), dim3(32, 8)>>>(W1,  B1h, B1l, HH, HH, 0);
    transconv_k<<<dim3(HH / 32, FF / 32), dim3(32, 8)>>>(Ws1, B1h, B1l, HH, HH, FF);
    transconv_k<<<dim3(HH / 32, HH / 32), dim3(32, 8)>>>(W2,  W2Th, W2Tl, HH, HH, 0);
    transconv_k<<<dim3(HH / 32, HH / 32), dim3(32, 8)>>>(Ws2, B2h, B2l, HH, K2TOT, NN);

    // layer 1: ax = adj @ x (split-K2)
    mma2_k<false, false><<<dim3(1, NN / 128), 256, 122880>>>(
        adjh, adjl, NN, BIGK, (const __nv_bfloat16*)0, (const __nv_bfloat16*)0, 0, xTh, xTl, NN,
        axp, (const float*)0, FF, 128, 0);
    mma2_k<false, false><<<dim3(1, NN / 128), 256, 122880>>>(
        adjh, adjl, NN, BIGK, (const __nv_bfloat16*)0, (const __nv_bfloat16*)0, 0, xTh, xTl, NN,
        axp + (size_t)NN * FF, (const float*)0, FF, 128, 128);
    combine_ax_k<<<NN * FF / 256, 256>>>(axp, axp + (size_t)NN * FF, A1h, A1l);
    // pre1 = relu([ax|x] @ [W1;Ws1]^T + b1)
    mma2_k<true, true><<<dim3(2, NN / 128), 256, 122880>>>(
        A1h, A1l, HH, BIGK, (const __nv_bfloat16*)0, (const __nv_bfloat16*)0, 0, B1h, B1l, HH,
        pre1, b1, HH, 8, 0);
    bn_partial_k<<<64, 256>>>(pre1, psum, psq);
    bn_finalize_k<<<1, 256>>>(psum, psq, g1, be1, scale, shift);
    bn_apply_k<true><<<(NN * HH / 4) / 256, 256>>>(pre1, scale, shift, h1h, h1l);

    // layer 2: g2in = h1 @ W2
    mma2_k<false, false><<<dim3(2, NN / 128), 256, 122880>>>(
        h1h, h1l, HH, BIGK, (const __nv_bfloat16*)0, (const __nv_bfloat16*)0, 0, W2Th, W2Tl, HH,
        g2in, (const float*)0, HH, 8, 0);
    transconv_k<<<dim3(HH / 32, NN / 32), dim3(32, 8)>>>(g2in, B2h, B2l, HH, K2TOT, 0);
    // pre2 = relu([adj|h1] @ [g2in;Ws2]^T + b2)
    mma2_k<true, true><<<dim3(2, NN / 128), 256, 122880>>>(
        adjh, adjl, NN, NN / 32, h1h, h1l, HH, B2h, B2l, K2TOT,
        pre2, b2, HH, K2TOT / 32, 0);
    bn_partial_k<<<64, 256>>>(pre2, psum, psq);
    bn_finalize_k<<<1, 256>>>(psum, psq, g2, be2, scale, shift);
    bn_apply_k<false><<<(NN * HH / 4) / 256, 256>>>(pre2, scale, shift, (__nv_bfloat16*)0, (__nv_bfloat16*)0);

    // pooling
    pool_k<<<GG, 256>>>(pre1, pre2, pool);

    // MLP head
    bn_small_k<<<8, 128>>>(pool, bn0g, bn0b, bnp, 1024);
    sgemm_k<true, true><<<dim3(512 / 64, GG / 128), 256>>>(bnp, L1W, l1, L1b, GG, 512, 1024);
    bn_small_k<<<4, 128>>>(l1, bn1g, bn1b, bn1, 512);
    sgemm_k<true, true><<<dim3(256 / 64, GG / 128), 256>>>(bn1, L2W, l2, L2b, GG, 256, 512);
    bn_small_k<<<2, 128>>>(l2, bn2g, bn2b, out_fp, 256);
    dense_small_k<<<(256 * 128 + 255) / 256, 256>>>(out_fp, L3W, L3b, out_main, 256, 128, 256);
    dense_small_k<<<(256 * 12 + 255) / 256, 256>>>(out_fp, catW, catb, out_class, 256, 12, 256);

    (void)in_sizes; (void)n_in; (void)out_size;
}

// round 9
// speedup vs baseline: 2.8554x; 1.4063x over previous
#include <cuda_runtime.h>
#include <cuda_fp16.h>
#include <math.h>
#include <stdint.h>

#define NN   8192
#define FF   128
#define HH   256
#define GG   256
#define NPG  32
#define EPSB 1e-5f
#define K2TOT (NN + HH)
#define BIGK (1 << 30)
#define ADJC 0.015625f

__device__ __half g_adjc [NN * NN];
__device__ __half g_xT_h [FF * NN];
__device__ __half g_xT_l [FF * NN];
__device__ float  g_axp  [2 * NN * FF];
__device__ float  g_biasax[FF];
__device__ float  g_bias2 [HH];
__device__ __half g_A1_h [NN * HH];
__device__ __half g_A1_l [NN * HH];
__device__ __half g_B1_h [HH * HH];
__device__ __half g_B1_l [HH * HH];
__device__ float  g_pre1 [NN * HH];
__device__ __half g_h1_h [NN * HH];
__device__ __half g_h1_l [NN * HH];
__device__ __half g_W2T_h[HH * HH];
__device__ __half g_W2T_l[HH * HH];
__device__ float  g_g2in [NN * HH];
__device__ __half g_B2_h [HH * K2TOT];
__device__ __half g_B2_l [HH * K2TOT];
__device__ float  g_pre2 [NN * HH];
__device__ float  g_pool [GG * 1024];
__device__ float  g_bnp  [GG * 1024];
__device__ float  g_l1   [GG * 512];
__device__ float  g_bn1  [GG * 512];
__device__ float  g_l2   [GG * 256];
__device__ float  g_psum [64 * HH];
__device__ float  g_psq  [64 * HH];
__device__ float  g_scale[HH];
__device__ float  g_shift[HH];

__device__ __forceinline__ uint32_t smem_u32(const void* p) {
    uint32_t a;
    asm("{ .reg .u64 t; cvta.to.shared.u64 t, %1; cvt.u32.u64 %0, t; }" : "=r"(a) : "l"(p));
    return a;
}
__device__ __forceinline__ void ldsm4(uint32_t* r, uint32_t addr) {
    asm volatile("ldmatrix.sync.aligned.m8n8.x4.shared.b16 {%0,%1,%2,%3}, [%4];"
        : "=r"(r[0]), "=r"(r[1]), "=r"(r[2]), "=r"(r[3]) : "r"(addr));
}
__device__ __forceinline__ void mma16816(float* d, const uint32_t* a, uint32_t b0, uint32_t b1) {
    asm volatile("mma.sync.aligned.m16n8k16.row.col.f32.f16.f16.f32 "
        "{%0,%1,%2,%3}, {%4,%5,%6,%7}, {%8,%9}, {%0,%1,%2,%3};"
        : "+f"(d[0]), "+f"(d[1]), "+f"(d[2]), "+f"(d[3])
        : "r"(a[0]), "r"(a[1]), "r"(a[2]), "r"(a[3]), "r"(b0), "r"(b1));
}
#define CP_ASYNC16(dst, src) asm volatile("cp.async.cg.shared.global [%0], [%1], 16;" :: "r"(dst), "l"(src))
#define CP_COMMIT()          asm volatile("cp.async.commit_group;" ::: "memory")
#define CP_WAIT1()           asm volatile("cp.async.wait_group 1;" ::: "memory")

__device__ __forceinline__ void split2h(float v, __half& h, __half& l) {
    h = __float2half_rn(v);
    l = __float2half_rn(v - __half2float(h));
}

// fp16 tensor-core GEMM, 3-stage cp.async pipeline.
// PASSES==2: C = A @ (Bh + Bl)^T        (A single plane, split-B)
// PASSES==3: C = (Ah+Al) @ (Bh+Bl)^T    (3 products, lo*lo dropped)
// A may concatenate two single-plane sources along K (first nck1 chunks A1, rest A2).
// blockIdx.z: split-K partials (chunk window shifts by z*nck, C shifts by z*zCstride).
template <int PASSES, bool BIAS, bool RELU>
__global__ void __launch_bounds__(256, 2)
mma2_k(const __half* __restrict__ A1h, const __half* __restrict__ A1l, int strA1, int nck1,
       const __half* __restrict__ A2h, int strA2,
       const __half* __restrict__ Bh,  const __half* __restrict__ Bl,  int strB,
       float* __restrict__ C, const float* __restrict__ bias, int Ntot,
       int nck, int ck0, size_t zCstride)
{
    constexpr int PLANE = 5120;                       // 128*40 halfs
    constexpr int STG_E = (PASSES == 3) ? 20480 : 15360;
    constexpr int AL_O  = PLANE;                      // only for PASSES==3
    constexpr int B_O   = (PASSES == 3) ? 2 * PLANE : PLANE;
    constexpr int BL_O  = B_O + PLANE;

    extern __shared__ __align__(16) __half sm[];
    const int tid  = threadIdx.x;
    const int wid  = tid >> 5;
    const int lane = tid & 31;
    const int m0 = blockIdx.y * 128;
    const int n0 = blockIdx.x * 128;
    const int wm = (wid & 3) * 32;
    const int wn = (wid >> 2) * 64;

    ck0 += blockIdx.z * nck;
    C   += blockIdx.z * zCstride;

    float acc[2][8][4];
#pragma unroll
    for (int i = 0; i < 2; i++)
#pragma unroll
        for (int j = 0; j < 8; j++)
#pragma unroll
            for (int v = 0; v < 4; v++) acc[i][j][v] = 0.f;

    auto loadStage = [&](int lck, int stg) {
        const int g = ck0 + lck;
        const __half* ah;
        const __half* al = A1l;
        int kloc, strA;
        if (g < nck1) { ah = A1h; strA = strA1; kloc = g * 32; }
        else          { ah = A2h; strA = strA2; kloc = (g - nck1) * 32; }
        const uint32_t sA  = smem_u32(sm + stg * STG_E);
        const uint32_t sAl = smem_u32(sm + stg * STG_E + AL_O);
        const uint32_t sBh = smem_u32(sm + stg * STG_E + B_O);
        const uint32_t sBl = smem_u32(sm + stg * STG_E + BL_O);
        const int kb = g * 32;
#pragma unroll
        for (int it = 0; it < 2; it++) {
            const int i = tid + it * 256;
            const int r = i >> 2, c = i & 3;
            const uint32_t so = (uint32_t)(r * 40 + c * 8) * 2;
            CP_ASYNC16(sA + so, ah + (size_t)(m0 + r) * strA + kloc + c * 8);
            if (PASSES == 3) CP_ASYNC16(sAl + so, al + (size_t)(m0 + r) * strA + kloc + c * 8);
            CP_ASYNC16(sBh + so, Bh + (size_t)(n0 + r) * strB + kb + c * 8);
            CP_ASYNC16(sBl + so, Bl + (size_t)(n0 + r) * strB + kb + c * 8);
        }
        CP_COMMIT();
    };

    loadStage(0, 0);
    if (nck > 1) loadStage(1, 1); else CP_COMMIT();
    CP_WAIT1();
    __syncthreads();

    for (int ck = 0; ck < nck; ck++) {
        const int stg = ck % 3;
        const uint32_t sA  = smem_u32(sm + stg * STG_E);
        const uint32_t sAl = smem_u32(sm + stg * STG_E + AL_O);
        const uint32_t sBh = smem_u32(sm + stg * STG_E + B_O);
        const uint32_t sBl = smem_u32(sm + stg * STG_E + BL_O);

#pragma unroll
        for (int ks = 0; ks < 2; ks++) {
            uint32_t af[2][4], alf[2][4];
#pragma unroll
            for (int i = 0; i < 2; i++) {
                const int row = wm + i * 16 + (lane & 15);
                const int col = ks * 16 + (lane >> 4) * 8;
                ldsm4(af[i], sA + (uint32_t)(row * 40 + col) * 2);
                if (PASSES == 3) ldsm4(alf[i], sAl + (uint32_t)(row * 40 + col) * 2);
            }
#pragma unroll
            for (int half = 0; half < 2; half++) {
                uint32_t bh[8], bl[8];
#pragma unroll
                for (int jp = 0; jp < 2; jp++) {
                    const int g = lane >> 3;
                    const int row = wn + (half * 4 + jp * 2 + (g >> 1)) * 8 + (lane & 7);
                    const int col = ks * 16 + (g & 1) * 8;
                    ldsm4(&bh[jp * 4], sBh + (uint32_t)(row * 40 + col) * 2);
                    ldsm4(&bl[jp * 4], sBl + (uint32_t)(row * 40 + col) * 2);
                }
#pragma unroll
                for (int i = 0; i < 2; i++)
#pragma unroll
                    for (int t = 0; t < 4; t++)
                        mma16816(acc[i][half * 4 + t], af[i], bh[t * 2], bh[t * 2 + 1]);
#pragma unroll
                for (int i = 0; i < 2; i++)
#pragma unroll
                    for (int t = 0; t < 4; t++)
                        mma16816(acc[i][half * 4 + t], af[i], bl[t * 2], bl[t * 2 + 1]);
                if (PASSES == 3) {
#pragma unroll
                    for (int i = 0; i < 2; i++)
#pragma unroll
                        for (int t = 0; t < 4; t++)
                            mma16816(acc[i][half * 4 + t], alf[i], bh[t * 2], bh[t * 2 + 1]);
                }
            }
        }

        if (ck + 2 < nck) loadStage(ck + 2, (ck + 2) % 3); else CP_COMMIT();
        CP_WAIT1();
        __syncthreads();
    }

#pragma unroll
    for (int i = 0; i < 2; i++) {
        const int r0 = m0 + wm + i * 16 + (lane >> 2);
#pragma unroll
        for (int j = 0; j < 8; j++) {
            const int cc = n0 + wn + j * 8 + (lane & 3) * 2;
            const size_t o0 = (size_t)r0 * Ntot + cc;
            const size_t o1 = (size_t)(r0 + 8) * Ntot + cc;
            float2 v0 = make_float2(acc[i][j][0], acc[i][j][1]);
            float2 v1 = make_float2(acc[i][j][2], acc[i][j][3]);
            if (BIAS) {
                const float2 bv = *(const float2*)(bias + cc);
                v0.x += bv.x; v0.y += bv.y; v1.x += bv.x; v1.y += bv.y;
            }
            if (RELU) {
                v0.x = fmaxf(v0.x, 0.f); v0.y = fmaxf(v0.y, 0.f);
                v1.x = fmaxf(v1.x, 0.f); v1.y = fmaxf(v1.y, 0.f);
            }
            *(float2*)(C + o0) = v0;
            *(float2*)(C + o1) = v1;
        }
    }
}

// adj fp32 -> (adj - 1/64) fp16 single plane
__global__ void cvt_adj_k(const float* __restrict__ in, __half* __restrict__ o)
{
    const int i = blockIdx.x * blockDim.x + threadIdx.x;
    float4 v = ((const float4*)in)[i];
    v.x -= ADJC; v.y -= ADJC; v.z -= ADJC; v.w -= ADJC;
    __half2 a = __floats2half2_rn(v.x, v.y);
    __half2 b = __floats2half2_rn(v.z, v.w);
    uint2 p;
    p.x = *(uint32_t*)&a;
    p.y = *(uint32_t*)&b;
    ((uint2*)o)[i] = p;
}

// out[c] = addend[c] + scale * sum_r in[r][c]   (one block per column)
__global__ void colsum_k(const float* __restrict__ in, int R, int C,
                         float scale, const float* __restrict__ addend,
                         float* __restrict__ out)
{
    __shared__ float red[256];
    const int c = blockIdx.x;
    float s = 0.f;
    for (int r = threadIdx.x; r < R; r += 256) s += in[(size_t)r * C + c];
    red[threadIdx.x] = s;
    __syncthreads();
    for (int o = 128; o > 0; o >>= 1) {
        if (threadIdx.x < o) red[threadIdx.x] += red[threadIdx.x + o];
        __syncthreads();
    }
    if (threadIdx.x == 0) out[c] = (addend ? addend[c] : 0.f) + scale * red[0];
}

// in[R][C] -> hi/lo fp16 into out rows stride ostr at column offset ooff
__global__ void split_into_k(const float* __restrict__ in, __half* __restrict__ oh,
                             __half* __restrict__ ol, int C, int ostr, int ooff)
{
    const int idx = blockIdx.x * blockDim.x + threadIdx.x;
    const int r = idx / C, c = idx - r * C;
    __half h, l;
    split2h(in[idx], h, l);
    oh[(size_t)r * ostr + ooff + c] = h;
    ol[(size_t)r * ostr + ooff + c] = l;
}

// combine split-K partials + bias, write hi/lo fp16 into A1 cols [0,128)
__global__ void combine_ax_k(const float* __restrict__ a0, const float* __restrict__ a1,
                             const float* __restrict__ bias,
                             __half* __restrict__ oh, __half* __restrict__ ol)
{
    const int idx = blockIdx.x * blockDim.x + threadIdx.x;
    const int r = idx >> 7, c = idx & 127;
    __half h, l;
    split2h(a0[idx] + a1[idx] + bias[c], h, l);
    oh[(size_t)r * HH + c] = h;
    ol[(size_t)r * HH + c] = l;
}

// transpose + hi/lo split: out[c][koff + r] = in[r][c], out stride ostr
__global__ void transconv2_k(const float* __restrict__ in, __half* __restrict__ oh,
                             __half* __restrict__ ol, int C, int ostr, int koff)
{
    __shared__ float t[32][33];
    const int c0 = blockIdx.x * 32, r0 = blockIdx.y * 32;
    const int tx = threadIdx.x, ty = threadIdx.y;
#pragma unroll
    for (int j = 0; j < 4; j++)
        t[ty + j * 8][tx] = in[(size_t)(r0 + ty + j * 8) * C + c0 + tx];
    __syncthreads();
#pragma unroll
    for (int j = 0; j < 4; j++) {
        __half h, l;
        split2h(t[tx][ty + j * 8], h, l);
        const size_t o = (size_t)(c0 + ty + j * 8) * ostr + koff + r0 + tx;
        oh[o] = h; ol[o] = l;
    }
}

template <bool BIAS, bool RELU>
__global__ void __launch_bounds__(256, 3)
sgemm_k(const float* __restrict__ A, const float* __restrict__ B,
        float* __restrict__ C, const float* __restrict__ bias, int M, int N, int K)
{
    constexpr int BM = 128, BN = 64, BK = 16, TM = 8, TN = 4;
    __shared__ float As[BK][BM];
    __shared__ float Bs[BK][BN];
    const int tid = threadIdx.x;
    const int bx = blockIdx.x, by = blockIdx.y;
    const int aRow = tid >> 1, aCol = (tid & 1) * 8;
    const float* Ag = A + (size_t)(by * BM + aRow) * K + aCol;
    const int bRow = tid >> 4, bCol = (tid & 15) * 4;
    const float* Bg = B + (size_t)bRow * N + bx * BN + bCol;
    const int tr = (tid >> 4) * TM, tc = (tid & 15) * TN;

    float acc[TM][TN];
#pragma unroll
    for (int i = 0; i < TM; i++)
#pragma unroll
        for (int j = 0; j < TN; j++) acc[i][j] = 0.f;

    for (int k0 = 0; k0 < K; k0 += BK) {
        float4 a0 = *(const float4*)(Ag + k0);
        float4 a1 = *(const float4*)(Ag + k0 + 4);
        As[aCol + 0][aRow] = a0.x;  As[aCol + 1][aRow] = a0.y;
        As[aCol + 2][aRow] = a0.z;  As[aCol + 3][aRow] = a0.w;
        As[aCol + 4][aRow] = a1.x;  As[aCol + 5][aRow] = a1.y;
        As[aCol + 6][aRow] = a1.z;  As[aCol + 7][aRow] = a1.w;
        *(float4*)&Bs[bRow][bCol] = *(const float4*)(Bg + (size_t)k0 * N);
        __syncthreads();
#pragma unroll
        for (int k = 0; k < BK; k++) {
            float ra[TM], rb[TN];
#pragma unroll
            for (int i = 0; i < TM; i++) ra[i] = As[k][tr + i];
#pragma unroll
            for (int j = 0; j < TN; j++) rb[j] = Bs[k][tc + j];
#pragma unroll
            for (int i = 0; i < TM; i++)
#pragma unroll
                for (int j = 0; j < TN; j++) acc[i][j] = fmaf(ra[i], rb[j], acc[i][j]);
        }
        __syncthreads();
    }
    float4 bv = make_float4(0.f, 0.f, 0.f, 0.f);
    if (BIAS) bv = *(const float4*)(bias + bx * BN + tc);
#pragma unroll
    for (int i = 0; i < TM; i++) {
        const size_t off = (size_t)(by * BM + tr + i) * N + bx * BN + tc;
        float4 v = make_float4(acc[i][0], acc[i][1], acc[i][2], acc[i][3]);
        if (BIAS) { v.x += bv.x; v.y += bv.y; v.z += bv.z; v.w += bv.w; }
        if (RELU) {
            v.x = fmaxf(v.x, 0.f); v.y = fmaxf(v.y, 0.f);
            v.z = fmaxf(v.z, 0.f); v.w = fmaxf(v.w, 0.f);
        }
        *(float4*)(C + off) = v;
    }
}

__global__ void bn_partial_k(const float* __restrict__ x, float* __restrict__ psum,
                             float* __restrict__ psq)
{
    const int t = threadIdx.x;
    const float* p = x + (size_t)blockIdx.x * 128 * HH + t;
    float s = 0.f, q = 0.f;
#pragma unroll 4
    for (int r = 0; r < 128; r++) { float v = p[(size_t)r * HH]; s += v; q += v * v; }
    psum[blockIdx.x * HH + t] = s;
    psq [blockIdx.x * HH + t] = q;
}

__global__ void bn_finalize_k(const float* __restrict__ psum, const float* __restrict__ psq,
                              const float* __restrict__ gamma, const float* __restrict__ beta,
                              float* __restrict__ scale, float* __restrict__ shift)
{
    const int t = threadIdx.x;
    float s = 0.f, q = 0.f;
#pragma unroll
    for (int b = 0; b < 64; b++) { s += psum[b * HH + t]; q += psq[b * HH + t]; }
    const float invn = 1.f / (float)NN;
    const float m = s * invn;
    const float var = q * invn - m * m;
    const float sc = gamma[t] * rsqrtf(var + EPSB);
    scale[t] = sc;
    shift[t] = beta[t] - m * sc;
}

template <bool CVT>
__global__ void bn_apply_k(float* __restrict__ x, const float* __restrict__ scale,
                           const float* __restrict__ shift,
                           __half* __restrict__ oh, __half* __restrict__ ol)
{
    const int i = blockIdx.x * blockDim.x + threadIdx.x;
    const int c = (i * 4) & (HH - 1);
    float4 v = ((float4*)x)[i];
    v.x = fmaf(v.x, scale[c + 0], shift[c + 0]);
    v.y = fmaf(v.y, scale[c + 1], shift[c + 1]);
    v.z = fmaf(v.z, scale[c + 2], shift[c + 2]);
    v.w = fmaf(v.w, scale[c + 3], shift[c + 3]);
    ((float4*)x)[i] = v;
    if (CVT) {
        __half h0, h1, h2, h3, l0, l1, l2, l3;
        split2h(v.x, h0, l0); split2h(v.y, h1, l1);
        split2h(v.z, h2, l2); split2h(v.w, h3, l3);
        __half2 ph0 = __halves2half2(h0, h1), ph1 = __halves2half2(h2, h3);
        __half2 pl0 = __halves2half2(l0, l1), pl1 = __halves2half2(l2, l3);
        uint2 hp, lp;
        hp.x = *(uint32_t*)&ph0; hp.y = *(uint32_t*)&ph1;
        lp.x = *(uint32_t*)&pl0; lp.y = *(uint32_t*)&pl1;
        ((uint2*)oh)[i] = hp;
        ((uint2*)ol)[i] = lp;
    }
}

__global__ void pool_k(const float* __restrict__ h1, const float* __restrict__ h2,
                       float* __restrict__ pooled)
{
    const int g = blockIdx.x, t = threadIdx.x;
    const size_t r0 = (size_t)g * NPG;
    float mx1 = -1e30f, mx2 = -1e30f, s1 = 0.f, s2 = 0.f;
#pragma unroll 4
    for (int r = 0; r < NPG; r++) {
        float v1 = h1[(r0 + r) * HH + t];
        float v2 = h2[(r0 + r) * HH + t];
        mx1 = fmaxf(mx1, v1); s1 += v1;
        mx2 = fmaxf(mx2, v2); s2 += v2;
    }
    float* out = pooled + (size_t)g * 1024;
    out[t]       = mx1;
    out[256 + t] = mx2;
    out[512 + t] = s1 * (1.f / NPG);
    out[768 + t] = s2 * (1.f / NPG);
}

__global__ void bn_small_k(const float* __restrict__ in, const float* __restrict__ gamma,
                           const float* __restrict__ beta, float* __restrict__ out, int C)
{
    const int c = blockIdx.x * blockDim.x + threadIdx.x;
    if (c >= C) return;
    float s = 0.f, q = 0.f;
    for (int r = 0; r < GG; r++) { float v = in[(size_t)r * C + c]; s += v; q += v * v; }
    const float m = s * (1.f / GG);
    const float var = q * (1.f / GG) - m * m;
    const float sc = gamma[c] * rsqrtf(var + EPSB);
    const float sh = beta[c] - m * sc;
    for (int r = 0; r < GG; r++) out[(size_t)r * C + c] = fmaf(in[(size_t)r * C + c], sc, sh);
}

__global__ void dense_small_k(const float* __restrict__ A, const float* __restrict__ W,
                              const float* __restrict__ b, float* __restrict__ C,
                              int M, int N, int K)
{
    const int idx = blockIdx.x * blockDim.x + threadIdx.x;
    if (idx >= M * N) return;
    const int m = idx / N, n = idx - m * N;
    float acc = b[n];
    const float* a = A + (size_t)m * K;
    for (int k = 0; k < K; k++) acc = fmaf(a[k], W[(size_t)k * N + n], acc);
    C[idx] = acc;
}

extern "C" void kernel_launch(void* const* d_in, const int* in_sizes, int n_in,
                              void* d_out, int out_size)
{
    const float* x    = (const float*)d_in[0];
    const float* adj  = (const float*)d_in[1];
    const float* W1   = (const float*)d_in[3];
    const float* Ws1  = (const float*)d_in[4];
    const float* b1   = (const float*)d_in[5];
    const float* g1   = (const float*)d_in[6];
    const float* be1  = (const float*)d_in[7];
    const float* W2   = (const float*)d_in[8];
    const float* Ws2  = (const float*)d_in[9];
    const float* b2   = (const float*)d_in[10];
    const float* g2   = (const float*)d_in[11];
    const float* be2  = (const float*)d_in[12];
    const float* bn0g = (const float*)d_in[13];
    const float* bn0b = (const float*)d_in[14];
    const float* L1W  = (const float*)d_in[15];
    const float* L1b  = (const float*)d_in[16];
    const float* bn1g = (const float*)d_in[17];
    const float* bn1b = (const float*)d_in[18];
    const float* L2W  = (const float*)d_in[19];
    const float* L2b  = (const float*)d_in[20];
    const float* bn2g = (const float*)d_in[21];
    const float* bn2b = (const float*)d_in[22];
    const float* L3W  = (const float*)d_in[23];
    const float* L3b  = (const float*)d_in[24];
    const float* catW = (const float*)d_in[25];
    const float* catb = (const float*)d_in[26];

    float* out = (float*)d_out;
    float* out_main  = out;
    float* out_class = out + 256 * 128;
    float* out_fp    = out + 256 * 128 + 256 * 12;

    __half *adjc, *xTh, *xTl, *A1h, *A1l, *B1h, *B1l, *h1h, *h1l, *W2Th, *W2Tl, *B2h, *B2l;
    float *axp, *biasax, *bias2, *pre1, *g2in, *pre2, *pool, *bnp, *l1, *bn1, *l2;
    float *psum, *psq, *scale, *shift;
    cudaGetSymbolAddress((void**)&adjc,  g_adjc);
    cudaGetSymbolAddress((void**)&xTh,   g_xT_h);
    cudaGetSymbolAddress((void**)&xTl,   g_xT_l);
    cudaGetSymbolAddress((void**)&axp,   g_axp);
    cudaGetSymbolAddress((void**)&biasax,g_biasax);
    cudaGetSymbolAddress((void**)&bias2, g_bias2);
    cudaGetSymbolAddress((void**)&A1h,   g_A1_h);
    cudaGetSymbolAddress((void**)&A1l,   g_A1_l);
    cudaGetSymbolAddress((void**)&B1h,   g_B1_h);
    cudaGetSymbolAddress((void**)&B1l,   g_B1_l);
    cudaGetSymbolAddress((void**)&pre1,  g_pre1);
    cudaGetSymbolAddress((void**)&h1h,   g_h1_h);
    cudaGetSymbolAddress((void**)&h1l,   g_h1_l);
    cudaGetSymbolAddress((void**)&W2Th,  g_W2T_h);
    cudaGetSymbolAddress((void**)&W2Tl,  g_W2T_l);
    cudaGetSymbolAddress((void**)&g2in,  g_g2in);
    cudaGetSymbolAddress((void**)&B2h,   g_B2_h);
    cudaGetSymbolAddress((void**)&B2l,   g_B2_l);
    cudaGetSymbolAddress((void**)&pre2,  g_pre2);
    cudaGetSymbolAddress((void**)&pool,  g_pool);
    cudaGetSymbolAddress((void**)&bnp,   g_bnp);
    cudaGetSymbolAddress((void**)&l1,    g_l1);
    cudaGetSymbolAddress((void**)&bn1,   g_bn1);
    cudaGetSymbolAddress((void**)&l2,    g_l2);
    cudaGetSymbolAddress((void**)&psum,  g_psum);
    cudaGetSymbolAddress((void**)&psq,   g_psq);
    cudaGetSymbolAddress((void**)&scale, g_scale);
    cudaGetSymbolAddress((void**)&shift, g_shift);

    static bool attr_done = false;
    if (!attr_done) {
        cudaFuncSetAttribute(mma2_k<2, false, false>, cudaFuncAttributeMaxDynamicSharedMemorySize, 92160);
        cudaFuncSetAttribute(mma2_k<2, true, true>,   cudaFuncAttributeMaxDynamicSharedMemorySize, 92160);
        cudaFuncSetAttribute(mma2_k<3, false, false>, cudaFuncAttributeMaxDynamicSharedMemorySize, 122880);
        cudaFuncSetAttribute(mma2_k<3, true, true>,   cudaFuncAttributeMaxDynamicSharedMemorySize, 122880);
        attr_done = true;
    }

    // prep
    cvt_adj_k<<<NN * NN / 4 / 256, 256>>>(adj, adjc);
    transconv2_k<<<dim3(FF / 32, NN / 32), dim3(32, 8)>>>(x, xTh, xTl, FF, NN, 0);
    split_into_k<<<NN * FF / 256, 256>>>(x, A1h, A1l, FF, HH, FF);
    transconv2_k<<<dim3(HH / 32, FF / 32), dim3(32, 8)>>>(W1,  B1h, B1l, HH, HH, 0);
    transconv2_k<<<dim3(HH / 32, FF / 32), dim3(32, 8)>>>(Ws1, B1h, B1l, HH, HH, FF);
    transconv2_k<<<dim3(HH / 32, HH / 32), dim3(32, 8)>>>(W2,  W2Th, W2Tl, HH, HH, 0);
    transconv2_k<<<dim3(HH / 32, HH / 32), dim3(32, 8)>>>(Ws2, B2h, B2l, HH, K2TOT, NN);
    colsum_k<<<FF, 256>>>(x, NN, FF, ADJC, (const float*)0, biasax);

    // layer 1: ax = adj_c @ x (2-pass split-B, split-K2 via z) + rank-1 correction in combine
    mma2_k<2, false, false><<<dim3(1, NN / 128, 2), 256, 92160>>>(
        adjc, (const __half*)0, NN, BIGK, (const __half*)0, 0, xTh, xTl, NN,
        axp, (const float*)0, FF, 128, 0, (size_t)NN * FF);
    combine_ax_k<<<NN * FF / 256, 256>>>(axp, axp + (size_t)NN * FF, biasax, A1h, A1l);
    // pre1 = relu([ax|x] @ [W1;Ws1]^T + b1)  (3-pass)
    mma2_k<3, true, true><<<dim3(2, NN / 128), 256, 122880>>>(
        A1h, A1l, HH, BIGK, (const __half*)0, 0, B1h, B1l, HH,
        pre1, b1, HH, 8, 0, 0);
    bn_partial_k<<<64, 256>>>(pre1, psum, psq);
    bn_finalize_k<<<1, 256>>>(psum, psq, g1, be1, scale, shift);
    bn_apply_k<true><<<(NN * HH / 4) / 256, 256>>>(pre1, scale, shift, h1h, h1l);

    // layer 2: g2in = h1 @ W2 (3-pass)
    mma2_k<3, false, false><<<dim3(2, NN / 128), 256, 122880>>>(
        h1h, h1l, HH, BIGK, (const __half*)0, 0, W2Th, W2Tl, HH,
        g2in, (const float*)0, HH, 8, 0, 0);
    transconv2_k<<<dim3(HH / 32, NN / 32), dim3(32, 8)>>>(g2in, B2h, B2l, HH, K2TOT, 0);
    colsum_k<<<HH, 256>>>(g2in, NN, HH, ADJC, b2, bias2);
    // pre2 = relu([adj_c|h1] @ [g2in;Ws2]^T + bias2)  (2-pass split-B)
    mma2_k<2, true, true><<<dim3(2, NN / 128), 256, 92160>>>(
        adjc, (const __half*)0, NN, NN / 32, h1h, HH, B2h, B2l, K2TOT,
        pre2, bias2, HH, K2TOT / 32, 0, 0);
    bn_partial_k<<<64, 256>>>(pre2, psum, psq);
    bn_finalize_k<<<1, 256>>>(psum, psq, g2, be2, scale, shift);
    bn_apply_k<false><<<(NN * HH / 4) / 256, 256>>>(pre2, scale, shift, (__half*)0, (__half*)0);

    // pooling
    pool_k<<<GG, 256>>>(pre1, pre2, pool);

    // MLP head
    bn_small_k<<<8, 128>>>(pool, bn0g, bn0b, bnp, 1024);
    sgemm_k<true, true><<<dim3(512 / 64, GG / 128), 256>>>(bnp, L1W, l1, L1b, GG, 512, 1024);
    bn_small_k<<<4, 128>>>(l1, bn1g, bn1b, bn1, 512);
    sgemm_k<true, true><<<dim3(256 / 64, GG / 128), 256>>>(bn1, L2W, l2, L2b, GG, 256, 512);
    bn_small_k<<<2, 128>>>(l2, bn2g, bn2b, out_fp, 256);
    dense_small_k<<<(256 * 128 + 255) / 256, 256>>>(out_fp, L3W, L3b, out_main, 256, 128, 256);
    dense_small_k<<<(256 * 12 + 255) / 256, 256>>>(out_fp, catW, catb, out_class, 256, 12, 256);

    (void)in_sizes; (void)n_in; (void)out_size;
}

// round 10
// speedup vs baseline: 3.1957x; 1.1192x over previous
#include <cuda_runtime.h>
#include <cuda_fp16.h>
#include <math.h>
#include <stdint.h>

#define NN   8192
#define FF   128
#define HH   256
#define GG   256
#define NPG  32
#define EPSB 1e-5f
#define K2TOT (NN + HH)
#define BIGK (1 << 30)
#define ADJC 0.015625f

__device__ __half g_adjc [NN * NN];
__device__ __half g_xT_h [FF * NN];
__device__ float  g_axp  [2 * NN * FF];
__device__ float  g_biasax[FF];
__device__ float  g_bias2 [HH];
__device__ __half g_A1_h [NN * HH];
__device__ __half g_A1_l [NN * HH];
__device__ __half g_B1_h [HH * HH];
__device__ __half g_B1_l [HH * HH];
__device__ float  g_pre1 [NN * HH];
__device__ __half g_h1_h [NN * HH];
__device__ __half g_h1_l [NN * HH];
__device__ __half g_W2T_h[HH * HH];
__device__ __half g_W2T_l[HH * HH];
__device__ float  g_g2in [NN * HH];
__device__ __half g_B2_h [HH * K2TOT];
__device__ __half g_B2_l [HH * K2TOT];
__device__ float  g_pre2 [NN * HH];
__device__ float  g_pool [GG * 1024];
__device__ float  g_bnp  [GG * 1024];
__device__ float  g_l1   [GG * 512];
__device__ float  g_bn1  [GG * 512];
__device__ float  g_l2   [GG * 256];
__device__ float  g_psum [256 * HH];
__device__ float  g_psq  [256 * HH];
__device__ float  g_scale[HH];
__device__ float  g_shift[HH];

__device__ __forceinline__ uint32_t smem_u32(const void* p) {
    uint32_t a;
    asm("{ .reg .u64 t; cvta.to.shared.u64 t, %1; cvt.u32.u64 %0, t; }" : "=r"(a) : "l"(p));
    return a;
}
__device__ __forceinline__ void ldsm4(uint32_t* r, uint32_t addr) {
    asm volatile("ldmatrix.sync.aligned.m8n8.x4.shared.b16 {%0,%1,%2,%3}, [%4];"
        : "=r"(r[0]), "=r"(r[1]), "=r"(r[2]), "=r"(r[3]) : "r"(addr));
}
__device__ __forceinline__ void mma16816(float* d, const uint32_t* a, uint32_t b0, uint32_t b1) {
    asm volatile("mma.sync.aligned.m16n8k16.row.col.f32.f16.f16.f32 "
        "{%0,%1,%2,%3}, {%4,%5,%6,%7}, {%8,%9}, {%0,%1,%2,%3};"
        : "+f"(d[0]), "+f"(d[1]), "+f"(d[2]), "+f"(d[3])
        : "r"(a[0]), "r"(a[1]), "r"(a[2]), "r"(a[3]), "r"(b0), "r"(b1));
}
#define CP_ASYNC16(dst, src) asm volatile("cp.async.cg.shared.global [%0], [%1], 16;" :: "r"(dst), "l"(src))
#define CP_COMMIT()          asm volatile("cp.async.commit_group;" ::: "memory")
#define CP_WAIT1()           asm volatile("cp.async.wait_group 1;" ::: "memory")

__device__ __forceinline__ void split2h(float v, __half& h, __half& l) {
    h = __float2half_rn(v);
    l = __float2half_rn(v - __half2float(h));
}

// fp16 tensor-core GEMM, 3-stage cp.async pipeline.
// PASSES==1: C = A @ B^T               (both single plane)
// PASSES==2: C = A @ (Bh + Bl)^T       (A single, split-B)
// PASSES==3: C = (Ah+Al) @ (Bh+Bl)^T   (lo*lo dropped)
// A may concatenate two single-plane sources along K (first nck1 chunks A1, rest A2).
// blockIdx.z: split-K partials (chunk window shifts by z*nck, C shifts by z*zCstride).
#define PLANE 5120

template <int PASSES, bool BIAS, bool RELU>
__global__ void __launch_bounds__(256, 2)
mma2_k(const __half* __restrict__ A1h, const __half* __restrict__ A1l, int strA1, int nck1,
       const __half* __restrict__ A2h, int strA2,
       const __half* __restrict__ Bh,  const __half* __restrict__ Bl,  int strB,
       float* __restrict__ C, const float* __restrict__ bias, int Ntot,
       int nck, int ck0, size_t zCstride)
{
    constexpr int NA = (PASSES == 3) ? 2 : 1;
    constexpr int NB = (PASSES >= 2) ? 2 : 1;
    constexpr int STG_E = (NA + NB) * PLANE;
    constexpr int AL_O  = PLANE;
    constexpr int B_O   = NA * PLANE;
    constexpr int BL_O  = B_O + PLANE;

    extern __shared__ __align__(16) __half sm[];
    const int tid  = threadIdx.x;
    const int wid  = tid >> 5;
    const int lane = tid & 31;
    const int m0 = blockIdx.y * 128;
    const int n0 = blockIdx.x * 128;
    const int wm = (wid & 3) * 32;
    const int wn = (wid >> 2) * 64;

    ck0 += blockIdx.z * nck;
    C   += blockIdx.z * zCstride;

    float acc[2][8][4];
#pragma unroll
    for (int i = 0; i < 2; i++)
#pragma unroll
        for (int j = 0; j < 8; j++)
#pragma unroll
            for (int v = 0; v < 4; v++) acc[i][j][v] = 0.f;

    auto loadStage = [&](int lck, int stg) {
        const int g = ck0 + lck;
        const __half* ah;
        int kloc, strA;
        if (g < nck1) { ah = A1h; strA = strA1; kloc = g * 32; }
        else          { ah = A2h; strA = strA2; kloc = (g - nck1) * 32; }
        const uint32_t sA  = smem_u32(sm + stg * STG_E);
        const uint32_t sAl = smem_u32(sm + stg * STG_E + AL_O);
        const uint32_t sBh = smem_u32(sm + stg * STG_E + B_O);
        const uint32_t sBl = smem_u32(sm + stg * STG_E + BL_O);
        const int kb = g * 32;
#pragma unroll
        for (int it = 0; it < 2; it++) {
            const int i = tid + it * 256;
            const int r = i >> 2, c = i & 3;
            const uint32_t so = (uint32_t)(r * 40 + c * 8) * 2;
            CP_ASYNC16(sA + so, ah + (size_t)(m0 + r) * strA + kloc + c * 8);
            if (NA == 2) CP_ASYNC16(sAl + so, A1l + (size_t)(m0 + r) * strA + kloc + c * 8);
            CP_ASYNC16(sBh + so, Bh + (size_t)(n0 + r) * strB + kb + c * 8);
            if (NB == 2) CP_ASYNC16(sBl + so, Bl + (size_t)(n0 + r) * strB + kb + c * 8);
        }
        CP_COMMIT();
    };

    loadStage(0, 0);
    if (nck > 1) loadStage(1, 1); else CP_COMMIT();
    CP_WAIT1();
    __syncthreads();

    for (int ck = 0; ck < nck; ck++) {
        const int stg = ck % 3;
        const uint32_t sA  = smem_u32(sm + stg * STG_E);
        const uint32_t sAl = smem_u32(sm + stg * STG_E + AL_O);
        const uint32_t sBh = smem_u32(sm + stg * STG_E + B_O);
        const uint32_t sBl = smem_u32(sm + stg * STG_E + BL_O);

#pragma unroll
        for (int ks = 0; ks < 2; ks++) {
            uint32_t af[2][4], alf[2][4];
#pragma unroll
            for (int i = 0; i < 2; i++) {
                const int row = wm + i * 16 + (lane & 15);
                const int col = ks * 16 + (lane >> 4) * 8;
                ldsm4(af[i], sA + (uint32_t)(row * 40 + col) * 2);
                if (NA == 2) ldsm4(alf[i], sAl + (uint32_t)(row * 40 + col) * 2);
            }
#pragma unroll
            for (int half = 0; half < 2; half++) {
                uint32_t bh[8], bl[8];
#pragma unroll
                for (int jp = 0; jp < 2; jp++) {
                    const int g = lane >> 3;
                    const int row = wn + (half * 4 + jp * 2 + (g >> 1)) * 8 + (lane & 7);
                    const int col = ks * 16 + (g & 1) * 8;
                    ldsm4(&bh[jp * 4], sBh + (uint32_t)(row * 40 + col) * 2);
                    if (NB == 2) ldsm4(&bl[jp * 4], sBl + (uint32_t)(row * 40 + col) * 2);
                }
#pragma unroll
                for (int i = 0; i < 2; i++)
#pragma unroll
                    for (int t = 0; t < 4; t++)
                        mma16816(acc[i][half * 4 + t], af[i], bh[t * 2], bh[t * 2 + 1]);
                if (NB == 2) {
#pragma unroll
                    for (int i = 0; i < 2; i++)
#pragma unroll
                        for (int t = 0; t < 4; t++)
                            mma16816(acc[i][half * 4 + t], af[i], bl[t * 2], bl[t * 2 + 1]);
                }
                if (NA == 2) {
#pragma unroll
                    for (int i = 0; i < 2; i++)
#pragma unroll
                        for (int t = 0; t < 4; t++)
                            mma16816(acc[i][half * 4 + t], alf[i], bh[t * 2], bh[t * 2 + 1]);
                }
            }
        }

        if (ck + 2 < nck) loadStage(ck + 2, (ck + 2) % 3); else CP_COMMIT();
        CP_WAIT1();
        __syncthreads();
    }

#pragma unroll
    for (int i = 0; i < 2; i++) {
        const int r0 = m0 + wm + i * 16 + (lane >> 2);
#pragma unroll
        for (int j = 0; j < 8; j++) {
            const int cc = n0 + wn + j * 8 + (lane & 3) * 2;
            const size_t o0 = (size_t)r0 * Ntot + cc;
            const size_t o1 = (size_t)(r0 + 8) * Ntot + cc;
            float2 v0 = make_float2(acc[i][j][0], acc[i][j][1]);
            float2 v1 = make_float2(acc[i][j][2], acc[i][j][3]);
            if (BIAS) {
                const float2 bv = *(const float2*)(bias + cc);
                v0.x += bv.x; v0.y += bv.y; v1.x += bv.x; v1.y += bv.y;
            }
            if (RELU) {
                v0.x = fmaxf(v0.x, 0.f); v0.y = fmaxf(v0.y, 0.f);
                v1.x = fmaxf(v1.x, 0.f); v1.y = fmaxf(v1.y, 0.f);
            }
            *(float2*)(C + o0) = v0;
            *(float2*)(C + o1) = v1;
        }
    }
}

// adj fp32 -> (adj - 1/64) fp16
__global__ void cvt_adj_k(const float* __restrict__ in, __half* __restrict__ o)
{
    const int i = blockIdx.x * blockDim.x + threadIdx.x;
    float4 v = ((const float4*)in)[i];
    v.x -= ADJC; v.y -= ADJC; v.z -= ADJC; v.w -= ADJC;
    __half2 a = __floats2half2_rn(v.x, v.y);
    __half2 b = __floats2half2_rn(v.z, v.w);
    uint2 p;
    p.x = *(uint32_t*)&a;
    p.y = *(uint32_t*)&b;
    ((uint2*)o)[i] = p;
}

// out[c] = addend[c] + scale * sum_r in[r][c]
__global__ void colsum_k(const float* __restrict__ in, int R, int C,
                         float scale, const float* __restrict__ addend,
                         float* __restrict__ out)
{
    __shared__ float red[256];
    const int c = blockIdx.x;
    float s = 0.f;
    for (int r = threadIdx.x; r < R; r += 256) s += in[(size_t)r * C + c];
    red[threadIdx.x] = s;
    __syncthreads();
    for (int o = 128; o > 0; o >>= 1) {
        if (threadIdx.x < o) red[threadIdx.x] += red[threadIdx.x + o];
        __syncthreads();
    }
    if (threadIdx.x == 0) out[c] = (addend ? addend[c] : 0.f) + scale * red[0];
}

// in[R][C] -> hi fp16 into xT plain + hi/lo into A1 cols [ooff..)
__global__ void split_into_k(const float* __restrict__ in, __half* __restrict__ oh,
                             __half* __restrict__ ol, int C, int ostr, int ooff)
{
    const int idx = blockIdx.x * blockDim.x + threadIdx.x;
    const int r = idx / C, c = idx - r * C;
    __half h, l;
    split2h(in[idx], h, l);
    oh[(size_t)r * ostr + ooff + c] = h;
    ol[(size_t)r * ostr + ooff + c] = l;
}

// combine split-K partials + bias, write hi/lo fp16 into A1 cols [0,128)
__global__ void combine_ax_k(const float* __restrict__ a0, const float* __restrict__ a1,
                             const float* __restrict__ bias,
                             __half* __restrict__ oh, __half* __restrict__ ol)
{
    const int idx = blockIdx.x * blockDim.x + threadIdx.x;
    const int r = idx >> 7, c = idx & 127;
    __half h, l;
    split2h(a0[idx] + a1[idx] + bias[c], h, l);
    oh[(size_t)r * HH + c] = h;
    ol[(size_t)r * HH + c] = l;
}

// transpose + single-plane fp16: out[c][koff+r] = rn16(in[r][c])
__global__ void transconv1_k(const float* __restrict__ in, __half* __restrict__ o,
                             int C, int ostr, int koff)
{
    __shared__ float t[32][33];
    const int c0 = blockIdx.x * 32, r0 = blockIdx.y * 32;
    const int tx = threadIdx.x, ty = threadIdx.y;
#pragma unroll
    for (int j = 0; j < 4; j++)
        t[ty + j * 8][tx] = in[(size_t)(r0 + ty + j * 8) * C + c0 + tx];
    __syncthreads();
#pragma unroll
    for (int j = 0; j < 4; j++)
        o[(size_t)(c0 + ty + j * 8) * ostr + koff + r0 + tx] = __float2half_rn(t[tx][ty + j * 8]);
}

// transpose + hi/lo split
__global__ void transconv2_k(const float* __restrict__ in, __half* __restrict__ oh,
                             __half* __restrict__ ol, int C, int ostr, int koff)
{
    __shared__ float t[32][33];
    const int c0 = blockIdx.x * 32, r0 = blockIdx.y * 32;
    const int tx = threadIdx.x, ty = threadIdx.y;
#pragma unroll
    for (int j = 0; j < 4; j++)
        t[ty + j * 8][tx] = in[(size_t)(r0 + ty + j * 8) * C + c0 + tx];
    __syncthreads();
#pragma unroll
    for (int j = 0; j < 4; j++) {
        __half h, l;
        split2h(t[tx][ty + j * 8], h, l);
        const size_t o = (size_t)(c0 + ty + j * 8) * ostr + koff + r0 + tx;
        oh[o] = h; ol[o] = l;
    }
}

// fp32 SGEMM, 64x64 tile (head GEMMs: small M)
template <bool BIAS, bool RELU>
__global__ void __launch_bounds__(256, 3)
sgemm64_k(const float* __restrict__ A, const float* __restrict__ B,
          float* __restrict__ C, const float* __restrict__ bias, int M, int N, int K)
{
    constexpr int BM = 64, BN = 64, BK = 16, TM = 4, TN = 4;
    __shared__ float As[BK][BM];
    __shared__ float Bs[BK][BN];
    const int tid = threadIdx.x;
    const int bx = blockIdx.x, by = blockIdx.y;
    const int aRow = tid >> 2, aCol = (tid & 3) * 4;
    const float* Ag = A + (size_t)(by * BM + aRow) * K + aCol;
    const int bRow = tid >> 4, bCol = (tid & 15) * 4;
    const float* Bg = B + (size_t)bRow * N + bx * BN + bCol;
    const int tr = (tid >> 4) * TM, tc = (tid & 15) * TN;

    float acc[TM][TN];
#pragma unroll
    for (int i = 0; i < TM; i++)
#pragma unroll
        for (int j = 0; j < TN; j++) acc[i][j] = 0.f;

    for (int k0 = 0; k0 < K; k0 += BK) {
        float4 a0 = *(const float4*)(Ag + k0);
        As[aCol + 0][aRow] = a0.x;  As[aCol + 1][aRow] = a0.y;
        As[aCol + 2][aRow] = a0.z;  As[aCol + 3][aRow] = a0.w;
        *(float4*)&Bs[bRow][bCol] = *(const float4*)(Bg + (size_t)k0 * N);
        __syncthreads();
#pragma unroll
        for (int k = 0; k < BK; k++) {
            float ra[TM], rb[TN];
#pragma unroll
            for (int i = 0; i < TM; i++) ra[i] = As[k][tr + i];
#pragma unroll
            for (int j = 0; j < TN; j++) rb[j] = Bs[k][tc + j];
#pragma unroll
            for (int i = 0; i < TM; i++)
#pragma unroll
                for (int j = 0; j < TN; j++) acc[i][j] = fmaf(ra[i], rb[j], acc[i][j]);
        }
        __syncthreads();
    }
    float4 bv = make_float4(0.f, 0.f, 0.f, 0.f);
    if (BIAS) bv = *(const float4*)(bias + bx * BN + tc);
#pragma unroll
    for (int i = 0; i < TM; i++) {
        const size_t off = (size_t)(by * BM + tr + i) * N + bx * BN + tc;
        float4 v = make_float4(acc[i][0], acc[i][1], acc[i][2], acc[i][3]);
        if (BIAS) { v.x += bv.x; v.y += bv.y; v.z += bv.z; v.w += bv.w; }
        if (RELU) {
            v.x = fmaxf(v.x, 0.f); v.y = fmaxf(v.y, 0.f);
            v.z = fmaxf(v.z, 0.f); v.w = fmaxf(v.w, 0.f);
        }
        *(float4*)(C + off) = v;
    }
}

// BatchNorm partials: 256 blocks x 32 rows
__global__ void bn_partial_k(const float* __restrict__ x, float* __restrict__ psum,
                             float* __restrict__ psq)
{
    const int t = threadIdx.x;
    const float* p = x + (size_t)blockIdx.x * 32 * HH + t;
    float s = 0.f, q = 0.f;
#pragma unroll 4
    for (int r = 0; r < 32; r++) { float v = p[(size_t)r * HH]; s += v; q += v * v; }
    psum[blockIdx.x * HH + t] = s;
    psq [blockIdx.x * HH + t] = q;
}

__global__ void bn_finalize_k(const float* __restrict__ psum, const float* __restrict__ psq,
                              const float* __restrict__ gamma, const float* __restrict__ beta,
                              float* __restrict__ scale, float* __restrict__ shift)
{
    const int t = threadIdx.x;
    float s = 0.f, q = 0.f;
#pragma unroll 8
    for (int b = 0; b < 256; b++) { s += psum[b * HH + t]; q += psq[b * HH + t]; }
    const float invn = 1.f / (float)NN;
    const float m = s * invn;
    const float var = q * invn - m * m;
    const float sc = gamma[t] * rsqrtf(var + EPSB);
    scale[t] = sc;
    shift[t] = beta[t] - m * sc;
}

template <bool CVT>
__global__ void bn_apply_k(float* __restrict__ x, const float* __restrict__ scale,
                           const float* __restrict__ shift,
                           __half* __restrict__ oh, __half* __restrict__ ol)
{
    const int i = blockIdx.x * blockDim.x + threadIdx.x;
    const int c = (i * 4) & (HH - 1);
    float4 v = ((float4*)x)[i];
    v.x = fmaf(v.x, scale[c + 0], shift[c + 0]);
    v.y = fmaf(v.y, scale[c + 1], shift[c + 1]);
    v.z = fmaf(v.z, scale[c + 2], shift[c + 2]);
    v.w = fmaf(v.w, scale[c + 3], shift[c + 3]);
    ((float4*)x)[i] = v;
    if (CVT) {
        __half h0, h1, h2, h3, l0, l1, l2, l3;
        split2h(v.x, h0, l0); split2h(v.y, h1, l1);
        split2h(v.z, h2, l2); split2h(v.w, h3, l3);
        __half2 ph0 = __halves2half2(h0, h1), ph1 = __halves2half2(h2, h3);
        __half2 pl0 = __halves2half2(l0, l1), pl1 = __halves2half2(l2, l3);
        uint2 hp, lp;
        hp.x = *(uint32_t*)&ph0; hp.y = *(uint32_t*)&ph1;
        lp.x = *(uint32_t*)&pl0; lp.y = *(uint32_t*)&pl1;
        ((uint2*)oh)[i] = hp;
        ((uint2*)ol)[i] = lp;
    }
}

__global__ void pool_k(const float* __restrict__ h1, const float* __restrict__ h2,
                       float* __restrict__ pooled)
{
    const int g = blockIdx.x, t = threadIdx.x;
    const size_t r0 = (size_t)g * NPG;
    float mx1 = -1e30f, mx2 = -1e30f, s1 = 0.f, s2 = 0.f;
#pragma unroll 4
    for (int r = 0; r < NPG; r++) {
        float v1 = h1[(r0 + r) * HH + t];
        float v2 = h2[(r0 + r) * HH + t];
        mx1 = fmaxf(mx1, v1); s1 += v1;
        mx2 = fmaxf(mx2, v2); s2 += v2;
    }
    float* out = pooled + (size_t)g * 1024;
    out[t]       = mx1;
    out[256 + t] = mx2;
    out[512 + t] = s1 * (1.f / NPG);
    out[768 + t] = s2 * (1.f / NPG);
}

// small BN: one block per 32 columns, block (32,8)
__global__ void bn_small_k(const float* __restrict__ in, const float* __restrict__ gamma,
                           const float* __restrict__ beta, float* __restrict__ out, int C)
{
    __shared__ float ssum[8][32], ssq[8][32], ssc[32], ssh[32];
    const int tx = threadIdx.x, ty = threadIdx.y;
    const int c = blockIdx.x * 32 + tx;
    float s = 0.f, q = 0.f;
    for (int r = ty; r < GG; r += 8) {
        const float v = in[(size_t)r * C + c];
        s += v; q += v * v;
    }
    ssum[ty][tx] = s; ssq[ty][tx] = q;
    __syncthreads();
    if (ty == 0) {
        float S = 0.f, Q = 0.f;
#pragma unroll
        for (int k = 0; k < 8; k++) { S += ssum[k][tx]; Q += ssq[k][tx]; }
        const float m = S * (1.f / GG);
        const float var = Q * (1.f / GG) - m * m;
        const float sc = gamma[c] * rsqrtf(var + EPSB);
        ssc[tx] = sc;
        ssh[tx] = beta[c] - m * sc;
    }
    __syncthreads();
    const float sc = ssc[tx], sh = ssh[tx];
    for (int r = ty; r < GG; r += 8)
        out[(size_t)r * C + c] = fmaf(in[(size_t)r * C + c], sc, sh);
}

__global__ void dense_small_k(const float* __restrict__ A, const float* __restrict__ W,
                              const float* __restrict__ b, float* __restrict__ C,
                              int M, int N, int K)
{
    const int idx = blockIdx.x * blockDim.x + threadIdx.x;
    if (idx >= M * N) return;
    const int m = idx / N, n = idx - m * N;
    float acc = b[n];
    const float* a = A + (size_t)m * K;
    for (int k = 0; k < K; k++) acc = fmaf(a[k], W[(size_t)k * N + n], acc);
    C[idx] = acc;
}

extern "C" void kernel_launch(void* const* d_in, const int* in_sizes, int n_in,
                              void* d_out, int out_size)
{
    const float* x    = (const float*)d_in[0];
    const float* adj  = (const float*)d_in[1];
    const float* W1   = (const float*)d_in[3];
    const float* Ws1  = (const float*)d_in[4];
    const float* b1   = (const float*)d_in[5];
    const float* g1   = (const float*)d_in[6];
    const float* be1  = (const float*)d_in[7];
    const float* W2   = (const float*)d_in[8];
    const float* Ws2  = (const float*)d_in[9];
    const float* b2   = (const float*)d_in[10];
    const float* g2   = (const float*)d_in[11];
    const float* be2  = (const float*)d_in[12];
    const float* bn0g = (const float*)d_in[13];
    const float* bn0b = (const float*)d_in[14];
    const float* L1W  = (const float*)d_in[15];
    const float* L1b  = (const float*)d_in[16];
    const float* bn1g = (const float*)d_in[17];
    const float* bn1b = (const float*)d_in[18];
    const float* L2W  = (const float*)d_in[19];
    const float* L2b  = (const float*)d_in[20];
    const float* bn2g = (const float*)d_in[21];
    const float* bn2b = (const float*)d_in[22];
    const float* L3W  = (const float*)d_in[23];
    const float* L3b  = (const float*)d_in[24];
    const float* catW = (const float*)d_in[25];
    const float* catb = (const float*)d_in[26];

    float* out = (float*)d_out;
    float* out_main  = out;
    float* out_class = out + 256 * 128;
    float* out_fp    = out + 256 * 128 + 256 * 12;

    __half *adjc, *xTh, *A1h, *A1l, *B1h, *B1l, *h1h, *h1l, *W2Th, *W2Tl, *B2h, *B2l;
    float *axp, *biasax, *bias2, *pre1, *g2in, *pre2, *pool, *bnp, *l1, *bn1, *l2;
    float *psum, *psq, *scale, *shift;
    cudaGetSymbolAddress((void**)&adjc,  g_adjc);
    cudaGetSymbolAddress((void**)&xTh,   g_xT_h);
    cudaGetSymbolAddress((void**)&axp,   g_axp);
    cudaGetSymbolAddress((void**)&biasax,g_biasax);
    cudaGetSymbolAddress((void**)&bias2, g_bias2);
    cudaGetSymbolAddress((void**)&A1h,   g_A1_h);
    cudaGetSymbolAddress((void**)&A1l,   g_A1_l);
    cudaGetSymbolAddress((void**)&B1h,   g_B1_h);
    cudaGetSymbolAddress((void**)&B1l,   g_B1_l);
    cudaGetSymbolAddress((void**)&pre1,  g_pre1);
    cudaGetSymbolAddress((void**)&h1h,   g_h1_h);
    cudaGetSymbolAddress((void**)&h1l,   g_h1_l);
    cudaGetSymbolAddress((void**)&W2Th,  g_W2T_h);
    cudaGetSymbolAddress((void**)&W2Tl,  g_W2T_l);
    cudaGetSymbolAddress((void**)&g2in,  g_g2in);
    cudaGetSymbolAddress((void**)&B2h,   g_B2_h);
    cudaGetSymbolAddress((void**)&B2l,   g_B2_l);
    cudaGetSymbolAddress((void**)&pre2,  g_pre2);
    cudaGetSymbolAddress((void**)&pool,  g_pool);
    cudaGetSymbolAddress((void**)&bnp,   g_bnp);
    cudaGetSymbolAddress((void**)&l1,    g_l1);
    cudaGetSymbolAddress((void**)&bn1,   g_bn1);
    cudaGetSymbolAddress((void**)&l2,    g_l2);
    cudaGetSymbolAddress((void**)&psum,  g_psum);
    cudaGetSymbolAddress((void**)&psq,   g_psq);
    cudaGetSymbolAddress((void**)&scale, g_scale);
    cudaGetSymbolAddress((void**)&shift, g_shift);

    static bool attr_done = false;
    if (!attr_done) {
        cudaFuncSetAttribute(mma2_k<1, false, false>, cudaFuncAttributeMaxDynamicSharedMemorySize, 61440);
        cudaFuncSetAttribute(mma2_k<2, true, true>,   cudaFuncAttributeMaxDynamicSharedMemorySize, 92160);
        cudaFuncSetAttribute(mma2_k<3, false, false>, cudaFuncAttributeMaxDynamicSharedMemorySize, 122880);
        cudaFuncSetAttribute(mma2_k<3, true, true>,   cudaFuncAttributeMaxDynamicSharedMemorySize, 122880);
        attr_done = true;
    }

    // prep
    cvt_adj_k<<<NN * NN / 4 / 256, 256>>>(adj, adjc);
    transconv1_k<<<dim3(FF / 32, NN / 32), dim3(32, 8)>>>(x, xTh, FF, NN, 0);
    split_into_k<<<NN * FF / 256, 256>>>(x, A1h, A1l, FF, HH, FF);
    transconv2_k<<<dim3(HH / 32, FF / 32), dim3(32, 8)>>>(W1,  B1h, B1l, HH, HH, 0);
    transconv2_k<<<dim3(HH / 32, FF / 32), dim3(32, 8)>>>(Ws1, B1h, B1l, HH, HH, FF);
    transconv2_k<<<dim3(HH / 32, HH / 32), dim3(32, 8)>>>(W2,  W2Th, W2Tl, HH, HH, 0);
    transconv2_k<<<dim3(HH / 32, HH / 32), dim3(32, 8)>>>(Ws2, B2h, B2l, HH, K2TOT, NN);
    colsum_k<<<FF, 256>>>(x, NN, FF, ADJC, (const float*)0, biasax);

    // layer 1: ax = adj_c @ x (single-pass fp16, split-K2 via z) + rank-1 correction
    mma2_k<1, false, false><<<dim3(1, NN / 128, 2), 256, 61440>>>(
        adjc, (const __half*)0, NN, BIGK, (const __half*)0, 0, xTh, (const __half*)0, NN,
        axp, (const float*)0, FF, 128, 0, (size_t)NN * FF);
    combine_ax_k<<<NN * FF / 256, 256>>>(axp, axp + (size_t)NN * FF, biasax, A1h, A1l);
    // pre1 = relu([ax|x] @ [W1;Ws1]^T + b1)  (3-pass)
    mma2_k<3, true, true><<<dim3(2, NN / 128), 256, 122880>>>(
        A1h, A1l, HH, BIGK, (const __half*)0, 0, B1h, B1l, HH,
        pre1, b1, HH, 8, 0, 0);
    bn_partial_k<<<256, 256>>>(pre1, psum, psq);
    bn_finalize_k<<<1, 256>>>(psum, psq, g1, be1, scale, shift);
    bn_apply_k<true><<<(NN * HH / 4) / 256, 256>>>(pre1, scale, shift, h1h, h1l);

    // layer 2: g2in = h1 @ W2 (3-pass)
    mma2_k<3, false, false><<<dim3(2, NN / 128), 256, 122880>>>(
        h1h, h1l, HH, BIGK, (const __half*)0, 0, W2Th, W2Tl, HH,
        g2in, (const float*)0, HH, 8, 0, 0);
    transconv2_k<<<dim3(HH / 32, NN / 32), dim3(32, 8)>>>(g2in, B2h, B2l, HH, K2TOT, 0);
    colsum_k<<<HH, 256>>>(g2in, NN, HH, ADJC, b2, bias2);
    // pre2 = relu([adj_c|h1] @ [g2in;Ws2]^T + bias2)  (2-pass split-B)
    mma2_k<2, true, true><<<dim3(2, NN / 128), 256, 92160>>>(
        adjc, (const __half*)0, NN, NN / 32, h1h, HH, B2h, B2l, K2TOT,
        pre2, bias2, HH, K2TOT / 32, 0, 0);
    bn_partial_k<<<256, 256>>>(pre2, psum, psq);
    bn_finalize_k<<<1, 256>>>(psum, psq, g2, be2, scale, shift);
    bn_apply_k<false><<<(NN * HH / 4) / 256, 256>>>(pre2, scale, shift, (__half*)0, (__half*)0);

    // pooling
    pool_k<<<GG, 256>>>(pre1, pre2, pool);

    // MLP head
    bn_small_k<<<1024 / 32, dim3(32, 8)>>>(pool, bn0g, bn0b, bnp, 1024);
    sgemm64_k<true, true><<<dim3(512 / 64, GG / 64), 256>>>(bnp, L1W, l1, L1b, GG, 512, 1024);
    bn_small_k<<<512 / 32, dim3(32, 8)>>>(l1, bn1g, bn1b, bn1, 512);
    sgemm64_k<true, true><<<dim3(256 / 64, GG / 64), 256>>>(bn1, L2W, l2, L2b, GG, 256, 512);
    bn_small_k<<<256 / 32, dim3(32, 8)>>>(l2, bn2g, bn2b, out_fp, 256);
    dense_small_k<<<(256 * 128 + 255) / 256, 256>>>(out_fp, L3W, L3b, out_main, 256, 128, 256);
    dense_small_k<<<(256 * 12 + 255) / 256, 256>>>(out_fp, catW, catb, out_class, 256, 12, 256);

    (void)in_sizes; (void)n_in; (void)out_size;
}

// round 11
// speedup vs baseline: 3.5517x; 1.1114x over previous
#include <cuda_runtime.h>
#include <cuda_fp16.h>
#include <math.h>
#include <stdint.h>

#define NN   8192
#define FF   128
#define HH   256
#define GG   256
#define NPG  32
#define EPSB 1e-5f
#define K2TOT (NN + HH)
#define BIGK (1 << 30)
#define ADJC 0.015625f

__device__ __half g_adjc [NN * NN];
__device__ __half g_xT_h [FF * NN];
__device__ float  g_axp  [2 * NN * FF];
__device__ float  g_biasax[FF];
__device__ float  g_bias2 [HH];
__device__ __half g_A1_h [NN * HH];
__device__ __half g_A1_l [NN * HH];
__device__ __half g_B1_h [HH * HH];
__device__ __half g_B1_l [HH * HH];
__device__ float  g_pre1 [NN * HH];
__device__ __half g_h1_h [NN * HH];
__device__ __half g_h1_l [NN * HH];
__device__ __half g_W2T_h[HH * HH];
__device__ __half g_W2T_l[HH * HH];
__device__ float  g_g2in [NN * HH];
__device__ __half g_B2_h [HH * K2TOT];
__device__ float  g_pre2 [NN * HH];
__device__ float  g_pool [GG * 1024];
__device__ float  g_bnp  [GG * 1024];
__device__ float  g_l1   [GG * 512];
__device__ float  g_bn1  [GG * 512];
__device__ float  g_l2   [GG * 256];
__device__ float  g_psum [256 * HH];
__device__ float  g_psq  [256 * HH];
__device__ float  g_scale[HH];
__device__ float  g_shift[HH];

__device__ __forceinline__ uint32_t smem_u32(const void* p) {
    uint32_t a;
    asm("{ .reg .u64 t; cvta.to.shared.u64 t, %1; cvt.u32.u64 %0, t; }" : "=r"(a) : "l"(p));
    return a;
}
__device__ __forceinline__ void ldsm4(uint32_t* r, uint32_t addr) {
    asm volatile("ldmatrix.sync.aligned.m8n8.x4.shared.b16 {%0,%1,%2,%3}, [%4];"
        : "=r"(r[0]), "=r"(r[1]), "=r"(r[2]), "=r"(r[3]) : "r"(addr));
}
__device__ __forceinline__ void mma16816(float* d, const uint32_t* a, uint32_t b0, uint32_t b1) {
    asm volatile("mma.sync.aligned.m16n8k16.row.col.f32.f16.f16.f32 "
        "{%0,%1,%2,%3}, {%4,%5,%6,%7}, {%8,%9}, {%0,%1,%2,%3};"
        : "+f"(d[0]), "+f"(d[1]), "+f"(d[2]), "+f"(d[3])
        : "r"(a[0]), "r"(a[1]), "r"(a[2]), "r"(a[3]), "r"(b0), "r"(b1));
}
#define CP_ASYNC16(dst, src) asm volatile("cp.async.cg.shared.global [%0], [%1], 16;" :: "r"(dst), "l"(src))
#define CP_COMMIT()          asm volatile("cp.async.commit_group;" ::: "memory")
#define CP_WAIT1()           asm volatile("cp.async.wait_group 1;" ::: "memory")

__device__ __forceinline__ void split2h(float v, __half& h, __half& l) {
    h = __float2half_rn(v);
    l = __float2half_rn(v - __half2float(h));
}

// fp16 tensor-core GEMM, 3-stage cp.async pipeline.
// PASSES==1: C = A @ B^T               (both single plane)
// PASSES==2: C = A @ (Bh + Bl)^T       (A single, split-B)
// PASSES==3: C = (Ah+Al) @ (Bh+Bl)^T   (lo*lo dropped)
// A may concatenate two single-plane sources along K (first nck1 chunks A1, rest A2).
// blockIdx.z: split-K partials (chunk window shifts by z*nck, C shifts by z*zCstride).
#define PLANE 5120

template <int PASSES, bool BIAS, bool RELU>
__global__ void __launch_bounds__(256, 2)
mma2_k(const __half* __restrict__ A1h, const __half* __restrict__ A1l, int strA1, int nck1,
       const __half* __restrict__ A2h, int strA2,
       const __half* __restrict__ Bh,  const __half* __restrict__ Bl,  int strB,
       float* __restrict__ C, const float* __restrict__ bias, int Ntot,
       int nck, int ck0, size_t zCstride)
{
    constexpr int NA = (PASSES == 3) ? 2 : 1;
    constexpr int NB = (PASSES >= 2) ? 2 : 1;
    constexpr int STG_E = (NA + NB) * PLANE;
    constexpr int AL_O  = PLANE;
    constexpr int B_O   = NA * PLANE;
    constexpr int BL_O  = B_O + PLANE;

    extern __shared__ __align__(16) __half sm[];
    const int tid  = threadIdx.x;
    const int wid  = tid >> 5;
    const int lane = tid & 31;
    const int m0 = blockIdx.y * 128;
    const int n0 = blockIdx.x * 128;
    const int wm = (wid & 3) * 32;
    const int wn = (wid >> 2) * 64;

    ck0 += blockIdx.z * nck;
    C   += blockIdx.z * zCstride;

    float acc[2][8][4];
#pragma unroll
    for (int i = 0; i < 2; i++)
#pragma unroll
        for (int j = 0; j < 8; j++)
#pragma unroll
            for (int v = 0; v < 4; v++) acc[i][j][v] = 0.f;

    auto loadStage = [&](int lck, int stg) {
        const int g = ck0 + lck;
        const __half* ah;
        int kloc, strA;
        if (g < nck1) { ah = A1h; strA = strA1; kloc = g * 32; }
        else          { ah = A2h; strA = strA2; kloc = (g - nck1) * 32; }
        const uint32_t sA  = smem_u32(sm + stg * STG_E);
        const uint32_t sAl = smem_u32(sm + stg * STG_E + AL_O);
        const uint32_t sBh = smem_u32(sm + stg * STG_E + B_O);
        const uint32_t sBl = smem_u32(sm + stg * STG_E + BL_O);
        const int kb = g * 32;
#pragma unroll
        for (int it = 0; it < 2; it++) {
            const int i = tid + it * 256;
            const int r = i >> 2, c = i & 3;
            const uint32_t so = (uint32_t)(r * 40 + c * 8) * 2;
            CP_ASYNC16(sA + so, ah + (size_t)(m0 + r) * strA + kloc + c * 8);
            if (NA == 2) CP_ASYNC16(sAl + so, A1l + (size_t)(m0 + r) * strA + kloc + c * 8);
            CP_ASYNC16(sBh + so, Bh + (size_t)(n0 + r) * strB + kb + c * 8);
            if (NB == 2) CP_ASYNC16(sBl + so, Bl + (size_t)(n0 + r) * strB + kb + c * 8);
        }
        CP_COMMIT();
    };

    loadStage(0, 0);
    if (nck > 1) loadStage(1, 1); else CP_COMMIT();
    CP_WAIT1();
    __syncthreads();

    for (int ck = 0; ck < nck; ck++) {
        const int stg = ck % 3;
        const uint32_t sA  = smem_u32(sm + stg * STG_E);
        const uint32_t sAl = smem_u32(sm + stg * STG_E + AL_O);
        const uint32_t sBh = smem_u32(sm + stg * STG_E + B_O);
        const uint32_t sBl = smem_u32(sm + stg * STG_E + BL_O);

#pragma unroll
        for (int ks = 0; ks < 2; ks++) {
            uint32_t af[2][4], alf[2][4];
#pragma unroll
            for (int i = 0; i < 2; i++) {
                const int row = wm + i * 16 + (lane & 15);
                const int col = ks * 16 + (lane >> 4) * 8;
                ldsm4(af[i], sA + (uint32_t)(row * 40 + col) * 2);
                if (NA == 2) ldsm4(alf[i], sAl + (uint32_t)(row * 40 + col) * 2);
            }
#pragma unroll
            for (int half = 0; half < 2; half++) {
                uint32_t bh[8], bl[8];
#pragma unroll
                for (int jp = 0; jp < 2; jp++) {
                    const int g = lane >> 3;
                    const int row = wn + (half * 4 + jp * 2 + (g >> 1)) * 8 + (lane & 7);
                    const int col = ks * 16 + (g & 1) * 8;
                    ldsm4(&bh[jp * 4], sBh + (uint32_t)(row * 40 + col) * 2);
                    if (NB == 2) ldsm4(&bl[jp * 4], sBl + (uint32_t)(row * 40 + col) * 2);
                }
#pragma unroll
                for (int i = 0; i < 2; i++)
#pragma unroll
                    for (int t = 0; t < 4; t++)
                        mma16816(acc[i][half * 4 + t], af[i], bh[t * 2], bh[t * 2 + 1]);
                if (NB == 2) {
#pragma unroll
                    for (int i = 0; i < 2; i++)
#pragma unroll
                        for (int t = 0; t < 4; t++)
                            mma16816(acc[i][half * 4 + t], af[i], bl[t * 2], bl[t * 2 + 1]);
                }
                if (NA == 2) {
#pragma unroll
                    for (int i = 0; i < 2; i++)
#pragma unroll
                        for (int t = 0; t < 4; t++)
                            mma16816(acc[i][half * 4 + t], alf[i], bh[t * 2], bh[t * 2 + 1]);
                }
            }
        }

        if (ck + 2 < nck) loadStage(ck + 2, (ck + 2) % 3); else CP_COMMIT();
        CP_WAIT1();
        __syncthreads();
    }

#pragma unroll
    for (int i = 0; i < 2; i++) {
        const int r0 = m0 + wm + i * 16 + (lane >> 2);
#pragma unroll
        for (int j = 0; j < 8; j++) {
            const int cc = n0 + wn + j * 8 + (lane & 3) * 2;
            const size_t o0 = (size_t)r0 * Ntot + cc;
            const size_t o1 = (size_t)(r0 + 8) * Ntot + cc;
            float2 v0 = make_float2(acc[i][j][0], acc[i][j][1]);
            float2 v1 = make_float2(acc[i][j][2], acc[i][j][3]);
            if (BIAS) {
                const float2 bv = *(const float2*)(bias + cc);
                v0.x += bv.x; v0.y += bv.y; v1.x += bv.x; v1.y += bv.y;
            }
            if (RELU) {
                v0.x = fmaxf(v0.x, 0.f); v0.y = fmaxf(v0.y, 0.f);
                v1.x = fmaxf(v1.x, 0.f); v1.y = fmaxf(v1.y, 0.f);
            }
            *(float2*)(C + o0) = v0;
            *(float2*)(C + o1) = v1;
        }
    }
}

// adj fp32 -> (adj - 1/64) fp16
__global__ void cvt_adj_k(const float* __restrict__ in, __half* __restrict__ o)
{
    const int i = blockIdx.x * blockDim.x + threadIdx.x;
    float4 v = ((const float4*)in)[i];
    v.x -= ADJC; v.y -= ADJC; v.z -= ADJC; v.w -= ADJC;
    __half2 a = __floats2half2_rn(v.x, v.y);
    __half2 b = __floats2half2_rn(v.z, v.w);
    uint2 p;
    p.x = *(uint32_t*)&a;
    p.y = *(uint32_t*)&b;
    ((uint2*)o)[i] = p;
}

// out[c] = addend[c] + scale * sum_r in[r][c]
__global__ void colsum_k(const float* __restrict__ in, int R, int C,
                         float scale, const float* __restrict__ addend,
                         float* __restrict__ out)
{
    __shared__ float red[256];
    const int c = blockIdx.x;
    float s = 0.f;
    for (int r = threadIdx.x; r < R; r += 256) s += in[(size_t)r * C + c];
    red[threadIdx.x] = s;
    __syncthreads();
    for (int o = 128; o > 0; o >>= 1) {
        if (threadIdx.x < o) red[threadIdx.x] += red[threadIdx.x + o];
        __syncthreads();
    }
    if (threadIdx.x == 0) out[c] = (addend ? addend[c] : 0.f) + scale * red[0];
}

// in[R][C] -> hi/lo fp16 into out cols [ooff..)
__global__ void split_into_k(const float* __restrict__ in, __half* __restrict__ oh,
                             __half* __restrict__ ol, int C, int ostr, int ooff)
{
    const int idx = blockIdx.x * blockDim.x + threadIdx.x;
    const int r = idx / C, c = idx - r * C;
    __half h, l;
    split2h(in[idx], h, l);
    oh[(size_t)r * ostr + ooff + c] = h;
    ol[(size_t)r * ostr + ooff + c] = l;
}

// combine split-K partials + bias, write hi/lo fp16 into A1 cols [0,128)
__global__ void combine_ax_k(const float* __restrict__ a0, const float* __restrict__ a1,
                             const float* __restrict__ bias,
                             __half* __restrict__ oh, __half* __restrict__ ol)
{
    const int idx = blockIdx.x * blockDim.x + threadIdx.x;
    const int r = idx >> 7, c = idx & 127;
    __half h, l;
    split2h(a0[idx] + a1[idx] + bias[c], h, l);
    oh[(size_t)r * HH + c] = h;
    ol[(size_t)r * HH + c] = l;
}

// transpose + single-plane fp16: out[c][koff+r] = rn16(in[r][c])
__global__ void transconv1_k(const float* __restrict__ in, __half* __restrict__ o,
                             int C, int ostr, int koff)
{
    __shared__ float t[32][33];
    const int c0 = blockIdx.x * 32, r0 = blockIdx.y * 32;
    const int tx = threadIdx.x, ty = threadIdx.y;
#pragma unroll
    for (int j = 0; j < 4; j++)
        t[ty + j * 8][tx] = in[(size_t)(r0 + ty + j * 8) * C + c0 + tx];
    __syncthreads();
#pragma unroll
    for (int j = 0; j < 4; j++)
        o[(size_t)(c0 + ty + j * 8) * ostr + koff + r0 + tx] = __float2half_rn(t[tx][ty + j * 8]);
}

// transpose + hi/lo split
__global__ void transconv2_k(const float* __restrict__ in, __half* __restrict__ oh,
                             __half* __restrict__ ol, int C, int ostr, int koff)
{
    __shared__ float t[32][33];
    const int c0 = blockIdx.x * 32, r0 = blockIdx.y * 32;
    const int tx = threadIdx.x, ty = threadIdx.y;
#pragma unroll
    for (int j = 0; j < 4; j++)
        t[ty + j * 8][tx] = in[(size_t)(r0 + ty + j * 8) * C + c0 + tx];
    __syncthreads();
#pragma unroll
    for (int j = 0; j < 4; j++) {
        __half h, l;
        split2h(t[tx][ty + j * 8], h, l);
        const size_t o = (size_t)(c0 + ty + j * 8) * ostr + koff + r0 + tx;
        oh[o] = h; ol[o] = l;
    }
}

// fp32 SGEMM, 64x64 tile (head GEMMs)
template <bool BIAS, bool RELU>
__global__ void __launch_bounds__(256, 3)
sgemm64_k(const float* __restrict__ A, const float* __restrict__ B,
          float* __restrict__ C, const float* __restrict__ bias, int M, int N, int K)
{
    constexpr int BM = 64, BN = 64, BK = 16, TM = 4, TN = 4;
    __shared__ float As[BK][BM];
    __shared__ float Bs[BK][BN];
    const int tid = threadIdx.x;
    const int bx = blockIdx.x, by = blockIdx.y;
    const int aRow = tid >> 2, aCol = (tid & 3) * 4;
    const float* Ag = A + (size_t)(by * BM + aRow) * K + aCol;
    const int bRow = tid >> 4, bCol = (tid & 15) * 4;
    const float* Bg = B + (size_t)bRow * N + bx * BN + bCol;
    const int tr = (tid >> 4) * TM, tc = (tid & 15) * TN;

    float acc[TM][TN];
#pragma unroll
    for (int i = 0; i < TM; i++)
#pragma unroll
        for (int j = 0; j < TN; j++) acc[i][j] = 0.f;

    for (int k0 = 0; k0 < K; k0 += BK) {
        float4 a0 = *(const float4*)(Ag + k0);
        As[aCol + 0][aRow] = a0.x;  As[aCol + 1][aRow] = a0.y;
        As[aCol + 2][aRow] = a0.z;  As[aCol + 3][aRow] = a0.w;
        *(float4*)&Bs[bRow][bCol] = *(const float4*)(Bg + (size_t)k0 * N);
        __syncthreads();
#pragma unroll
        for (int k = 0; k < BK; k++) {
            float ra[TM], rb[TN];
#pragma unroll
            for (int i = 0; i < TM; i++) ra[i] = As[k][tr + i];
#pragma unroll
            for (int j = 0; j < TN; j++) rb[j] = Bs[k][tc + j];
#pragma unroll
            for (int i = 0; i < TM; i++)
#pragma unroll
                for (int j = 0; j < TN; j++) acc[i][j] = fmaf(ra[i], rb[j], acc[i][j]);
        }
        __syncthreads();
    }
    float4 bv = make_float4(0.f, 0.f, 0.f, 0.f);
    if (BIAS) bv = *(const float4*)(bias + bx * BN + tc);
#pragma unroll
    for (int i = 0; i < TM; i++) {
        const size_t off = (size_t)(by * BM + tr + i) * N + bx * BN + tc;
        float4 v = make_float4(acc[i][0], acc[i][1], acc[i][2], acc[i][3]);
        if (BIAS) { v.x += bv.x; v.y += bv.y; v.z += bv.z; v.w += bv.w; }
        if (RELU) {
            v.x = fmaxf(v.x, 0.f); v.y = fmaxf(v.y, 0.f);
            v.z = fmaxf(v.z, 0.f); v.w = fmaxf(v.w, 0.f);
        }
        *(float4*)(C + off) = v;
    }
}

// BatchNorm partials: 256 blocks x 32 rows
__global__ void bn_partial_k(const float* __restrict__ x, float* __restrict__ psum,
                             float* __restrict__ psq)
{
    const int t = threadIdx.x;
    const float* p = x + (size_t)blockIdx.x * 32 * HH + t;
    float s = 0.f, q = 0.f;
#pragma unroll 4
    for (int r = 0; r < 32; r++) { float v = p[(size_t)r * HH]; s += v; q += v * v; }
    psum[blockIdx.x * HH + t] = s;
    psq [blockIdx.x * HH + t] = q;
}

__global__ void bn_finalize_k(const float* __restrict__ psum, const float* __restrict__ psq,
                              const float* __restrict__ gamma, const float* __restrict__ beta,
                              float* __restrict__ scale, float* __restrict__ shift)
{
    const int t = threadIdx.x;
    float s = 0.f, q = 0.f;
#pragma unroll 8
    for (int b = 0; b < 256; b++) { s += psum[b * HH + t]; q += psq[b * HH + t]; }
    const float invn = 1.f / (float)NN;
    const float m = s * invn;
    const float var = q * invn - m * m;
    const float sc = gamma[t] * rsqrtf(var + EPSB);
    scale[t] = sc;
    shift[t] = beta[t] - m * sc;
}

template <bool CVT>
__global__ void bn_apply_k(float* __restrict__ x, const float* __restrict__ scale,
                           const float* __restrict__ shift,
                           __half* __restrict__ oh, __half* __restrict__ ol)
{
    const int i = blockIdx.x * blockDim.x + threadIdx.x;
    const int c = (i * 4) & (HH - 1);
    float4 v = ((float4*)x)[i];
    v.x = fmaf(v.x, scale[c + 0], shift[c + 0]);
    v.y = fmaf(v.y, scale[c + 1], shift[c + 1]);
    v.z = fmaf(v.z, scale[c + 2], shift[c + 2]);
    v.w = fmaf(v.w, scale[c + 3], shift[c + 3]);
    ((float4*)x)[i] = v;
    if (CVT) {
        __half h0, h1, h2, h3, l0, l1, l2, l3;
        split2h(v.x, h0, l0); split2h(v.y, h1, l1);
        split2h(v.z, h2, l2); split2h(v.w, h3, l3);
        __half2 ph0 = __halves2half2(h0, h1), ph1 = __halves2half2(h2, h3);
        __half2 pl0 = __halves2half2(l0, l1), pl1 = __halves2half2(l2, l3);
        uint2 hp, lp;
        hp.x = *(uint32_t*)&ph0; hp.y = *(uint32_t*)&ph1;
        lp.x = *(uint32_t*)&pl0; lp.y = *(uint32_t*)&pl1;
        ((uint2*)oh)[i] = hp;
        ((uint2*)ol)[i] = lp;
    }
}

__global__ void pool_k(const float* __restrict__ h1, const float* __restrict__ h2,
                       float* __restrict__ pooled)
{
    const int g = blockIdx.x, t = threadIdx.x;
    const size_t r0 = (size_t)g * NPG;
    float mx1 = -1e30f, mx2 = -1e30f, s1 = 0.f, s2 = 0.f;
#pragma unroll 4
    for (int r = 0; r < NPG; r++) {
        float v1 = h1[(r0 + r) * HH + t];
        float v2 = h2[(r0 + r) * HH + t];
        mx1 = fmaxf(mx1, v1); s1 += v1;
        mx2 = fmaxf(mx2, v2); s2 += v2;
    }
    float* out = pooled + (size_t)g * 1024;
    out[t]       = mx1;
    out[256 + t] = mx2;
    out[512 + t] = s1 * (1.f / NPG);
    out[768 + t] = s2 * (1.f / NPG);
}

// small BN: one block per 32 columns, block (32,8)
__global__ void bn_small_k(const float* __restrict__ in, const float* __restrict__ gamma,
                           const float* __restrict__ beta, float* __restrict__ out, int C)
{
    __shared__ float ssum[8][32], ssq[8][32], ssc[32], ssh[32];
    const int tx = threadIdx.x, ty = threadIdx.y;
    const int c = blockIdx.x * 32 + tx;
    float s = 0.f, q = 0.f;
    for (int r = ty; r < GG; r += 8) {
        const float v = in[(size_t)r * C + c];
        s += v; q += v * v;
    }
    ssum[ty][tx] = s; ssq[ty][tx] = q;
    __syncthreads();
    if (ty == 0) {
        float S = 0.f, Q = 0.f;
#pragma unroll
        for (int k = 0; k < 8; k++) { S += ssum[k][tx]; Q += ssq[k][tx]; }
        const float m = S * (1.f / GG);
        const float var = Q * (1.f / GG) - m * m;
        const float sc = gamma[c] * rsqrtf(var + EPSB);
        ssc[tx] = sc;
        ssh[tx] = beta[c] - m * sc;
    }
    __syncthreads();
    const float sc = ssc[tx], sh = ssh[tx];
    for (int r = ty; r < GG; r += 8)
        out[(size_t)r * C + c] = fmaf(in[(size_t)r * C + c], sc, sh);
}

__global__ void dense_small_k(const float* __restrict__ A, const float* __restrict__ W,
                              const float* __restrict__ b, float* __restrict__ C,
                              int M, int N, int K)
{
    const int idx = blockIdx.x * blockDim.x + threadIdx.x;
    if (idx >= M * N) return;
    const int m = idx / N, n = idx - m * N;
    float acc = b[n];
    const float* a = A + (size_t)m * K;
    for (int k = 0; k < K; k++) acc = fmaf(a[k], W[(size_t)k * N + n], acc);
    C[idx] = acc;
}

extern "C" void kernel_launch(void* const* d_in, const int* in_sizes, int n_in,
                              void* d_out, int out_size)
{
    const float* x    = (const float*)d_in[0];
    const float* adj  = (const float*)d_in[1];
    const float* W1   = (const float*)d_in[3];
    const float* Ws1  = (const float*)d_in[4];
    const float* b1   = (const float*)d_in[5];
    const float* g1   = (const float*)d_in[6];
    const float* be1  = (const float*)d_in[7];
    const float* W2   = (const float*)d_in[8];
    const float* Ws2  = (const float*)d_in[9];
    const float* b2   = (const float*)d_in[10];
    const float* g2   = (const float*)d_in[11];
    const float* be2  = (const float*)d_in[12];
    const float* bn0g = (const float*)d_in[13];
    const float* bn0b = (const float*)d_in[14];
    const float* L1W  = (const float*)d_in[15];
    const float* L1b  = (const float*)d_in[16];
    const float* bn1g = (const float*)d_in[17];
    const float* bn1b = (const float*)d_in[18];
    const float* L2W  = (const float*)d_in[19];
    const float* L2b  = (const float*)d_in[20];
    const float* bn2g = (const float*)d_in[21];
    const float* bn2b = (const float*)d_in[22];
    const float* L3W  = (const float*)d_in[23];
    const float* L3b  = (const float*)d_in[24];
    const float* catW = (const float*)d_in[25];
    const float* catb = (const float*)d_in[26];

    float* out = (float*)d_out;
    float* out_main  = out;
    float* out_class = out + 256 * 128;
    float* out_fp    = out + 256 * 128 + 256 * 12;

    __half *adjc, *xTh, *A1h, *A1l, *B1h, *B1l, *h1h, *h1l, *W2Th, *W2Tl, *B2h;
    float *axp, *biasax, *bias2, *pre1, *g2in, *pre2, *pool, *bnp, *l1, *bn1, *l2;
    float *psum, *psq, *scale, *shift;
    cudaGetSymbolAddress((void**)&adjc,  g_adjc);
    cudaGetSymbolAddress((void**)&xTh,   g_xT_h);
    cudaGetSymbolAddress((void**)&axp,   g_axp);
    cudaGetSymbolAddress((void**)&biasax,g_biasax);
    cudaGetSymbolAddress((void**)&bias2, g_bias2);
    cudaGetSymbolAddress((void**)&A1h,   g_A1_h);
    cudaGetSymbolAddress((void**)&A1l,   g_A1_l);
    cudaGetSymbolAddress((void**)&B1h,   g_B1_h);
    cudaGetSymbolAddress((void**)&B1l,   g_B1_l);
    cudaGetSymbolAddress((void**)&pre1,  g_pre1);
    cudaGetSymbolAddress((void**)&h1h,   g_h1_h);
    cudaGetSymbolAddress((void**)&h1l,   g_h1_l);
    cudaGetSymbolAddress((void**)&W2Th,  g_W2T_h);
    cudaGetSymbolAddress((void**)&W2Tl,  g_W2T_l);
    cudaGetSymbolAddress((void**)&g2in,  g_g2in);
    cudaGetSymbolAddress((void**)&B2h,   g_B2_h);
    cudaGetSymbolAddress((void**)&pre2,  g_pre2);
    cudaGetSymbolAddress((void**)&pool,  g_pool);
    cudaGetSymbolAddress((void**)&bnp,   g_bnp);
    cudaGetSymbolAddress((void**)&l1,    g_l1);
    cudaGetSymbolAddress((void**)&bn1,   g_bn1);
    cudaGetSymbolAddress((void**)&l2,    g_l2);
    cudaGetSymbolAddress((void**)&psum,  g_psum);
    cudaGetSymbolAddress((void**)&psq,   g_psq);
    cudaGetSymbolAddress((void**)&scale, g_scale);
    cudaGetSymbolAddress((void**)&shift, g_shift);

    static bool attr_done = false;
    if (!attr_done) {
        cudaFuncSetAttribute(mma2_k<1, false, false>, cudaFuncAttributeMaxDynamicSharedMemorySize, 61440);
        cudaFuncSetAttribute(mma2_k<1, true, true>,   cudaFuncAttributeMaxDynamicSharedMemorySize, 61440);
        cudaFuncSetAttribute(mma2_k<3, false, false>, cudaFuncAttributeMaxDynamicSharedMemorySize, 122880);
        cudaFuncSetAttribute(mma2_k<3, true, true>,   cudaFuncAttributeMaxDynamicSharedMemorySize, 122880);
        attr_done = true;
    }

    // prep
    cvt_adj_k<<<NN * NN / 4 / 256, 256>>>(adj, adjc);
    transconv1_k<<<dim3(FF / 32, NN / 32), dim3(32, 8)>>>(x, xTh, FF, NN, 0);
    split_into_k<<<NN * FF / 256, 256>>>(x, A1h, A1l, FF, HH, FF);
    transconv2_k<<<dim3(HH / 32, FF / 32), dim3(32, 8)>>>(W1,  B1h, B1l, HH, HH, 0);
    transconv2_k<<<dim3(HH / 32, FF / 32), dim3(32, 8)>>>(Ws1, B1h, B1l, HH, HH, FF);
    transconv2_k<<<dim3(HH / 32, HH / 32), dim3(32, 8)>>>(W2,  W2Th, W2Tl, HH, HH, 0);
    transconv1_k<<<dim3(HH / 32, HH / 32), dim3(32, 8)>>>(Ws2, B2h, HH, K2TOT, NN);
    colsum_k<<<FF, 256>>>(x, NN, FF, ADJC, (const float*)0, biasax);

    // layer 1: ax = adj_c @ x (single-pass fp16, split-K2 via z) + rank-1 correction
    mma2_k<1, false, false><<<dim3(1, NN / 128, 2), 256, 61440>>>(
        adjc, (const __half*)0, NN, BIGK, (const __half*)0, 0, xTh, (const __half*)0, NN,
        axp, (const float*)0, FF, 128, 0, (size_t)NN * FF);
    combine_ax_k<<<NN * FF / 256, 256>>>(axp, axp + (size_t)NN * FF, biasax, A1h, A1l);
    // pre1 = relu([ax|x] @ [W1;Ws1]^T + b1)  (3-pass)
    mma2_k<3, true, true><<<dim3(2, NN / 128), 256, 122880>>>(
        A1h, A1l, HH, BIGK, (const __half*)0, 0, B1h, B1l, HH,
        pre1, b1, HH, 8, 0, 0);
    bn_partial_k<<<256, 256>>>(pre1, psum, psq);
    bn_finalize_k<<<1, 256>>>(psum, psq, g1, be1, scale, shift);
    bn_apply_k<true><<<(NN * HH / 4) / 256, 256>>>(pre1, scale, shift, h1h, h1l);

    // layer 2: g2in = h1 @ W2 (3-pass)
    mma2_k<3, false, false><<<dim3(2, NN / 128), 256, 122880>>>(
        h1h, h1l, HH, BIGK, (const __half*)0, 0, W2Th, W2Tl, HH,
        g2in, (const float*)0, HH, 8, 0, 0);
    transconv1_k<<<dim3(HH / 32, NN / 32), dim3(32, 8)>>>(g2in, B2h, HH, K2TOT, 0);
    colsum_k<<<HH, 256>>>(g2in, NN, HH, ADJC, b2, bias2);
    // pre2 = relu([adj_c|h1] @ [g2in;Ws2]^T + bias2)  (single-pass)
    mma2_k<1, true, true><<<dim3(2, NN / 128), 256, 61440>>>(
        adjc, (const __half*)0, NN, NN / 32, h1h, HH, B2h, (const __half*)0, K2TOT,
        pre2, bias2, HH, K2TOT / 32, 0, 0);
    bn_partial_k<<<256, 256>>>(pre2, psum, psq);
    bn_finalize_k<<<1, 256>>>(psum, psq, g2, be2, scale, shift);
    bn_apply_k<false><<<(NN * HH / 4) / 256, 256>>>(pre2, scale, shift, (__half*)0, (__half*)0);

    // pooling
    pool_k<<<GG, 256>>>(pre1, pre2, pool);

    // MLP head
    bn_small_k<<<1024 / 32, dim3(32, 8)>>>(pool, bn0g, bn0b, bnp, 1024);
    sgemm64_k<true, true><<<dim3(512 / 64, GG / 64), 256>>>(bnp, L1W, l1, L1b, GG, 512, 1024);
    bn_small_k<<<512 / 32, dim3(32, 8)>>>(l1, bn1g, bn1b, bn1, 512);
    sgemm64_k<true, true><<<dim3(256 / 64, GG / 64), 256>>>(bn1, L2W, l2, L2b, GG, 256, 512);
    bn_small_k<<<256 / 32, dim3(32, 8)>>>(l2, bn2g, bn2b, out_fp, 256);
    dense_small_k<<<(256 * 128 + 255) / 256, 256>>>(out_fp, L3W, L3b, out_main, 256, 128, 256);
    dense_small_k<<<(256 * 12 + 255) / 256, 256>>>(out_fp, catW, catb, out_class, 256, 12, 256);

    (void)in_sizes; (void)n_in; (void)out_size;
}

// round 12
// speedup vs baseline: 4.0257x; 1.1335x over previous
#include <cuda_runtime.h>
#include <cuda_fp16.h>
#include <math.h>
#include <stdint.h>

#define NN   8192
#define FF   128
#define HH   256
#define GG   256
#define NPG  32
#define EPSB 1e-5f
#define K2TOT (NN + HH)
#define BIGK (1 << 30)
#define ADJC 0.015625f

__device__ __half g_adjc [NN * NN];
__device__ __half g_xT_h [FF * NN];
__device__ float  g_axp  [2 * NN * FF];
__device__ float  g_biasax[FF];
__device__ float  g_bias2 [HH];
__device__ __half g_A1_h [NN * HH];
__device__ __half g_A1_l [NN * HH];
__device__ __half g_B1_h [HH * HH];
__device__ __half g_B1_l [HH * HH];
__device__ float  g_pre1 [NN * HH];
__device__ __half g_h1_h [NN * HH];
__device__ __half g_h1_l [NN * HH];
__device__ __half g_W2T_h[HH * HH];
__device__ __half g_W2T_l[HH * HH];
__device__ float  g_g2in [NN * HH];
__device__ __half g_B2_h [HH * K2TOT];
__device__ float  g_pre2 [NN * HH];
__device__ float  g_pool [GG * 1024];
__device__ float  g_bnp  [GG * 1024];
__device__ float  g_l1   [GG * 512];
__device__ float  g_bn1  [GG * 512];
__device__ float  g_l2   [GG * 256];
__device__ float  g_psum [256 * HH];
__device__ float  g_psq  [256 * HH];
__device__ float  g_scale[HH];
__device__ float  g_shift[HH];

__device__ __forceinline__ uint32_t smem_u32(const void* p) {
    uint32_t a;
    asm("{ .reg .u64 t; cvta.to.shared.u64 t, %1; cvt.u32.u64 %0, t; }" : "=r"(a) : "l"(p));
    return a;
}
__device__ __forceinline__ void ldsm4(uint32_t* r, uint32_t addr) {
    asm volatile("ldmatrix.sync.aligned.m8n8.x4.shared.b16 {%0,%1,%2,%3}, [%4];"
        : "=r"(r[0]), "=r"(r[1]), "=r"(r[2]), "=r"(r[3]) : "r"(addr));
}
__device__ __forceinline__ void mma16816(float* d, const uint32_t* a, uint32_t b0, uint32_t b1) {
    asm volatile("mma.sync.aligned.m16n8k16.row.col.f32.f16.f16.f32 "
        "{%0,%1,%2,%3}, {%4,%5,%6,%7}, {%8,%9}, {%0,%1,%2,%3};"
        : "+f"(d[0]), "+f"(d[1]), "+f"(d[2]), "+f"(d[3])
        : "r"(a[0]), "r"(a[1]), "r"(a[2]), "r"(a[3]), "r"(b0), "r"(b1));
}
#define CP_ASYNC16(dst, src) asm volatile("cp.async.cg.shared.global [%0], [%1], 16;" :: "r"(dst), "l"(src))
#define CP_COMMIT()          asm volatile("cp.async.commit_group;" ::: "memory")
#define CP_WAIT1()           asm volatile("cp.async.wait_group 1;" ::: "memory")

__device__ __forceinline__ void split2h(float v, __half& h, __half& l) {
    h = __float2half_rn(v);
    l = __float2half_rn(v - __half2float(h));
}

// fp16 tensor-core GEMM, BK=64 chunks, 3-stage cp.async pipeline.
// PASSES==1: C = A @ B^T               (both single plane)
// PASSES==3: C = (Ah+Al) @ (Bh+Bl)^T   (lo*lo dropped)
// A may concatenate two single-plane sources along K (first nck1 chunks A1, rest A2).
// blockIdx.z: split-K partials (chunk window shifts by z*nck, C shifts by z*zCstride).
// smem row stride 72 halfs (144 B) -> LDSM conflict-free.
#define PLANE_E 9216

template <int PASSES, bool BIAS, bool RELU>
__global__ void __launch_bounds__(256, 2)
mma2_k(const __half* __restrict__ A1h, const __half* __restrict__ A1l, int strA1, int nck1,
       const __half* __restrict__ A2h, int strA2,
       const __half* __restrict__ Bh,  const __half* __restrict__ Bl,  int strB,
       float* __restrict__ C, const float* __restrict__ bias, int Ntot,
       int nck, int ck0, size_t zCstride)
{
    constexpr int NA = (PASSES == 3) ? 2 : 1;
    constexpr int NB = (PASSES == 3) ? 2 : 1;
    constexpr int STG_E = (NA + NB) * PLANE_E;
    constexpr int AL_O  = PLANE_E;
    constexpr int B_O   = NA * PLANE_E;
    constexpr int BL_O  = B_O + PLANE_E;

    extern __shared__ __align__(16) __half sm[];
    const int tid  = threadIdx.x;
    const int wid  = tid >> 5;
    const int lane = tid & 31;
    const int m0 = blockIdx.y * 128;
    const int n0 = blockIdx.x * 128;
    const int wm = (wid & 3) * 32;
    const int wn = (wid >> 2) * 64;

    ck0 += blockIdx.z * nck;
    C   += blockIdx.z * zCstride;

    float acc[2][8][4];
#pragma unroll
    for (int i = 0; i < 2; i++)
#pragma unroll
        for (int j = 0; j < 8; j++)
#pragma unroll
            for (int v = 0; v < 4; v++) acc[i][j][v] = 0.f;

    auto loadStage = [&](int lck, int stg) {
        const int g = ck0 + lck;
        const __half* ah;
        int kloc, strA;
        if (g < nck1) { ah = A1h; strA = strA1; kloc = g * 64; }
        else          { ah = A2h; strA = strA2; kloc = (g - nck1) * 64; }
        const uint32_t sA  = smem_u32(sm + stg * STG_E);
        const uint32_t sAl = smem_u32(sm + stg * STG_E + AL_O);
        const uint32_t sBh = smem_u32(sm + stg * STG_E + B_O);
        const uint32_t sBl = smem_u32(sm + stg * STG_E + BL_O);
        const int kb = g * 64;
#pragma unroll
        for (int it = 0; it < 4; it++) {
            const int i = tid + it * 256;
            const int r = i >> 3, c = i & 7;
            const uint32_t so = (uint32_t)(r * 72 + c * 8) * 2;
            CP_ASYNC16(sA + so, ah + (size_t)(m0 + r) * strA + kloc + c * 8);
            if (NA == 2) CP_ASYNC16(sAl + so, A1l + (size_t)(m0 + r) * strA + kloc + c * 8);
            CP_ASYNC16(sBh + so, Bh + (size_t)(n0 + r) * strB + kb + c * 8);
            if (NB == 2) CP_ASYNC16(sBl + so, Bl + (size_t)(n0 + r) * strB + kb + c * 8);
        }
        CP_COMMIT();
    };

    loadStage(0, 0);
    if (nck > 1) loadStage(1, 1); else CP_COMMIT();
    CP_WAIT1();
    __syncthreads();

    for (int ck = 0; ck < nck; ck++) {
        const int stg = ck % 3;
        const uint32_t sA  = smem_u32(sm + stg * STG_E);
        const uint32_t sAl = smem_u32(sm + stg * STG_E + AL_O);
        const uint32_t sBh = smem_u32(sm + stg * STG_E + B_O);
        const uint32_t sBl = smem_u32(sm + stg * STG_E + BL_O);

#pragma unroll
        for (int ks = 0; ks < 4; ks++) {
            uint32_t af[2][4], alf[2][4];
#pragma unroll
            for (int i = 0; i < 2; i++) {
                const int row = wm + i * 16 + (lane & 15);
                const int col = ks * 16 + (lane >> 4) * 8;
                ldsm4(af[i], sA + (uint32_t)(row * 72 + col) * 2);
                if (NA == 2) ldsm4(alf[i], sAl + (uint32_t)(row * 72 + col) * 2);
            }
#pragma unroll
            for (int half = 0; half < 2; half++) {
                uint32_t bh[8], bl[8];
#pragma unroll
                for (int jp = 0; jp < 2; jp++) {
                    const int g = lane >> 3;
                    const int row = wn + (half * 4 + jp * 2 + (g >> 1)) * 8 + (lane & 7);
                    const int col = ks * 16 + (g & 1) * 8;
                    ldsm4(&bh[jp * 4], sBh + (uint32_t)(row * 72 + col) * 2);
                    if (NB == 2) ldsm4(&bl[jp * 4], sBl + (uint32_t)(row * 72 + col) * 2);
                }
#pragma unroll
                for (int i = 0; i < 2; i++)
#pragma unroll
                    for (int t = 0; t < 4; t++)
                        mma16816(acc[i][half * 4 + t], af[i], bh[t * 2], bh[t * 2 + 1]);
                if (NB == 2) {
#pragma unroll
                    for (int i = 0; i < 2; i++)
#pragma unroll
                        for (int t = 0; t < 4; t++)
                            mma16816(acc[i][half * 4 + t], af[i], bl[t * 2], bl[t * 2 + 1]);
                }
                if (NA == 2) {
#pragma unroll
                    for (int i = 0; i < 2; i++)
#pragma unroll
                        for (int t = 0; t < 4; t++)
                            mma16816(acc[i][half * 4 + t], alf[i], bh[t * 2], bh[t * 2 + 1]);
                }
            }
        }

        if (ck + 2 < nck) loadStage(ck + 2, (ck + 2) % 3); else CP_COMMIT();
        CP_WAIT1();
        __syncthreads();
    }

#pragma unroll
    for (int i = 0; i < 2; i++) {
        const int r0 = m0 + wm + i * 16 + (lane >> 2);
#pragma unroll
        for (int j = 0; j < 8; j++) {
            const int cc = n0 + wn + j * 8 + (lane & 3) * 2;
            const size_t o0 = (size_t)r0 * Ntot + cc;
            const size_t o1 = (size_t)(r0 + 8) * Ntot + cc;
            float2 v0 = make_float2(acc[i][j][0], acc[i][j][1]);
            float2 v1 = make_float2(acc[i][j][2], acc[i][j][3]);
            if (BIAS) {
                const float2 bv = *(const float2*)(bias + cc);
                v0.x += bv.x; v0.y += bv.y; v1.x += bv.x; v1.y += bv.y;
            }
            if (RELU) {
                v0.x = fmaxf(v0.x, 0.f); v0.y = fmaxf(v0.y, 0.f);
                v1.x = fmaxf(v1.x, 0.f); v1.y = fmaxf(v1.y, 0.f);
            }
            *(float2*)(C + o0) = v0;
            *(float2*)(C + o1) = v1;
        }
    }
}

// adj fp32 -> (adj - 1/64) fp16
__global__ void cvt_adj_k(const float* __restrict__ in, __half* __restrict__ o)
{
    const int i = blockIdx.x * blockDim.x + threadIdx.x;
    float4 v = ((const float4*)in)[i];
    v.x -= ADJC; v.y -= ADJC; v.z -= ADJC; v.w -= ADJC;
    __half2 a = __floats2half2_rn(v.x, v.y);
    __half2 b = __floats2half2_rn(v.z, v.w);
    uint2 p;
    p.x = *(uint32_t*)&a;
    p.y = *(uint32_t*)&b;
    ((uint2*)o)[i] = p;
}

// out[c] = addend[c] + scale * sum_r in[r][c]
__global__ void colsum_k(const float* __restrict__ in, int R, int C,
                         float scale, const float* __restrict__ addend,
                         float* __restrict__ out)
{
    __shared__ float red[256];
    const int c = blockIdx.x;
    float s = 0.f;
    for (int r = threadIdx.x; r < R; r += 256) s += in[(size_t)r * C + c];
    red[threadIdx.x] = s;
    __syncthreads();
    for (int o = 128; o > 0; o >>= 1) {
        if (threadIdx.x < o) red[threadIdx.x] += red[threadIdx.x + o];
        __syncthreads();
    }
    if (threadIdx.x == 0) out[c] = (addend ? addend[c] : 0.f) + scale * red[0];
}

// in[R][C] -> hi/lo fp16 into out cols [ooff..)
__global__ void split_into_k(const float* __restrict__ in, __half* __restrict__ oh,
                             __half* __restrict__ ol, int C, int ostr, int ooff)
{
    const int idx = blockIdx.x * blockDim.x + threadIdx.x;
    const int r = idx / C, c = idx - r * C;
    __half h, l;
    split2h(in[idx], h, l);
    oh[(size_t)r * ostr + ooff + c] = h;
    ol[(size_t)r * ostr + ooff + c] = l;
}

// combine split-K partials + bias, write hi/lo fp16 into A1 cols [0,128)
__global__ void combine_ax_k(const float* __restrict__ a0, const float* __restrict__ a1,
                             const float* __restrict__ bias,
                             __half* __restrict__ oh, __half* __restrict__ ol)
{
    const int idx = blockIdx.x * blockDim.x + threadIdx.x;
    const int r = idx >> 7, c = idx & 127;
    __half h, l;
    split2h(a0[idx] + a1[idx] + bias[c], h, l);
    oh[(size_t)r * HH + c] = h;
    ol[(size_t)r * HH + c] = l;
}

// transpose + single-plane fp16: out[c][koff+r] = rn16(in[r][c])
__global__ void transconv1_k(const float* __restrict__ in, __half* __restrict__ o,
                             int C, int ostr, int koff)
{
    __shared__ float t[32][33];
    const int c0 = blockIdx.x * 32, r0 = blockIdx.y * 32;
    const int tx = threadIdx.x, ty = threadIdx.y;
#pragma unroll
    for (int j = 0; j < 4; j++)
        t[ty + j * 8][tx] = in[(size_t)(r0 + ty + j * 8) * C + c0 + tx];
    __syncthreads();
#pragma unroll
    for (int j = 0; j < 4; j++)
        o[(size_t)(c0 + ty + j * 8) * ostr + koff + r0 + tx] = __float2half_rn(t[tx][ty + j * 8]);
}

// transpose + hi/lo split
__global__ void transconv2_k(const float* __restrict__ in, __half* __restrict__ oh,
                             __half* __restrict__ ol, int C, int ostr, int koff)
{
    __shared__ float t[32][33];
    const int c0 = blockIdx.x * 32, r0 = blockIdx.y * 32;
    const int tx = threadIdx.x, ty = threadIdx.y;
#pragma unroll
    for (int j = 0; j < 4; j++)
        t[ty + j * 8][tx] = in[(size_t)(r0 + ty + j * 8) * C + c0 + tx];
    __syncthreads();
#pragma unroll
    for (int j = 0; j < 4; j++) {
        __half h, l;
        split2h(t[tx][ty + j * 8], h, l);
        const size_t o = (size_t)(c0 + ty + j * 8) * ostr + koff + r0 + tx;
        oh[o] = h; ol[o] = l;
    }
}

// fp32 SGEMM, 64x64 tile (head GEMMs)
template <bool BIAS, bool RELU>
__global__ void __launch_bounds__(256, 3)
sgemm64_k(const float* __restrict__ A, const float* __restrict__ B,
          float* __restrict__ C, const float* __restrict__ bias, int M, int N, int K)
{
    constexpr int BM = 64, BN = 64, BK = 16, TM = 4, TN = 4;
    __shared__ float As[BK][BM];
    __shared__ float Bs[BK][BN];
    const int tid = threadIdx.x;
    const int bx = blockIdx.x, by = blockIdx.y;
    const int aRow = tid >> 2, aCol = (tid & 3) * 4;
    const float* Ag = A + (size_t)(by * BM + aRow) * K + aCol;
    const int bRow = tid >> 4, bCol = (tid & 15) * 4;
    const float* Bg = B + (size_t)bRow * N + bx * BN + bCol;
    const int tr = (tid >> 4) * TM, tc = (tid & 15) * TN;

    float acc[TM][TN];
#pragma unroll
    for (int i = 0; i < TM; i++)
#pragma unroll
        for (int j = 0; j < TN; j++) acc[i][j] = 0.f;

    for (int k0 = 0; k0 < K; k0 += BK) {
        float4 a0 = *(const float4*)(Ag + k0);
        As[aCol + 0][aRow] = a0.x;  As[aCol + 1][aRow] = a0.y;
        As[aCol + 2][aRow] = a0.z;  As[aCol + 3][aRow] = a0.w;
        *(float4*)&Bs[bRow][bCol] = *(const float4*)(Bg + (size_t)k0 * N);
        __syncthreads();
#pragma unroll
        for (int k = 0; k < BK; k++) {
            float ra[TM], rb[TN];
#pragma unroll
            for (int i = 0; i < TM; i++) ra[i] = As[k][tr + i];
#pragma unroll
            for (int j = 0; j < TN; j++) rb[j] = Bs[k][tc + j];
#pragma unroll
            for (int i = 0; i < TM; i++)
#pragma unroll
                for (int j = 0; j < TN; j++) acc[i][j] = fmaf(ra[i], rb[j], acc[i][j]);
        }
        __syncthreads();
    }
    float4 bv = make_float4(0.f, 0.f, 0.f, 0.f);
    if (BIAS) bv = *(const float4*)(bias + bx * BN + tc);
#pragma unroll
    for (int i = 0; i < TM; i++) {
        const size_t off = (size_t)(by * BM + tr + i) * N + bx * BN + tc;
        float4 v = make_float4(acc[i][0], acc[i][1], acc[i][2], acc[i][3]);
        if (BIAS) { v.x += bv.x; v.y += bv.y; v.z += bv.z; v.w += bv.w; }
        if (RELU) {
            v.x = fmaxf(v.x, 0.f); v.y = fmaxf(v.y, 0.f);
            v.z = fmaxf(v.z, 0.f); v.w = fmaxf(v.w, 0.f);
        }
        *(float4*)(C + off) = v;
    }
}

// BatchNorm partials: 256 blocks x 32 rows
__global__ void bn_partial_k(const float* __restrict__ x, float* __restrict__ psum,
                             float* __restrict__ psq)
{
    const int t = threadIdx.x;
    const float* p = x + (size_t)blockIdx.x * 32 * HH + t;
    float s = 0.f, q = 0.f;
#pragma unroll 4
    for (int r = 0; r < 32; r++) { float v = p[(size_t)r * HH]; s += v; q += v * v; }
    psum[blockIdx.x * HH + t] = s;
    psq [blockIdx.x * HH + t] = q;
}

__global__ void bn_finalize_k(const float* __restrict__ psum, const float* __restrict__ psq,
                              const float* __restrict__ gamma, const float* __restrict__ beta,
                              float* __restrict__ scale, float* __restrict__ shift)
{
    const int t = threadIdx.x;
    float s = 0.f, q = 0.f;
#pragma unroll 8
    for (int b = 0; b < 256; b++) { s += psum[b * HH + t]; q += psq[b * HH + t]; }
    const float invn = 1.f / (float)NN;
    const float m = s * invn;
    const float var = q * invn - m * m;
    const float sc = gamma[t] * rsqrtf(var + EPSB);
    scale[t] = sc;
    shift[t] = beta[t] - m * sc;
}

template <bool CVT>
__global__ void bn_apply_k(float* __restrict__ x, const float* __restrict__ scale,
                           const float* __restrict__ shift,
                           __half* __restrict__ oh, __half* __restrict__ ol)
{
    const int i = blockIdx.x * blockDim.x + threadIdx.x;
    const int c = (i * 4) & (HH - 1);
    float4 v = ((float4*)x)[i];
    v.x = fmaf(v.x, scale[c + 0], shift[c + 0]);
    v.y = fmaf(v.y, scale[c + 1], shift[c + 1]);
    v.z = fmaf(v.z, scale[c + 2], shift[c + 2]);
    v.w = fmaf(v.w, scale[c + 3], shift[c + 3]);
    ((float4*)x)[i] = v;
    if (CVT) {
        __half h0, h1, h2, h3, l0, l1, l2, l3;
        split2h(v.x, h0, l0); split2h(v.y, h1, l1);
        split2h(v.z, h2, l2); split2h(v.w, h3, l3);
        __half2 ph0 = __halves2half2(h0, h1), ph1 = __halves2half2(h2, h3);
        __half2 pl0 = __halves2half2(l0, l1), pl1 = __halves2half2(l2, l3);
        uint2 hp, lp;
        hp.x = *(uint32_t*)&ph0; hp.y = *(uint32_t*)&ph1;
        lp.x = *(uint32_t*)&pl0; lp.y = *(uint32_t*)&pl1;
        ((uint2*)oh)[i] = hp;
        ((uint2*)ol)[i] = lp;
    }
}

__global__ void pool_k(const float* __restrict__ h1, const float* __restrict__ h2,
                       float* __restrict__ pooled)
{
    const int g = blockIdx.x, t = threadIdx.x;
    const size_t r0 = (size_t)g * NPG;
    float mx1 = -1e30f, mx2 = -1e30f, s1 = 0.f, s2 = 0.f;
#pragma unroll 4
    for (int r = 0; r < NPG; r++) {
        float v1 = h1[(r0 + r) * HH + t];
        float v2 = h2[(r0 + r) * HH + t];
        mx1 = fmaxf(mx1, v1); s1 += v1;
        mx2 = fmaxf(mx2, v2); s2 += v2;
    }
    float* out = pooled + (size_t)g * 1024;
    out[t]       = mx1;
    out[256 + t] = mx2;
    out[512 + t] = s1 * (1.f / NPG);
    out[768 + t] = s2 * (1.f / NPG);
}

// small BN: one block per 32 columns, block (32,8)
__global__ void bn_small_k(const float* __restrict__ in, const float* __restrict__ gamma,
                           const float* __restrict__ beta, float* __restrict__ out, int C)
{
    __shared__ float ssum[8][32], ssq[8][32], ssc[32], ssh[32];
    const int tx = threadIdx.x, ty = threadIdx.y;
    const int c = blockIdx.x * 32 + tx;
    float s = 0.f, q = 0.f;
    for (int r = ty; r < GG; r += 8) {
        const float v = in[(size_t)r * C + c];
        s += v; q += v * v;
    }
    ssum[ty][tx] = s; ssq[ty][tx] = q;
    __syncthreads();
    if (ty == 0) {
        float S = 0.f, Q = 0.f;
#pragma unroll
        for (int k = 0; k < 8; k++) { S += ssum[k][tx]; Q += ssq[k][tx]; }
        const float m = S * (1.f / GG);
        const float var = Q * (1.f / GG) - m * m;
        const float sc = gamma[c] * rsqrtf(var + EPSB);
        ssc[tx] = sc;
        ssh[tx] = beta[c] - m * sc;
    }
    __syncthreads();
    const float sc = ssc[tx], sh = ssh[tx];
    for (int r = ty; r < GG; r += 8)
        out[(size_t)r * C + c] = fmaf(in[(size_t)r * C + c], sc, sh);
}

__global__ void dense_small_k(const float* __restrict__ A, const float* __restrict__ W,
                              const float* __restrict__ b, float* __restrict__ C,
                              int M, int N, int K)
{
    const int idx = blockIdx.x * blockDim.x + threadIdx.x;
    if (idx >= M * N) return;
    const int m = idx / N, n = idx - m * N;
    float acc = b[n];
    const float* a = A + (size_t)m * K;
    for (int k = 0; k < K; k++) acc = fmaf(a[k], W[(size_t)k * N + n], acc);
    C[idx] = acc;
}

extern "C" void kernel_launch(void* const* d_in, const int* in_sizes, int n_in,
                              void* d_out, int out_size)
{
    const float* x    = (const float*)d_in[0];
    const float* adj  = (const float*)d_in[1];
    const float* W1   = (const float*)d_in[3];
    const float* Ws1  = (const float*)d_in[4];
    const float* b1   = (const float*)d_in[5];
    const float* g1   = (const float*)d_in[6];
    const float* be1  = (const float*)d_in[7];
    const float* W2   = (const float*)d_in[8];
    const float* Ws2  = (const float*)d_in[9];
    const float* b2   = (const float*)d_in[10];
    const float* g2   = (const float*)d_in[11];
    const float* be2  = (const float*)d_in[12];
    const float* bn0g = (const float*)d_in[13];
    const float* bn0b = (const float*)d_in[14];
    const float* L1W  = (const float*)d_in[15];
    const float* L1b  = (const float*)d_in[16];
    const float* bn1g = (const float*)d_in[17];
    const float* bn1b = (const float*)d_in[18];
    const float* L2W  = (const float*)d_in[19];
    const float* L2b  = (const float*)d_in[20];
    const float* bn2g = (const float*)d_in[21];
    const float* bn2b = (const float*)d_in[22];
    const float* L3W  = (const float*)d_in[23];
    const float* L3b  = (const float*)d_in[24];
    const float* catW = (const float*)d_in[25];
    const float* catb = (const float*)d_in[26];

    float* out = (float*)d_out;
    float* out_main  = out;
    float* out_class = out + 256 * 128;
    float* out_fp    = out + 256 * 128 + 256 * 12;

    __half *adjc, *xTh, *A1h, *A1l, *B1h, *B1l, *h1h, *h1l, *W2Th, *W2Tl, *B2h;
    float *axp, *biasax, *bias2, *pre1, *g2in, *pre2, *pool, *bnp, *l1, *bn1, *l2;
    float *psum, *psq, *scale, *shift;
    cudaGetSymbolAddress((void**)&adjc,  g_adjc);
    cudaGetSymbolAddress((void**)&xTh,   g_xT_h);
    cudaGetSymbolAddress((void**)&axp,   g_axp);
    cudaGetSymbolAddress((void**)&biasax,g_biasax);
    cudaGetSymbolAddress((void**)&bias2, g_bias2);
    cudaGetSymbolAddress((void**)&A1h,   g_A1_h);
    cudaGetSymbolAddress((void**)&A1l,   g_A1_l);
    cudaGetSymbolAddress((void**)&B1h,   g_B1_h);
    cudaGetSymbolAddress((void**)&B1l,   g_B1_l);
    cudaGetSymbolAddress((void**)&pre1,  g_pre1);
    cudaGetSymbolAddress((void**)&h1h,   g_h1_h);
    cudaGetSymbolAddress((void**)&h1l,   g_h1_l);
    cudaGetSymbolAddress((void**)&W2Th,  g_W2T_h);
    cudaGetSymbolAddress((void**)&W2Tl,  g_W2T_l);
    cudaGetSymbolAddress((void**)&g2in,  g_g2in);
    cudaGetSymbolAddress((void**)&B2h,   g_B2_h);
    cudaGetSymbolAddress((void**)&pre2,  g_pre2);
    cudaGetSymbolAddress((void**)&pool,  g_pool);
    cudaGetSymbolAddress((void**)&bnp,   g_bnp);
    cudaGetSymbolAddress((void**)&l1,    g_l1);
    cudaGetSymbolAddress((void**)&bn1,   g_bn1);
    cudaGetSymbolAddress((void**)&l2,    g_l2);
    cudaGetSymbolAddress((void**)&psum,  g_psum);
    cudaGetSymbolAddress((void**)&psq,   g_psq);
    cudaGetSymbolAddress((void**)&scale, g_scale);
    cudaGetSymbolAddress((void**)&shift, g_shift);

    static bool attr_done = false;
    if (!attr_done) {
        cudaFuncSetAttribute(mma2_k<1, false, false>, cudaFuncAttributeMaxDynamicSharedMemorySize, 110592);
        cudaFuncSetAttribute(mma2_k<1, true, true>,   cudaFuncAttributeMaxDynamicSharedMemorySize, 110592);
        cudaFuncSetAttribute(mma2_k<3, false, false>, cudaFuncAttributeMaxDynamicSharedMemorySize, 221184);
        cudaFuncSetAttribute(mma2_k<3, true, true>,   cudaFuncAttributeMaxDynamicSharedMemorySize, 221184);
        attr_done = true;
    }

    // prep
    cvt_adj_k<<<NN * NN / 4 / 256, 256>>>(adj, adjc);
    transconv1_k<<<dim3(FF / 32, NN / 32), dim3(32, 8)>>>(x, xTh, FF, NN, 0);
    split_into_k<<<NN * FF / 256, 256>>>(x, A1h, A1l, FF, HH, FF);
    transconv2_k<<<dim3(HH / 32, FF / 32), dim3(32, 8)>>>(W1,  B1h, B1l, HH, HH, 0);
    transconv2_k<<<dim3(HH / 32, FF / 32), dim3(32, 8)>>>(Ws1, B1h, B1l, HH, HH, FF);
    transconv2_k<<<dim3(HH / 32, HH / 32), dim3(32, 8)>>>(W2,  W2Th, W2Tl, HH, HH, 0);
    transconv1_k<<<dim3(HH / 32, HH / 32), dim3(32, 8)>>>(Ws2, B2h, HH, K2TOT, NN);
    colsum_k<<<FF, 256>>>(x, NN, FF, ADJC, (const float*)0, biasax);

    // layer 1: ax = adj_c @ x (single-pass fp16, BK=64, split-K2 via z) + rank-1 correction
    mma2_k<1, false, false><<<dim3(1, NN / 128, 2), 256, 110592>>>(
        adjc, (const __half*)0, NN, BIGK, (const __half*)0, 0, xTh, (const __half*)0, NN,
        axp, (const float*)0, FF, 64, 0, (size_t)NN * FF);
    combine_ax_k<<<NN * FF / 256, 256>>>(axp, axp + (size_t)NN * FF, biasax, A1h, A1l);
    // pre1 = relu([ax|x] @ [W1;Ws1]^T + b1)  (3-pass)
    mma2_k<3, true, true><<<dim3(2, NN / 128), 256, 221184>>>(
        A1h, A1l, HH, BIGK, (const __half*)0, 0, B1h, B1l, HH,
        pre1, b1, HH, 4, 0, 0);
    bn_partial_k<<<256, 256>>>(pre1, psum, psq);
    bn_finalize_k<<<1, 256>>>(psum, psq, g1, be1, scale, shift);
    bn_apply_k<true><<<(NN * HH / 4) / 256, 256>>>(pre1, scale, shift, h1h, h1l);

    // layer 2: g2in = h1 @ W2 (3-pass)
    mma2_k<3, false, false><<<dim3(2, NN / 128), 256, 221184>>>(
        h1h, h1l, HH, BIGK, (const __half*)0, 0, W2Th, W2Tl, HH,
        g2in, (const float*)0, HH, 4, 0, 0);
    transconv1_k<<<dim3(HH / 32, NN / 32), dim3(32, 8)>>>(g2in, B2h, HH, K2TOT, 0);
    colsum_k<<<HH, 256>>>(g2in, NN, HH, ADJC, b2, bias2);
    // pre2 = relu([adj_c|h1] @ [g2in;Ws2]^T + bias2)  (single-pass, BK=64)
    mma2_k<1, true, true><<<dim3(2, NN / 128), 256, 110592>>>(
        adjc, (const __half*)0, NN, NN / 64, h1h, HH, B2h, (const __half*)0, K2TOT,
        pre2, bias2, HH, K2TOT / 64, 0, 0);
    bn_partial_k<<<256, 256>>>(pre2, psum, psq);
    bn_finalize_k<<<1, 256>>>(psum, psq, g2, be2, scale, shift);
    bn_apply_k<false><<<(NN * HH / 4) / 256, 256>>>(pre2, scale, shift, (__half*)0, (__half*)0);

    // pooling
    pool_k<<<GG, 256>>>(pre1, pre2, pool);

    // MLP head
    bn_small_k<<<1024 / 32, dim3(32, 8)>>>(pool, bn0g, bn0b, bnp, 1024);
    sgemm64_k<true, true><<<dim3(512 / 64, GG / 64), 256>>>(bnp, L1W, l1, L1b, GG, 512, 1024);
    bn_small_k<<<512 / 32, dim3(32, 8)>>>(l1, bn1g, bn1b, bn1, 512);
    sgemm64_k<true, true><<<dim3(256 / 64, GG / 64), 256>>>(bn1, L2W, l2, L2b, GG, 256, 512);
    bn_small_k<<<256 / 32, dim3(32, 8)>>>(l2, bn2g, bn2b, out_fp, 256);
    dense_small_k<<<(256 * 128 + 255) / 256, 256>>>(out_fp, L3W, L3b, out_main, 256, 128, 256);
    dense_small_k<<<(256 * 12 + 255) / 256, 256>>>(out_fp, catW, catb, out_class, 256, 12, 256);

    (void)in_sizes; (void)n_in; (void)out_size;
}

// round 13
// speedup vs baseline: 4.1703x; 1.0359x over previous
#include <cuda_runtime.h>
#include <cuda_fp16.h>
#include <math.h>
#include <stdint.h>

#define NN   8192
#define FF   128
#define HH   256
#define GG   256
#define NPG  32
#define EPSB 1e-5f
#define K2TOT (NN + HH)
#define BIGK (1 << 30)
#define ADJC 0.015625f

__device__ __half g_adjc [NN * NN];
__device__ __half g_xT_h [FF * NN];
__device__ float  g_axp  [4 * NN * FF];
__device__ float  g_p2p  [2 * NN * HH];
__device__ float  g_biasax[FF];
__device__ float  g_bias2 [HH];
__device__ __half g_A1_h [NN * HH];
__device__ __half g_A1_l [NN * HH];
__device__ __half g_B1_h [HH * HH];
__device__ __half g_B1_l [HH * HH];
__device__ float  g_pre1 [NN * HH];
__device__ __half g_h1_h [NN * HH];
__device__ __half g_h1_l [NN * HH];
__device__ __half g_W2T_h[HH * HH];
__device__ __half g_W2T_l[HH * HH];
__device__ float  g_g2in [NN * HH];
__device__ __half g_B2_h [HH * K2TOT];
__device__ float  g_pre2 [NN * HH];
__device__ float  g_pool [GG * 1024];
__device__ float  g_bnp  [GG * 1024];
__device__ float  g_l1   [GG * 512];
__device__ float  g_bn1  [GG * 512];
__device__ float  g_l2   [GG * 256];
__device__ float  g_psum [256 * HH];
__device__ float  g_psq  [256 * HH];
__device__ float  g_scale[HH];
__device__ float  g_shift[HH];

__device__ __forceinline__ uint32_t smem_u32(const void* p) {
    uint32_t a;
    asm("{ .reg .u64 t; cvta.to.shared.u64 t, %1; cvt.u32.u64 %0, t; }" : "=r"(a) : "l"(p));
    return a;
}
__device__ __forceinline__ void ldsm4(uint32_t* r, uint32_t addr) {
    asm volatile("ldmatrix.sync.aligned.m8n8.x4.shared.b16 {%0,%1,%2,%3}, [%4];"
        : "=r"(r[0]), "=r"(r[1]), "=r"(r[2]), "=r"(r[3]) : "r"(addr));
}
__device__ __forceinline__ void mma16816(float* d, const uint32_t* a, uint32_t b0, uint32_t b1) {
    asm volatile("mma.sync.aligned.m16n8k16.row.col.f32.f16.f16.f32 "
        "{%0,%1,%2,%3}, {%4,%5,%6,%7}, {%8,%9}, {%0,%1,%2,%3};"
        : "+f"(d[0]), "+f"(d[1]), "+f"(d[2]), "+f"(d[3])
        : "r"(a[0]), "r"(a[1]), "r"(a[2]), "r"(a[3]), "r"(b0), "r"(b1));
}
#define CP_ASYNC16(dst, src) asm volatile("cp.async.cg.shared.global [%0], [%1], 16;" :: "r"(dst), "l"(src))
#define CP_COMMIT()          asm volatile("cp.async.commit_group;" ::: "memory")
#define CP_WAIT1()           asm volatile("cp.async.wait_group 1;" ::: "memory")

__device__ __forceinline__ void split2h(float v, __half& h, __half& l) {
    h = __float2half_rn(v);
    l = __float2half_rn(v - __half2float(h));
}

// fp16 tensor-core GEMM, BK=64 chunks, 3-stage cp.async pipeline.
// PASSES==1: C = A @ B^T               (both single plane)
// PASSES==3: C = (Ah+Al) @ (Bh+Bl)^T   (lo*lo dropped)
// A may concatenate two single-plane sources along K (first nck1 chunks A1, rest A2).
// blockIdx.z: split-K partials (chunk window shifts by z*nck, C shifts by z*zCstride).
#define PLANE_E 9216

template <int PASSES, bool BIAS, bool RELU>
__global__ void __launch_bounds__(256, 2)
mma2_k(const __half* __restrict__ A1h, const __half* __restrict__ A1l, int strA1, int nck1,
       const __half* __restrict__ A2h, int strA2,
       const __half* __restrict__ Bh,  const __half* __restrict__ Bl,  int strB,
       float* __restrict__ C, const float* __restrict__ bias, int Ntot,
       int nck, int ck0, size_t zCstride)
{
    constexpr int NA = (PASSES == 3) ? 2 : 1;
    constexpr int NB = (PASSES == 3) ? 2 : 1;
    constexpr int STG_E = (NA + NB) * PLANE_E;
    constexpr int AL_O  = PLANE_E;
    constexpr int B_O   = NA * PLANE_E;
    constexpr int BL_O  = B_O + PLANE_E;

    extern __shared__ __align__(16) __half sm[];
    const int tid  = threadIdx.x;
    const int wid  = tid >> 5;
    const int lane = tid & 31;
    const int m0 = blockIdx.y * 128;
    const int n0 = blockIdx.x * 128;
    const int wm = (wid & 3) * 32;
    const int wn = (wid >> 2) * 64;

    ck0 += blockIdx.z * nck;
    C   += blockIdx.z * zCstride;

    float acc[2][8][4];
#pragma unroll
    for (int i = 0; i < 2; i++)
#pragma unroll
        for (int j = 0; j < 8; j++)
#pragma unroll
            for (int v = 0; v < 4; v++) acc[i][j][v] = 0.f;

    auto loadStage = [&](int lck, int stg) {
        const int g = ck0 + lck;
        const __half* ah;
        int kloc, strA;
        if (g < nck1) { ah = A1h; strA = strA1; kloc = g * 64; }
        else          { ah = A2h; strA = strA2; kloc = (g - nck1) * 64; }
        const uint32_t sA  = smem_u32(sm + stg * STG_E);
        const uint32_t sAl = smem_u32(sm + stg * STG_E + AL_O);
        const uint32_t sBh = smem_u32(sm + stg * STG_E + B_O);
        const uint32_t sBl = smem_u32(sm + stg * STG_E + BL_O);
        const int kb = g * 64;
#pragma unroll
        for (int it = 0; it < 4; it++) {
            const int i = tid + it * 256;
            const int r = i >> 3, c = i & 7;
            const uint32_t so = (uint32_t)(r * 72 + c * 8) * 2;
            CP_ASYNC16(sA + so, ah + (size_t)(m0 + r) * strA + kloc + c * 8);
            if (NA == 2) CP_ASYNC16(sAl + so, A1l + (size_t)(m0 + r) * strA + kloc + c * 8);
            CP_ASYNC16(sBh + so, Bh + (size_t)(n0 + r) * strB + kb + c * 8);
            if (NB == 2) CP_ASYNC16(sBl + so, Bl + (size_t)(n0 + r) * strB + kb + c * 8);
        }
        CP_COMMIT();
    };

    loadStage(0, 0);
    if (nck > 1) loadStage(1, 1); else CP_COMMIT();
    CP_WAIT1();
    __syncthreads();

    for (int ck = 0; ck < nck; ck++) {
        const int stg = ck % 3;
        const uint32_t sA  = smem_u32(sm + stg * STG_E);
        const uint32_t sAl = smem_u32(sm + stg * STG_E + AL_O);
        const uint32_t sBh = smem_u32(sm + stg * STG_E + B_O);
        const uint32_t sBl = smem_u32(sm + stg * STG_E + BL_O);

#pragma unroll
        for (int ks = 0; ks < 4; ks++) {
            uint32_t af[2][4], alf[2][4];
#pragma unroll
            for (int i = 0; i < 2; i++) {
                const int row = wm + i * 16 + (lane & 15);
                const int col = ks * 16 + (lane >> 4) * 8;
                ldsm4(af[i], sA + (uint32_t)(row * 72 + col) * 2);
                if (NA == 2) ldsm4(alf[i], sAl + (uint32_t)(row * 72 + col) * 2);
            }
#pragma unroll
            for (int half = 0; half < 2; half++) {
                uint32_t bh[8], bl[8];
#pragma unroll
                for (int jp = 0; jp < 2; jp++) {
                    const int g = lane >> 3;
                    const int row = wn + (half * 4 + jp * 2 + (g >> 1)) * 8 + (lane & 7);
                    const int col = ks * 16 + (g & 1) * 8;
                    ldsm4(&bh[jp * 4], sBh + (uint32_t)(row * 72 + col) * 2);
                    if (NB == 2) ldsm4(&bl[jp * 4], sBl + (uint32_t)(row * 72 + col) * 2);
                }
#pragma unroll
                for (int i = 0; i < 2; i++)
#pragma unroll
                    for (int t = 0; t < 4; t++)
                        mma16816(acc[i][half * 4 + t], af[i], bh[t * 2], bh[t * 2 + 1]);
                if (NB == 2) {
#pragma unroll
                    for (int i = 0; i < 2; i++)
#pragma unroll
                        for (int t = 0; t < 4; t++)
                            mma16816(acc[i][half * 4 + t], af[i], bl[t * 2], bl[t * 2 + 1]);
                }
                if (NA == 2) {
#pragma unroll
                    for (int i = 0; i < 2; i++)
#pragma unroll
                        for (int t = 0; t < 4; t++)
                            mma16816(acc[i][half * 4 + t], alf[i], bh[t * 2], bh[t * 2 + 1]);
                }
            }
        }

        if (ck + 2 < nck) loadStage(ck + 2, (ck + 2) % 3); else CP_COMMIT();
        CP_WAIT1();
        __syncthreads();
    }

#pragma unroll
    for (int i = 0; i < 2; i++) {
        const int r0 = m0 + wm + i * 16 + (lane >> 2);
#pragma unroll
        for (int j = 0; j < 8; j++) {
            const int cc = n0 + wn + j * 8 + (lane & 3) * 2;
            const size_t o0 = (size_t)r0 * Ntot + cc;
            const size_t o1 = (size_t)(r0 + 8) * Ntot + cc;
            float2 v0 = make_float2(acc[i][j][0], acc[i][j][1]);
            float2 v1 = make_float2(acc[i][j][2], acc[i][j][3]);
            if (BIAS) {
                const float2 bv = *(const float2*)(bias + cc);
                v0.x += bv.x; v0.y += bv.y; v1.x += bv.x; v1.y += bv.y;
            }
            if (RELU) {
                v0.x = fmaxf(v0.x, 0.f); v0.y = fmaxf(v0.y, 0.f);
                v1.x = fmaxf(v1.x, 0.f); v1.y = fmaxf(v1.y, 0.f);
            }
            *(float2*)(C + o0) = v0;
            *(float2*)(C + o1) = v1;
        }
    }
}

// adj fp32 -> (adj - 1/64) fp16
__global__ void cvt_adj_k(const float* __restrict__ in, __half* __restrict__ o)
{
    const int i = blockIdx.x * blockDim.x + threadIdx.x;
    float4 v = ((const float4*)in)[i];
    v.x -= ADJC; v.y -= ADJC; v.z -= ADJC; v.w -= ADJC;
    __half2 a = __floats2half2_rn(v.x, v.y);
    __half2 b = __floats2half2_rn(v.z, v.w);
    uint2 p;
    p.x = *(uint32_t*)&a;
    p.y = *(uint32_t*)&b;
    ((uint2*)o)[i] = p;
}

// out[c] = addend[c] + scale * sum_r in[r][c]
__global__ void colsum_k(const float* __restrict__ in, int R, int C,
                         float scale, const float* __restrict__ addend,
                         float* __restrict__ out)
{
    __shared__ float red[256];
    const int c = blockIdx.x;
    float s = 0.f;
    for (int r = threadIdx.x; r < R; r += 256) s += in[(size_t)r * C + c];
    red[threadIdx.x] = s;
    __syncthreads();
    for (int o = 128; o > 0; o >>= 1) {
        if (threadIdx.x < o) red[threadIdx.x] += red[threadIdx.x + o];
        __syncthreads();
    }
    if (threadIdx.x == 0) out[c] = (addend ? addend[c] : 0.f) + scale * red[0];
}

// in[R][C] -> hi/lo fp16 into out cols [ooff..)
__global__ void split_into_k(const float* __restrict__ in, __half* __restrict__ oh,
                             __half* __restrict__ ol, int C, int ostr, int ooff)
{
    const int idx = blockIdx.x * blockDim.x + threadIdx.x;
    const int r = idx / C, c = idx - r * C;
    __half h, l;
    split2h(in[idx], h, l);
    oh[(size_t)r * ostr + ooff + c] = h;
    ol[(size_t)r * ostr + ooff + c] = l;
}

// combine 4 split-K partials + bias, write hi/lo fp16 into A1 cols [0,128)
__global__ void combine_ax_k(const float* __restrict__ a0, const float* __restrict__ bias,
                             __half* __restrict__ oh, __half* __restrict__ ol)
{
    const int idx = blockIdx.x * blockDim.x + threadIdx.x;
    const int r = idx >> 7, c = idx & 127;
    const size_t st = (size_t)NN * FF;
    __half h, l;
    split2h((a0[idx] + a0[idx + st]) + (a0[idx + 2 * st] + a0[idx + 3 * st]) + bias[c], h, l);
    oh[(size_t)r * HH + c] = h;
    ol[(size_t)r * HH + c] = l;
}

// combine 2 split-K partials of pre2 + bias + relu
__global__ void combine_pre2_k(const float* __restrict__ p, const float* __restrict__ bias,
                               float* __restrict__ out)
{
    const int idx = blockIdx.x * blockDim.x + threadIdx.x;
    const int c = idx & (HH - 1);
    const float v = p[idx] + p[idx + (size_t)NN * HH] + bias[c];
    out[idx] = fmaxf(v, 0.f);
}

// transpose + single-plane fp16: out[c][koff+r] = rn16(in[r][c])
__global__ void transconv1_k(const float* __restrict__ in, __half* __restrict__ o,
                             int C, int ostr, int koff)
{
    __shared__ float t[32][33];
    const int c0 = blockIdx.x * 32, r0 = blockIdx.y * 32;
    const int tx = threadIdx.x, ty = threadIdx.y;
#pragma unroll
    for (int j = 0; j < 4; j++)
        t[ty + j * 8][tx] = in[(size_t)(r0 + ty + j * 8) * C + c0 + tx];
    __syncthreads();
#pragma unroll
    for (int j = 0; j < 4; j++)
        o[(size_t)(c0 + ty + j * 8) * ostr + koff + r0 + tx] = __float2half_rn(t[tx][ty + j * 8]);
}

// transpose + hi/lo split
__global__ void transconv2_k(const float* __restrict__ in, __half* __restrict__ oh,
                             __half* __restrict__ ol, int C, int ostr, int koff)
{
    __shared__ float t[32][33];
    const int c0 = blockIdx.x * 32, r0 = blockIdx.y * 32;
    const int tx = threadIdx.x, ty = threadIdx.y;
#pragma unroll
    for (int j = 0; j < 4; j++)
        t[ty + j * 8][tx] = in[(size_t)(r0 + ty + j * 8) * C + c0 + tx];
    __syncthreads();
#pragma unroll
    for (int j = 0; j < 4; j++) {
        __half h, l;
        split2h(t[tx][ty + j * 8], h, l);
        const size_t o = (size_t)(c0 + ty + j * 8) * ostr + koff + r0 + tx;
        oh[o] = h; ol[o] = l;
    }
}

// fp32 SGEMM, 64x64 tile (head GEMMs)
template <bool BIAS, bool RELU>
__global__ void __launch_bounds__(256, 3)
sgemm64_k(const float* __restrict__ A, const float* __restrict__ B,
          float* __restrict__ C, const float* __restrict__ bias, int M, int N, int K)
{
    constexpr int BM = 64, BN = 64, BK = 16, TM = 4, TN = 4;
    __shared__ float As[BK][BM];
    __shared__ float Bs[BK][BN];
    const int tid = threadIdx.x;
    const int bx = blockIdx.x, by = blockIdx.y;
    const int aRow = tid >> 2, aCol = (tid & 3) * 4;
    const float* Ag = A + (size_t)(by * BM + aRow) * K + aCol;
    const int bRow = tid >> 4, bCol = (tid & 15) * 4;
    const float* Bg = B + (size_t)bRow * N + bx * BN + bCol;
    const int tr = (tid >> 4) * TM, tc = (tid & 15) * TN;

    float acc[TM][TN];
#pragma unroll
    for (int i = 0; i < TM; i++)
#pragma unroll
        for (int j = 0; j < TN; j++) acc[i][j] = 0.f;

    for (int k0 = 0; k0 < K; k0 += BK) {
        float4 a0 = *(const float4*)(Ag + k0);
        As[aCol + 0][aRow] = a0.x;  As[aCol + 1][aRow] = a0.y;
        As[aCol + 2][aRow] = a0.z;  As[aCol + 3][aRow] = a0.w;
        *(float4*)&Bs[bRow][bCol] = *(const float4*)(Bg + (size_t)k0 * N);
        __syncthreads();
#pragma unroll
        for (int k = 0; k < BK; k++) {
            float ra[TM], rb[TN];
#pragma unroll
            for (int i = 0; i < TM; i++) ra[i] = As[k][tr + i];
#pragma unroll
            for (int j = 0; j < TN; j++) rb[j] = Bs[k][tc + j];
#pragma unroll
            for (int i = 0; i < TM; i++)
#pragma unroll
                for (int j = 0; j < TN; j++) acc[i][j] = fmaf(ra[i], rb[j], acc[i][j]);
        }
        __syncthreads();
    }
    float4 bv = make_float4(0.f, 0.f, 0.f, 0.f);
    if (BIAS) bv = *(const float4*)(bias + bx * BN + tc);
#pragma unroll
    for (int i = 0; i < TM; i++) {
        const size_t off = (size_t)(by * BM + tr + i) * N + bx * BN + tc;
        float4 v = make_float4(acc[i][0], acc[i][1], acc[i][2], acc[i][3]);
        if (BIAS) { v.x += bv.x; v.y += bv.y; v.z += bv.z; v.w += bv.w; }
        if (RELU) {
            v.x = fmaxf(v.x, 0.f); v.y = fmaxf(v.y, 0.f);
            v.z = fmaxf(v.z, 0.f); v.w = fmaxf(v.w, 0.f);
        }
        *(float4*)(C + off) = v;
    }
}

// BatchNorm partials: 256 blocks x 32 rows
__global__ void bn_partial_k(const float* __restrict__ x, float* __restrict__ psum,
                             float* __restrict__ psq)
{
    const int t = threadIdx.x;
    const float* p = x + (size_t)blockIdx.x * 32 * HH + t;
    float s = 0.f, q = 0.f;
#pragma unroll 4
    for (int r = 0; r < 32; r++) { float v = p[(size_t)r * HH]; s += v; q += v * v; }
    psum[blockIdx.x * HH + t] = s;
    psq [blockIdx.x * HH + t] = q;
}

__global__ void bn_finalize_k(const float* __restrict__ psum, const float* __restrict__ psq,
                              const float* __restrict__ gamma, const float* __restrict__ beta,
                              float* __restrict__ scale, float* __restrict__ shift)
{
    const int t = threadIdx.x;
    float s = 0.f, q = 0.f;
#pragma unroll 8
    for (int b = 0; b < 256; b++) { s += psum[b * HH + t]; q += psq[b * HH + t]; }
    const float invn = 1.f / (float)NN;
    const float m = s * invn;
    const float var = q * invn - m * m;
    const float sc = gamma[t] * rsqrtf(var + EPSB);
    scale[t] = sc;
    shift[t] = beta[t] - m * sc;
}

template <bool CVT>
__global__ void bn_apply_k(float* __restrict__ x, const float* __restrict__ scale,
                           const float* __restrict__ shift,
                           __half* __restrict__ oh, __half* __restrict__ ol)
{
    const int i = blockIdx.x * blockDim.x + threadIdx.x;
    const int c = (i * 4) & (HH - 1);
    float4 v = ((float4*)x)[i];
    v.x = fmaf(v.x, scale[c + 0], shift[c + 0]);
    v.y = fmaf(v.y, scale[c + 1], shift[c + 1]);
    v.z = fmaf(v.z, scale[c + 2], shift[c + 2]);
    v.w = fmaf(v.w, scale[c + 3], shift[c + 3]);
    ((float4*)x)[i] = v;
    if (CVT) {
        __half h0, h1, h2, h3, l0, l1, l2, l3;
        split2h(v.x, h0, l0); split2h(v.y, h1, l1);
        split2h(v.z, h2, l2); split2h(v.w, h3, l3);
        __half2 ph0 = __halves2half2(h0, h1), ph1 = __halves2half2(h2, h3);
        __half2 pl0 = __halves2half2(l0, l1), pl1 = __halves2half2(l2, l3);
        uint2 hp, lp;
        hp.x = *(uint32_t*)&ph0; hp.y = *(uint32_t*)&ph1;
        lp.x = *(uint32_t*)&pl0; lp.y = *(uint32_t*)&pl1;
        ((uint2*)oh)[i] = hp;
        ((uint2*)ol)[i] = lp;
    }
}

__global__ void pool_k(const float* __restrict__ h1, const float* __restrict__ h2,
                       float* __restrict__ pooled)
{
    const int g = blockIdx.x, t = threadIdx.x;
    const size_t r0 = (size_t)g * NPG;
    float mx1 = -1e30f, mx2 = -1e30f, s1 = 0.f, s2 = 0.f;
#pragma unroll 4
    for (int r = 0; r < NPG; r++) {
        float v1 = h1[(r0 + r) * HH + t];
        float v2 = h2[(r0 + r) * HH + t];
        mx1 = fmaxf(mx1, v1); s1 += v1;
        mx2 = fmaxf(mx2, v2); s2 += v2;
    }
    float* out = pooled + (size_t)g * 1024;
    out[t]       = mx1;
    out[256 + t] = mx2;
    out[512 + t] = s1 * (1.f / NPG);
    out[768 + t] = s2 * (1.f / NPG);
}

// small BN: one block per 32 columns, block (32,8)
__global__ void bn_small_k(const float* __restrict__ in, const float* __restrict__ gamma,
                           const float* __restrict__ beta, float* __restrict__ out, int C)
{
    __shared__ float ssum[8][32], ssq[8][32], ssc[32], ssh[32];
    const int tx = threadIdx.x, ty = threadIdx.y;
    const int c = blockIdx.x * 32 + tx;
    float s = 0.f, q = 0.f;
    for (int r = ty; r < GG; r += 8) {
        const float v = in[(size_t)r * C + c];
        s += v; q += v * v;
    }
    ssum[ty][tx] = s; ssq[ty][tx] = q;
    __syncthreads();
    if (ty == 0) {
        float S = 0.f, Q = 0.f;
#pragma unroll
        for (int k = 0; k < 8; k++) { S += ssum[k][tx]; Q += ssq[k][tx]; }
        const float m = S * (1.f / GG);
        const float var = Q * (1.f / GG) - m * m;
        const float sc = gamma[c] * rsqrtf(var + EPSB);
        ssc[tx] = sc;
        ssh[tx] = beta[c] - m * sc;
    }
    __syncthreads();
    const float sc = ssc[tx], sh = ssh[tx];
    for (int r = ty; r < GG; r += 8)
        out[(size_t)r * C + c] = fmaf(in[(size_t)r * C + c], sc, sh);
}

__global__ void dense_small_k(const float* __restrict__ A, const float* __restrict__ W,
                              const float* __restrict__ b, float* __restrict__ C,
                              int M, int N, int K)
{
    const int idx = blockIdx.x * blockDim.x + threadIdx.x;
    if (idx >= M * N) return;
    const int m = idx / N, n = idx - m * N;
    float acc = b[n];
    const float* a = A + (size_t)m * K;
    for (int k = 0; k < K; k++) acc = fmaf(a[k], W[(size_t)k * N + n], acc);
    C[idx] = acc;
}

extern "C" void kernel_launch(void* const* d_in, const int* in_sizes, int n_in,
                              void* d_out, int out_size)
{
    const float* x    = (const float*)d_in[0];
    const float* adj  = (const float*)d_in[1];
    const float* W1   = (const float*)d_in[3];
    const float* Ws1  = (const float*)d_in[4];
    const float* b1   = (const float*)d_in[5];
    const float* g1   = (const float*)d_in[6];
    const float* be1  = (const float*)d_in[7];
    const float* W2   = (const float*)d_in[8];
    const float* Ws2  = (const float*)d_in[9];
    const float* b2   = (const float*)d_in[10];
    const float* g2   = (const float*)d_in[11];
    const float* be2  = (const float*)d_in[12];
    const float* bn0g = (const float*)d_in[13];
    const float* bn0b = (const float*)d_in[14];
    const float* L1W  = (const float*)d_in[15];
    const float* L1b  = (const float*)d_in[16];
    const float* bn1g = (const float*)d_in[17];
    const float* bn1b = (const float*)d_in[18];
    const float* L2W  = (const float*)d_in[19];
    const float* L2b  = (const float*)d_in[20];
    const float* bn2g = (const float*)d_in[21];
    const float* bn2b = (const float*)d_in[22];
    const float* L3W  = (const float*)d_in[23];
    const float* L3b  = (const float*)d_in[24];
    const float* catW = (const float*)d_in[25];
    const float* catb = (const float*)d_in[26];

    float* out = (float*)d_out;
    float* out_main  = out;
    float* out_class = out + 256 * 128;
    float* out_fp    = out + 256 * 128 + 256 * 12;

    __half *adjc, *xTh, *A1h, *A1l, *B1h, *B1l, *h1h, *h1l, *W2Th, *W2Tl, *B2h;
    float *axp, *p2p, *biasax, *bias2, *pre1, *g2in, *pre2, *pool, *bnp, *l1, *bn1, *l2;
    float *psum, *psq, *scale, *shift;
    cudaGetSymbolAddress((void**)&adjc,  g_adjc);
    cudaGetSymbolAddress((void**)&xTh,   g_xT_h);
    cudaGetSymbolAddress((void**)&axp,   g_axp);
    cudaGetSymbolAddress((void**)&p2p,   g_p2p);
    cudaGetSymbolAddress((void**)&biasax,g_biasax);
    cudaGetSymbolAddress((void**)&bias2, g_bias2);
    cudaGetSymbolAddress((void**)&A1h,   g_A1_h);
    cudaGetSymbolAddress((void**)&A1l,   g_A1_l);
    cudaGetSymbolAddress((void**)&B1h,   g_B1_h);
    cudaGetSymbolAddress((void**)&B1l,   g_B1_l);
    cudaGetSymbolAddress((void**)&pre1,  g_pre1);
    cudaGetSymbolAddress((void**)&h1h,   g_h1_h);
    cudaGetSymbolAddress((void**)&h1l,   g_h1_l);
    cudaGetSymbolAddress((void**)&W2Th,  g_W2T_h);
    cudaGetSymbolAddress((void**)&W2Tl,  g_W2T_l);
    cudaGetSymbolAddress((void**)&g2in,  g_g2in);
    cudaGetSymbolAddress((void**)&B2h,   g_B2_h);
    cudaGetSymbolAddress((void**)&pre2,  g_pre2);
    cudaGetSymbolAddress((void**)&pool,  g_pool);
    cudaGetSymbolAddress((void**)&bnp,   g_bnp);
    cudaGetSymbolAddress((void**)&l1,    g_l1);
    cudaGetSymbolAddress((void**)&bn1,   g_bn1);
    cudaGetSymbolAddress((void**)&l2,    g_l2);
    cudaGetSymbolAddress((void**)&psum,  g_psum);
    cudaGetSymbolAddress((void**)&psq,   g_psq);
    cudaGetSymbolAddress((void**)&scale, g_scale);
    cudaGetSymbolAddress((void**)&shift, g_shift);

    static bool attr_done = false;
    if (!attr_done) {
        cudaFuncSetAttribute(mma2_k<1, false, false>, cudaFuncAttributeMaxDynamicSharedMemorySize, 110592);
        cudaFuncSetAttribute(mma2_k<3, false, false>, cudaFuncAttributeMaxDynamicSharedMemorySize, 221184);
        cudaFuncSetAttribute(mma2_k<3, true, true>,   cudaFuncAttributeMaxDynamicSharedMemorySize, 221184);
        attr_done = true;
    }

    // prep
    cvt_adj_k<<<NN * NN / 4 / 256, 256>>>(adj, adjc);
    transconv1_k<<<dim3(FF / 32, NN / 32), dim3(32, 8)>>>(x, xTh, FF, NN, 0);
    split_into_k<<<NN * FF / 256, 256>>>(x, A1h, A1l, FF, HH, FF);
    transconv2_k<<<dim3(HH / 32, FF / 32), dim3(32, 8)>>>(W1,  B1h, B1l, HH, HH, 0);
    transconv2_k<<<dim3(HH / 32, FF / 32), dim3(32, 8)>>>(Ws1, B1h, B1l, HH, HH, FF);
    transconv2_k<<<dim3(HH / 32, HH / 32), dim3(32, 8)>>>(W2,  W2Th, W2Tl, HH, HH, 0);
    transconv1_k<<<dim3(HH / 32, HH / 32), dim3(32, 8)>>>(Ws2, B2h, HH, K2TOT, NN);
    colsum_k<<<FF, 256>>>(x, NN, FF, ADJC, (const float*)0, biasax);

    // layer 1: ax = adj_c @ x (single-pass fp16, BK=64, split-K4 via z) + rank-1 correction
    mma2_k<1, false, false><<<dim3(1, NN / 128, 4), 256, 110592>>>(
        adjc, (const __half*)0, NN, BIGK, (const __half*)0, 0, xTh, (const __half*)0, NN,
        axp, (const float*)0, FF, 32, 0, (size_t)NN * FF);
    combine_ax_k<<<NN * FF / 256, 256>>>(axp, biasax, A1h, A1l);
    // pre1 = relu([ax|x] @ [W1;Ws1]^T + b1)  (3-pass)
    mma2_k<3, true, true><<<dim3(2, NN / 128), 256, 221184>>>(
        A1h, A1l, HH, BIGK, (const __half*)0, 0, B1h, B1l, HH,
        pre1, b1, HH, 4, 0, 0);
    bn_partial_k<<<256, 256>>>(pre1, psum, psq);
    bn_finalize_k<<<1, 256>>>(psum, psq, g1, be1, scale, shift);
    bn_apply_k<true><<<(NN * HH / 4) / 256, 256>>>(pre1, scale, shift, h1h, h1l);

    // layer 2: g2in = h1 @ W2 (3-pass)
    mma2_k<3, false, false><<<dim3(2, NN / 128), 256, 221184>>>(
        h1h, h1l, HH, BIGK, (const __half*)0, 0, W2Th, W2Tl, HH,
        g2in, (const float*)0, HH, 4, 0, 0);
    transconv1_k<<<dim3(HH / 32, NN / 32), dim3(32, 8)>>>(g2in, B2h, HH, K2TOT, 0);
    colsum_k<<<HH, 256>>>(g2in, NN, HH, ADJC, b2, bias2);
    // pre2 partials (single-pass, BK=64, split-K2 via z), then combine + bias + relu
    mma2_k<1, false, false><<<dim3(2, NN / 128, 2), 256, 110592>>>(
        adjc, (const __half*)0, NN, NN / 64, h1h, HH, B2h, (const __half*)0, K2TOT,
        p2p, (const float*)0, HH, K2TOT / 128, 0, (size_t)NN * HH);
    combine_pre2_k<<<NN * HH / 256, 256>>>(p2p, bias2, pre2);
    bn_partial_k<<<256, 256>>>(pre2, psum, psq);
    bn_finalize_k<<<1, 256>>>(psum, psq, g2, be2, scale, shift);
    bn_apply_k<false><<<(NN * HH / 4) / 256, 256>>>(pre2, scale, shift, (__half*)0, (__half*)0);

    // pooling
    pool_k<<<GG, 256>>>(pre1, pre2, pool);

    // MLP head
    bn_small_k<<<1024 / 32, dim3(32, 8)>>>(pool, bn0g, bn0b, bnp, 1024);
    sgemm64_k<true, true><<<dim3(512 / 64, GG / 64), 256>>>(bnp, L1W, l1, L1b, GG, 512, 1024);
    bn_small_k<<<512 / 32, dim3(32, 8)>>>(l1, bn1g, bn1b, bn1, 512);
    sgemm64_k<true, true><<<dim3(256 / 64, GG / 64), 256>>>(bn1, L2W, l2, L2b, GG, 256, 512);
    bn_small_k<<<256 / 32, dim3(32, 8)>>>(l2, bn2g, bn2b, out_fp, 256);
    dense_small_k<<<(256 * 128 + 255) / 256, 256>>>(out_fp, L3W, L3b, out_main, 256, 128, 256);
    dense_small_k<<<(256 * 12 + 255) / 256, 256>>>(out_fp, catW, catb, out_class, 256, 12, 256);

    (void)in_sizes; (void)n_in; (void)out_size;
}

// round 14
// speedup vs baseline: 4.3683x; 1.0475x over previous
#include <cuda_runtime.h>
#include <cuda_fp16.h>
#include <math.h>
#include <stdint.h>

#define NN   8192
#define FF   128
#define HH   256
#define GG   256
#define NPG  32
#define EPSB 1e-5f
#define K2TOT (NN + HH)
#define BIGK (1 << 30)
#define ADJC 0.015625f

__device__ __half g_adjc [NN * NN];
__device__ __half g_xT_h [FF * NN];
__device__ float  g_axp  [4 * NN * FF];
__device__ float  g_p2p  [2 * NN * HH];
__device__ float  g_biasax[FF];
__device__ float  g_bias2 [HH];
__device__ __half g_A1_h [NN * HH];
__device__ __half g_A1_l [NN * HH];
__device__ __half g_B1_h [HH * HH];
__device__ __half g_B1_l [HH * HH];
__device__ float  g_pre1 [NN * HH];
__device__ __half g_h1_h [NN * HH];
__device__ __half g_h1_l [NN * HH];
__device__ __half g_W2T_h[HH * HH];
__device__ __half g_W2T_l[HH * HH];
__device__ float  g_g2in [NN * HH];
__device__ __half g_B2_h [HH * K2TOT];
__device__ float  g_pre2 [NN * HH];
__device__ float  g_pool [GG * 1024];
__device__ float  g_bnp  [GG * 1024];
__device__ float  g_l1   [GG * 512];
__device__ float  g_bn1  [GG * 512];
__device__ float  g_l2   [GG * 256];
__device__ float  g_psum [256 * HH];
__device__ float  g_psq  [256 * HH];
__device__ float  g_scale[HH];
__device__ float  g_shift[HH];

__device__ __forceinline__ uint32_t smem_u32(const void* p) {
    uint32_t a;
    asm("{ .reg .u64 t; cvta.to.shared.u64 t, %1; cvt.u32.u64 %0, t; }" : "=r"(a) : "l"(p));
    return a;
}
__device__ __forceinline__ void ldsm4(uint32_t* r, uint32_t addr) {
    asm volatile("ldmatrix.sync.aligned.m8n8.x4.shared.b16 {%0,%1,%2,%3}, [%4];"
        : "=r"(r[0]), "=r"(r[1]), "=r"(r[2]), "=r"(r[3]) : "r"(addr));
}
__device__ __forceinline__ void mma16816(float* d, const uint32_t* a, uint32_t b0, uint32_t b1) {
    asm volatile("mma.sync.aligned.m16n8k16.row.col.f32.f16.f16.f32 "
        "{%0,%1,%2,%3}, {%4,%5,%6,%7}, {%8,%9}, {%0,%1,%2,%3};"
        : "+f"(d[0]), "+f"(d[1]), "+f"(d[2]), "+f"(d[3])
        : "r"(a[0]), "r"(a[1]), "r"(a[2]), "r"(a[3]), "r"(b0), "r"(b1));
}
#define CP_ASYNC16(dst, src) asm volatile("cp.async.cg.shared.global [%0], [%1], 16;" :: "r"(dst), "l"(src))
#define CP_COMMIT()          asm volatile("cp.async.commit_group;" ::: "memory")
#define CP_WAIT1()           asm volatile("cp.async.wait_group 1;" ::: "memory")
#define CP_WAIT0()           asm volatile("cp.async.wait_group 0;" ::: "memory")

__device__ __forceinline__ void split2h(float v, __half& h, __half& l) {
    h = __float2half_rn(v);
    l = __float2half_rn(v - __half2float(h));
}

#define PLANE_E 9216

// ============ ax GEMM with fused adj fp32->fp16 conversion ============
// C_partial[z] = (adj - 1/64)[rows m0..m0+127][K-slice z] @ xT^T
// Also WRITES the converted fp16 adj plane to adjc (each element exactly once).
// 2-stage: A via LDG-prefetch + convert + STS (+ STG to adjc), B via cp.async.
__global__ void __launch_bounds__(256, 2)
axcvt_k(const float* __restrict__ adj, __half* __restrict__ adjc,
        const __half* __restrict__ Bt, float* __restrict__ C,
        int nck, size_t zCstride)
{
    constexpr int STG_E = 2 * PLANE_E;   // A plane + B plane per stage
    extern __shared__ __align__(16) __half sm[];
    const int tid  = threadIdx.x;
    const int wid  = tid >> 5;
    const int lane = tid & 31;
    const int m0 = blockIdx.y * 128;
    const int wm = (wid & 3) * 32;
    const int wn = (wid >> 2) * 64;
    const int ck0 = blockIdx.z * nck;
    C += blockIdx.z * zCstride;

    float acc[2][8][4];
#pragma unroll
    for (int i = 0; i < 2; i++)
#pragma unroll
        for (int j = 0; j < 8; j++)
#pragma unroll
            for (int v = 0; v < 4; v++) acc[i][j][v] = 0.f;

    float4 aPre[8];
    auto ldgA = [&](int lck) {
        const int kb = (ck0 + lck) * 64;
#pragma unroll
        for (int it = 0; it < 4; it++) {
            const int i = tid + it * 256;
            const int r = i >> 3, c = i & 7;
            const float* p = adj + (size_t)(m0 + r) * NN + kb + c * 8;
            aPre[it * 2]     = *(const float4*)p;
            aPre[it * 2 + 1] = *(const float4*)(p + 4);
        }
    };
    auto cvtstA = [&](int lck, int stg) {
        const int kb = (ck0 + lck) * 64;
        __half* sA = sm + stg * STG_E;
#pragma unroll
        for (int it = 0; it < 4; it++) {
            const int i = tid + it * 256;
            const int r = i >> 3, c = i & 7;
            const float4 v0 = aPre[it * 2];
            const float4 v1 = aPre[it * 2 + 1];
            __half2 h01 = __floats2half2_rn(v0.x - ADJC, v0.y - ADJC);
            __half2 h23 = __floats2half2_rn(v0.z - ADJC, v0.w - ADJC);
            __half2 h45 = __floats2half2_rn(v1.x - ADJC, v1.y - ADJC);
            __half2 h67 = __floats2half2_rn(v1.z - ADJC, v1.w - ADJC);
            uint4 pk;
            pk.x = *(uint32_t*)&h01; pk.y = *(uint32_t*)&h23;
            pk.z = *(uint32_t*)&h45; pk.w = *(uint32_t*)&h67;
            *(uint4*)(sA + r * 72 + c * 8) = pk;
            *(uint4*)(adjc + (size_t)(m0 + r) * NN + kb + c * 8) = pk;
        }
    };
    auto cpB = [&](int lck, int stg) {
        const int kb = (ck0 + lck) * 64;
        const uint32_t sB = smem_u32(sm + stg * STG_E + PLANE_E);
#pragma unroll
        for (int it = 0; it < 4; it++) {
            const int i = tid + it * 256;
            const int r = i >> 3, c = i & 7;
            CP_ASYNC16(sB + (uint32_t)(r * 72 + c * 8) * 2,
                       Bt + (size_t)r * NN + kb + c * 8);
        }
        CP_COMMIT();
    };

    // prologue
    ldgA(0);
    cvtstA(0, 0);
    cpB(0, 0);
    CP_WAIT0();
    __syncthreads();

    for (int ck = 0; ck < nck; ck++) {
        const int cur = ck & 1;
        const int nxt = cur ^ 1;
        const bool more = (ck + 1) < nck;
        if (more) { ldgA(ck + 1); cpB(ck + 1, nxt); }

        const uint32_t sA = smem_u32(sm + cur * STG_E);
        const uint32_t sB = smem_u32(sm + cur * STG_E + PLANE_E);
#pragma unroll
        for (int ks = 0; ks < 4; ks++) {
            uint32_t af[2][4];
#pragma unroll
            for (int i = 0; i < 2; i++) {
                const int row = wm + i * 16 + (lane & 15);
                const int col = ks * 16 + (lane >> 4) * 8;
                ldsm4(af[i], sA + (uint32_t)(row * 72 + col) * 2);
            }
#pragma unroll
            for (int half = 0; half < 2; half++) {
                uint32_t bf[8];
#pragma unroll
                for (int jp = 0; jp < 2; jp++) {
                    const int g = lane >> 3;
                    const int row = wn + (half * 4 + jp * 2 + (g >> 1)) * 8 + (lane & 7);
                    const int col = ks * 16 + (g & 1) * 8;
                    ldsm4(&bf[jp * 4], sB + (uint32_t)(row * 72 + col) * 2);
                }
#pragma unroll
                for (int i = 0; i < 2; i++)
#pragma unroll
                    for (int t = 0; t < 4; t++)
                        mma16816(acc[i][half * 4 + t], af[i], bf[t * 2], bf[t * 2 + 1]);
            }
        }

        if (more) { cvtstA(ck + 1, nxt); CP_WAIT0(); }
        __syncthreads();
    }

#pragma unroll
    for (int i = 0; i < 2; i++) {
        const int r0 = m0 + wm + i * 16 + (lane >> 2);
#pragma unroll
        for (int j = 0; j < 8; j++) {
            const int cc = wn + j * 8 + (lane & 3) * 2;
            *(float2*)(C + (size_t)r0 * FF + cc) =
                make_float2(acc[i][j][0], acc[i][j][1]);
            *(float2*)(C + (size_t)(r0 + 8) * FF + cc) =
                make_float2(acc[i][j][2], acc[i][j][3]);
        }
    }
}

// ============ general fp16 GEMM (BK=64, 3-stage cp.async) ============
// PASSES==1: C = A @ B^T;  PASSES==3: C = (Ah+Al)@(Bh+Bl)^T (lo*lo dropped)
template <int PASSES, bool BIAS, bool RELU>
__global__ void __launch_bounds__(256, 2)
mma2_k(const __half* __restrict__ A1h, const __half* __restrict__ A1l, int strA1, int nck1,
       const __half* __restrict__ A2h, int strA2,
       const __half* __restrict__ Bh,  const __half* __restrict__ Bl,  int strB,
       float* __restrict__ C, const float* __restrict__ bias, int Ntot,
       int nck, int ck0, size_t zCstride)
{
    constexpr int NA = (PASSES == 3) ? 2 : 1;
    constexpr int NB = (PASSES == 3) ? 2 : 1;
    constexpr int STG_E = (NA + NB) * PLANE_E;
    constexpr int AL_O  = PLANE_E;
    constexpr int B_O   = NA * PLANE_E;
    constexpr int BL_O  = B_O + PLANE_E;

    extern __shared__ __align__(16) __half sm[];
    const int tid  = threadIdx.x;
    const int wid  = tid >> 5;
    const int lane = tid & 31;
    const int m0 = blockIdx.y * 128;
    const int n0 = blockIdx.x * 128;
    const int wm = (wid & 3) * 32;
    const int wn = (wid >> 2) * 64;

    ck0 += blockIdx.z * nck;
    C   += blockIdx.z * zCstride;

    float acc[2][8][4];
#pragma unroll
    for (int i = 0; i < 2; i++)
#pragma unroll
        for (int j = 0; j < 8; j++)
#pragma unroll
            for (int v = 0; v < 4; v++) acc[i][j][v] = 0.f;

    auto loadStage = [&](int lck, int stg) {
        const int g = ck0 + lck;
        const __half* ah;
        int kloc, strA;
        if (g < nck1) { ah = A1h; strA = strA1; kloc = g * 64; }
        else          { ah = A2h; strA = strA2; kloc = (g - nck1) * 64; }
        const uint32_t sA  = smem_u32(sm + stg * STG_E);
        const uint32_t sAl = smem_u32(sm + stg * STG_E + AL_O);
        const uint32_t sBh = smem_u32(sm + stg * STG_E + B_O);
        const uint32_t sBl = smem_u32(sm + stg * STG_E + BL_O);
        const int kb = g * 64;
#pragma unroll
        for (int it = 0; it < 4; it++) {
            const int i = tid + it * 256;
            const int r = i >> 3, c = i & 7;
            const uint32_t so = (uint32_t)(r * 72 + c * 8) * 2;
            CP_ASYNC16(sA + so, ah + (size_t)(m0 + r) * strA + kloc + c * 8);
            if (NA == 2) CP_ASYNC16(sAl + so, A1l + (size_t)(m0 + r) * strA + kloc + c * 8);
            CP_ASYNC16(sBh + so, Bh + (size_t)(n0 + r) * strB + kb + c * 8);
            if (NB == 2) CP_ASYNC16(sBl + so, Bl + (size_t)(n0 + r) * strB + kb + c * 8);
        }
        CP_COMMIT();
    };

    loadStage(0, 0);
    if (nck > 1) loadStage(1, 1); else CP_COMMIT();
    CP_WAIT1();
    __syncthreads();

    for (int ck = 0; ck < nck; ck++) {
        const int stg = ck % 3;
        const uint32_t sA  = smem_u32(sm + stg * STG_E);
        const uint32_t sAl = smem_u32(sm + stg * STG_E + AL_O);
        const uint32_t sBh = smem_u32(sm + stg * STG_E + B_O);
        const uint32_t sBl = smem_u32(sm + stg * STG_E + BL_O);

#pragma unroll
        for (int ks = 0; ks < 4; ks++) {
            uint32_t af[2][4], alf[2][4];
#pragma unroll
            for (int i = 0; i < 2; i++) {
                const int row = wm + i * 16 + (lane & 15);
                const int col = ks * 16 + (lane >> 4) * 8;
                ldsm4(af[i], sA + (uint32_t)(row * 72 + col) * 2);
                if (NA == 2) ldsm4(alf[i], sAl + (uint32_t)(row * 72 + col) * 2);
            }
#pragma unroll
            for (int half = 0; half < 2; half++) {
                uint32_t bh[8], bl[8];
#pragma unroll
                for (int jp = 0; jp < 2; jp++) {
                    const int g = lane >> 3;
                    const int row = wn + (half * 4 + jp * 2 + (g >> 1)) * 8 + (lane & 7);
                    const int col = ks * 16 + (g & 1) * 8;
                    ldsm4(&bh[jp * 4], sBh + (uint32_t)(row * 72 + col) * 2);
                    if (NB == 2) ldsm4(&bl[jp * 4], sBl + (uint32_t)(row * 72 + col) * 2);
                }
#pragma unroll
                for (int i = 0; i < 2; i++)
#pragma unroll
                    for (int t = 0; t < 4; t++)
                        mma16816(acc[i][half * 4 + t], af[i], bh[t * 2], bh[t * 2 + 1]);
                if (NB == 2) {
#pragma unroll
                    for (int i = 0; i < 2; i++)
#pragma unroll
                        for (int t = 0; t < 4; t++)
                            mma16816(acc[i][half * 4 + t], af[i], bl[t * 2], bl[t * 2 + 1]);
                }
                if (NA == 2) {
#pragma unroll
                    for (int i = 0; i < 2; i++)
#pragma unroll
                        for (int t = 0; t < 4; t++)
                            mma16816(acc[i][half * 4 + t], alf[i], bh[t * 2], bh[t * 2 + 1]);
                }
            }
        }

        if (ck + 2 < nck) loadStage(ck + 2, (ck + 2) % 3); else CP_COMMIT();
        CP_WAIT1();
        __syncthreads();
    }

#pragma unroll
    for (int i = 0; i < 2; i++) {
        const int r0 = m0 + wm + i * 16 + (lane >> 2);
#pragma unroll
        for (int j = 0; j < 8; j++) {
            const int cc = n0 + wn + j * 8 + (lane & 3) * 2;
            const size_t o0 = (size_t)r0 * Ntot + cc;
            const size_t o1 = (size_t)(r0 + 8) * Ntot + cc;
            float2 v0 = make_float2(acc[i][j][0], acc[i][j][1]);
            float2 v1 = make_float2(acc[i][j][2], acc[i][j][3]);
            if (BIAS) {
                const float2 bv = *(const float2*)(bias + cc);
                v0.x += bv.x; v0.y += bv.y; v1.x += bv.x; v1.y += bv.y;
            }
            if (RELU) {
                v0.x = fmaxf(v0.x, 0.f); v0.y = fmaxf(v0.y, 0.f);
                v1.x = fmaxf(v1.x, 0.f); v1.y = fmaxf(v1.y, 0.f);
            }
            *(float2*)(C + o0) = v0;
            *(float2*)(C + o1) = v1;
        }
    }
}

// out[c] = addend[c] + scale * sum_r in[r][c]
__global__ void colsum_k(const float* __restrict__ in, int R, int C,
                         float scale, const float* __restrict__ addend,
                         float* __restrict__ out)
{
    __shared__ float red[256];
    const int c = blockIdx.x;
    float s = 0.f;
    for (int r = threadIdx.x; r < R; r += 256) s += in[(size_t)r * C + c];
    red[threadIdx.x] = s;
    __syncthreads();
    for (int o = 128; o > 0; o >>= 1) {
        if (threadIdx.x < o) red[threadIdx.x] += red[threadIdx.x + o];
        __syncthreads();
    }
    if (threadIdx.x == 0) out[c] = (addend ? addend[c] : 0.f) + scale * red[0];
}

// in[R][C] -> hi/lo fp16 into out cols [ooff..)
__global__ void split_into_k(const float* __restrict__ in, __half* __restrict__ oh,
                             __half* __restrict__ ol, int C, int ostr, int ooff)
{
    const int idx = blockIdx.x * blockDim.x + threadIdx.x;
    const int r = idx / C, c = idx - r * C;
    __half h, l;
    split2h(in[idx], h, l);
    oh[(size_t)r * ostr + ooff + c] = h;
    ol[(size_t)r * ostr + ooff + c] = l;
}

// combine 4 split-K partials + bias, write hi/lo fp16 into A1 cols [0,128)
__global__ void combine_ax_k(const float* __restrict__ a0, const float* __restrict__ bias,
                             __half* __restrict__ oh, __half* __restrict__ ol)
{
    const int idx = blockIdx.x * blockDim.x + threadIdx.x;
    const int r = idx >> 7, c = idx & 127;
    const size_t st = (size_t)NN * FF;
    __half h, l;
    split2h((a0[idx] + a0[idx + st]) + (a0[idx + 2 * st] + a0[idx + 3 * st]) + bias[c], h, l);
    oh[(size_t)r * HH + c] = h;
    ol[(size_t)r * HH + c] = l;
}

// combine 2 split-K partials of pre2 + bias + relu
__global__ void combine_pre2_k(const float* __restrict__ p, const float* __restrict__ bias,
                               float* __restrict__ out)
{
    const int idx = blockIdx.x * blockDim.x + threadIdx.x;
    const int c = idx & (HH - 1);
    const float v = p[idx] + p[idx + (size_t)NN * HH] + bias[c];
    out[idx] = fmaxf(v, 0.f);
}

// transpose + single-plane fp16
__global__ void transconv1_k(const float* __restrict__ in, __half* __restrict__ o,
                             int C, int ostr, int koff)
{
    __shared__ float t[32][33];
    const int c0 = blockIdx.x * 32, r0 = blockIdx.y * 32;
    const int tx = threadIdx.x, ty = threadIdx.y;
#pragma unroll
    for (int j = 0; j < 4; j++)
        t[ty + j * 8][tx] = in[(size_t)(r0 + ty + j * 8) * C + c0 + tx];
    __syncthreads();
#pragma unroll
    for (int j = 0; j < 4; j++)
        o[(size_t)(c0 + ty + j * 8) * ostr + koff + r0 + tx] = __float2half_rn(t[tx][ty + j * 8]);
}

// transpose + hi/lo split
__global__ void transconv2_k(const float* __restrict__ in, __half* __restrict__ oh,
                             __half* __restrict__ ol, int C, int ostr, int koff)
{
    __shared__ float t[32][33];
    const int c0 = blockIdx.x * 32, r0 = blockIdx.y * 32;
    const int tx = threadIdx.x, ty = threadIdx.y;
#pragma unroll
    for (int j = 0; j < 4; j++)
        t[ty + j * 8][tx] = in[(size_t)(r0 + ty + j * 8) * C + c0 + tx];
    __syncthreads();
#pragma unroll
    for (int j = 0; j < 4; j++) {
        __half h, l;
        split2h(t[tx][ty + j * 8], h, l);
        const size_t o = (size_t)(c0 + ty + j * 8) * ostr + koff + r0 + tx;
        oh[o] = h; ol[o] = l;
    }
}

// fp32 SGEMM, 64x64 tile (head GEMMs)
template <bool BIAS, bool RELU>
__global__ void __launch_bounds__(256, 3)
sgemm64_k(const float* __restrict__ A, const float* __restrict__ B,
          float* __restrict__ C, const float* __restrict__ bias, int M, int N, int K)
{
    constexpr int BM = 64, BN = 64, BK = 16, TM = 4, TN = 4;
    __shared__ float As[BK][BM];
    __shared__ float Bs[BK][BN];
    const int tid = threadIdx.x;
    const int bx = blockIdx.x, by = blockIdx.y;
    const int aRow = tid >> 2, aCol = (tid & 3) * 4;
    const float* Ag = A + (size_t)(by * BM + aRow) * K + aCol;
    const int bRow = tid >> 4, bCol = (tid & 15) * 4;
    const float* Bg = B + (size_t)bRow * N + bx * BN + bCol;
    const int tr = (tid >> 4) * TM, tc = (tid & 15) * TN;

    float acc[TM][TN];
#pragma unroll
    for (int i = 0; i < TM; i++)
#pragma unroll
        for (int j = 0; j < TN; j++) acc[i][j] = 0.f;

    for (int k0 = 0; k0 < K; k0 += BK) {
        float4 a0 = *(const float4*)(Ag + k0);
        As[aCol + 0][aRow] = a0.x;  As[aCol + 1][aRow] = a0.y;
        As[aCol + 2][aRow] = a0.z;  As[aCol + 3][aRow] = a0.w;
        *(float4*)&Bs[bRow][bCol] = *(const float4*)(Bg + (size_t)k0 * N);
        __syncthreads();
#pragma unroll
        for (int k = 0; k < BK; k++) {
            float ra[TM], rb[TN];
#pragma unroll
            for (int i = 0; i < TM; i++) ra[i] = As[k][tr + i];
#pragma unroll
            for (int j = 0; j < TN; j++) rb[j] = Bs[k][tc + j];
#pragma unroll
            for (int i = 0; i < TM; i++)
#pragma unroll
                for (int j = 0; j < TN; j++) acc[i][j] = fmaf(ra[i], rb[j], acc[i][j]);
        }
        __syncthreads();
    }
    float4 bv = make_float4(0.f, 0.f, 0.f, 0.f);
    if (BIAS) bv = *(const float4*)(bias + bx * BN + tc);
#pragma unroll
    for (int i = 0; i < TM; i++) {
        const size_t off = (size_t)(by * BM + tr + i) * N + bx * BN + tc;
        float4 v = make_float4(acc[i][0], acc[i][1], acc[i][2], acc[i][3]);
        if (BIAS) { v.x += bv.x; v.y += bv.y; v.z += bv.z; v.w += bv.w; }
        if (RELU) {
            v.x = fmaxf(v.x, 0.f); v.y = fmaxf(v.y, 0.f);
            v.z = fmaxf(v.z, 0.f); v.w = fmaxf(v.w, 0.f);
        }
        *(float4*)(C + off) = v;
    }
}

// BatchNorm partials: 256 blocks x 32 rows
__global__ void bn_partial_k(const float* __restrict__ x, float* __restrict__ psum,
                             float* __restrict__ psq)
{
    const int t = threadIdx.x;
    const float* p = x + (size_t)blockIdx.x * 32 * HH + t;
    float s = 0.f, q = 0.f;
#pragma unroll 4
    for (int r = 0; r < 32; r++) { float v = p[(size_t)r * HH]; s += v; q += v * v; }
    psum[blockIdx.x * HH + t] = s;
    psq [blockIdx.x * HH + t] = q;
}

__global__ void bn_finalize_k(const float* __restrict__ psum, const float* __restrict__ psq,
                              const float* __restrict__ gamma, const float* __restrict__ beta,
                              float* __restrict__ scale, float* __restrict__ shift)
{
    const int t = threadIdx.x;
    float s = 0.f, q = 0.f;
#pragma unroll 8
    for (int b = 0; b < 256; b++) { s += psum[b * HH + t]; q += psq[b * HH + t]; }
    const float invn = 1.f / (float)NN;
    const float m = s * invn;
    const float var = q * invn - m * m;
    const float sc = gamma[t] * rsqrtf(var + EPSB);
    scale[t] = sc;
    shift[t] = beta[t] - m * sc;
}

template <bool CVT>
__global__ void bn_apply_k(float* __restrict__ x, const float* __restrict__ scale,
                           const float* __restrict__ shift,
                           __half* __restrict__ oh, __half* __restrict__ ol)
{
    const int i = blockIdx.x * blockDim.x + threadIdx.x;
    const int c = (i * 4) & (HH - 1);
    float4 v = ((float4*)x)[i];
    v.x = fmaf(v.x, scale[c + 0], shift[c + 0]);
    v.y = fmaf(v.y, scale[c + 1], shift[c + 1]);
    v.z = fmaf(v.z, scale[c + 2], shift[c + 2]);
    v.w = fmaf(v.w, scale[c + 3], shift[c + 3]);
    ((float4*)x)[i] = v;
    if (CVT) {
        __half h0, h1, h2, h3, l0, l1, l2, l3;
        split2h(v.x, h0, l0); split2h(v.y, h1, l1);
        split2h(v.z, h2, l2); split2h(v.w, h3, l3);
        __half2 ph0 = __halves2half2(h0, h1), ph1 = __halves2half2(h2, h3);
        __half2 pl0 = __halves2half2(l0, l1), pl1 = __halves2half2(l2, l3);
        uint2 hp, lp;
        hp.x = *(uint32_t*)&ph0; hp.y = *(uint32_t*)&ph1;
        lp.x = *(uint32_t*)&pl0; lp.y = *(uint32_t*)&pl1;
        ((uint2*)oh)[i] = hp;
        ((uint2*)ol)[i] = lp;
    }
}

__global__ void pool_k(const float* __restrict__ h1, const float* __restrict__ h2,
                       float* __restrict__ pooled)
{
    const int g = blockIdx.x, t = threadIdx.x;
    const size_t r0 = (size_t)g * NPG;
    float mx1 = -1e30f, mx2 = -1e30f, s1 = 0.f, s2 = 0.f;
#pragma unroll 4
    for (int r = 0; r < NPG; r++) {
        float v1 = h1[(r0 + r) * HH + t];
        float v2 = h2[(r0 + r) * HH + t];
        mx1 = fmaxf(mx1, v1); s1 += v1;
        mx2 = fmaxf(mx2, v2); s2 += v2;
    }
    float* out = pooled + (size_t)g * 1024;
    out[t]       = mx1;
    out[256 + t] = mx2;
    out[512 + t] = s1 * (1.f / NPG);
    out[768 + t] = s2 * (1.f / NPG);
}

// small BN: one block per 32 columns, block (32,8)
__global__ void bn_small_k(const float* __restrict__ in, const float* __restrict__ gamma,
                           const float* __restrict__ beta, float* __restrict__ out, int C)
{
    __shared__ float ssum[8][32], ssq[8][32], ssc[32], ssh[32];
    const int tx = threadIdx.x, ty = threadIdx.y;
    const int c = blockIdx.x * 32 + tx;
    float s = 0.f, q = 0.f;
    for (int r = ty; r < GG; r += 8) {
        const float v = in[(size_t)r * C + c];
        s += v; q += v * v;
    }
    ssum[ty][tx] = s; ssq[ty][tx] = q;
    __syncthreads();
    if (ty == 0) {
        float S = 0.f, Q = 0.f;
#pragma unroll
        for (int k = 0; k < 8; k++) { S += ssum[k][tx]; Q += ssq[k][tx]; }
        const float m = S * (1.f / GG);
        const float var = Q * (1.f / GG) - m * m;
        const float sc = gamma[c] * rsqrtf(var + EPSB);
        ssc[tx] = sc;
        ssh[tx] = beta[c] - m * sc;
    }
    __syncthreads();
    const float sc = ssc[tx], sh = ssh[tx];
    for (int r = ty; r < GG; r += 8)
        out[(size_t)r * C + c] = fmaf(in[(size_t)r * C + c], sc, sh);
}

__global__ void dense_small_k(const float* __restrict__ A, const float* __restrict__ W,
                              const float* __restrict__ b, float* __restrict__ C,
                              int M, int N, int K)
{
    const int idx = blockIdx.x * blockDim.x + threadIdx.x;
    if (idx >= M * N) return;
    const int m = idx / N, n = idx - m * N;
    float acc = b[n];
    const float* a = A + (size_t)m * K;
    for (int k = 0; k < K; k++) acc = fmaf(a[k], W[(size_t)k * N + n], acc);
    C[idx] = acc;
}

extern "C" void kernel_launch(void* const* d_in, const int* in_sizes, int n_in,
                              void* d_out, int out_size)
{
    const float* x    = (const float*)d_in[0];
    const float* adj  = (const float*)d_in[1];
    const float* W1   = (const float*)d_in[3];
    const float* Ws1  = (const float*)d_in[4];
    const float* b1   = (const float*)d_in[5];
    const float* g1   = (const float*)d_in[6];
    const float* be1  = (const float*)d_in[7];
    const float* W2   = (const float*)d_in[8];
    const float* Ws2  = (const float*)d_in[9];
    const float* b2   = (const float*)d_in[10];
    const float* g2   = (const float*)d_in[11];
    const float* be2  = (const float*)d_in[12];
    const float* bn0g = (const float*)d_in[13];
    const float* bn0b = (const float*)d_in[14];
    const float* L1W  = (const float*)d_in[15];
    const float* L1b  = (const float*)d_in[16];
    const float* bn1g = (const float*)d_in[17];
    const float* bn1b = (const float*)d_in[18];
    const float* L2W  = (const float*)d_in[19];
    const float* L2b  = (const float*)d_in[20];
    const float* bn2g = (const float*)d_in[21];
    const float* bn2b = (const float*)d_in[22];
    const float* L3W  = (const float*)d_in[23];
    const float* L3b  = (const float*)d_in[24];
    const float* catW = (const float*)d_in[25];
    const float* catb = (const float*)d_in[26];

    float* out = (float*)d_out;
    float* out_main  = out;
    float* out_class = out + 256 * 128;
    float* out_fp    = out + 256 * 128 + 256 * 12;

    __half *adjc, *xTh, *A1h, *A1l, *B1h, *B1l, *h1h, *h1l, *W2Th, *W2Tl, *B2h;
    float *axp, *p2p, *biasax, *bias2, *pre1, *g2in, *pre2, *pool, *bnp, *l1, *bn1, *l2;
    float *psum, *psq, *scale, *shift;
    cudaGetSymbolAddress((void**)&adjc,  g_adjc);
    cudaGetSymbolAddress((void**)&xTh,   g_xT_h);
    cudaGetSymbolAddress((void**)&axp,   g_axp);
    cudaGetSymbolAddress((void**)&p2p,   g_p2p);
    cudaGetSymbolAddress((void**)&biasax,g_biasax);
    cudaGetSymbolAddress((void**)&bias2, g_bias2);
    cudaGetSymbolAddress((void**)&A1h,   g_A1_h);
    cudaGetSymbolAddress((void**)&A1l,   g_A1_l);
    cudaGetSymbolAddress((void**)&B1h,   g_B1_h);
    cudaGetSymbolAddress((void**)&B1l,   g_B1_l);
    cudaGetSymbolAddress((void**)&pre1,  g_pre1);
    cudaGetSymbolAddress((void**)&h1h,   g_h1_h);
    cudaGetSymbolAddress((void**)&h1l,   g_h1_l);
    cudaGetSymbolAddress((void**)&W2Th,  g_W2T_h);
    cudaGetSymbolAddress((void**)&W2Tl,  g_W2T_l);
    cudaGetSymbolAddress((void**)&g2in,  g_g2in);
    cudaGetSymbolAddress((void**)&B2h,   g_B2_h);
    cudaGetSymbolAddress((void**)&pre2,  g_pre2);
    cudaGetSymbolAddress((void**)&pool,  g_pool);
    cudaGetSymbolAddress((void**)&bnp,   g_bnp);
    cudaGetSymbolAddress((void**)&l1,    g_l1);
    cudaGetSymbolAddress((void**)&bn1,   g_bn1);
    cudaGetSymbolAddress((void**)&l2,    g_l2);
    cudaGetSymbolAddress((void**)&psum,  g_psum);
    cudaGetSymbolAddress((void**)&psq,   g_psq);
    cudaGetSymbolAddress((void**)&scale, g_scale);
    cudaGetSymbolAddress((void**)&shift, g_shift);

    static bool attr_done = false;
    if (!attr_done) {
        cudaFuncSetAttribute(axcvt_k, cudaFuncAttributeMaxDynamicSharedMemorySize, 73728);
        cudaFuncSetAttribute(mma2_k<1, false, false>, cudaFuncAttributeMaxDynamicSharedMemorySize, 110592);
        cudaFuncSetAttribute(mma2_k<3, false, false>, cudaFuncAttributeMaxDynamicSharedMemorySize, 221184);
        cudaFuncSetAttribute(mma2_k<3, true, true>,   cudaFuncAttributeMaxDynamicSharedMemorySize, 221184);
        attr_done = true;
    }

    // prep (no standalone adj conversion; fused into axcvt_k)
    transconv1_k<<<dim3(FF / 32, NN / 32), dim3(32, 8)>>>(x, xTh, FF, NN, 0);
    split_into_k<<<NN * FF / 256, 256>>>(x, A1h, A1l, FF, HH, FF);
    transconv2_k<<<dim3(HH / 32, FF / 32), dim3(32, 8)>>>(W1,  B1h, B1l, HH, HH, 0);
    transconv2_k<<<dim3(HH / 32, FF / 32), dim3(32, 8)>>>(Ws1, B1h, B1l, HH, HH, FF);
    transconv2_k<<<dim3(HH / 32, HH / 32), dim3(32, 8)>>>(W2,  W2Th, W2Tl, HH, HH, 0);
    transconv1_k<<<dim3(HH / 32, HH / 32), dim3(32, 8)>>>(Ws2, B2h, HH, K2TOT, NN);
    colsum_k<<<FF, 256>>>(x, NN, FF, ADJC, (const float*)0, biasax);

    // layer 1: ax = (adj - 1/64) @ x with FUSED conversion (writes adjc); split-K4 via z
    axcvt_k<<<dim3(1, NN / 128, 4), 256, 73728>>>(adj, adjc, xTh, axp, 32, (size_t)NN * FF);
    combine_ax_k<<<NN * FF / 256, 256>>>(axp, biasax, A1h, A1l);
    // pre1 = relu([ax|x] @ [W1;Ws1]^T + b1)  (3-pass)
    mma2_k<3, true, true><<<dim3(2, NN / 128), 256, 221184>>>(
        A1h, A1l, HH, BIGK, (const __half*)0, 0, B1h, B1l, HH,
        pre1, b1, HH, 4, 0, 0);
    bn_partial_k<<<256, 256>>>(pre1, psum, psq);
    bn_finalize_k<<<1, 256>>>(psum, psq, g1, be1, scale, shift);
    bn_apply_k<true><<<(NN * HH / 4) / 256, 256>>>(pre1, scale, shift, h1h, h1l);

    // layer 2: g2in = h1 @ W2 (3-pass)
    mma2_k<3, false, false><<<dim3(2, NN / 128), 256, 221184>>>(
        h1h, h1l, HH, BIGK, (const __half*)0, 0, W2Th, W2Tl, HH,
        g2in, (const float*)0, HH, 4, 0, 0);
    transconv1_k<<<dim3(HH / 32, NN / 32), dim3(32, 8)>>>(g2in, B2h, HH, K2TOT, 0);
    colsum_k<<<HH, 256>>>(g2in, NN, HH, ADJC, b2, bias2);
    // pre2 partials (single-pass, BK=64, split-K2 via z), then combine + bias + relu
    mma2_k<1, false, false><<<dim3(2, NN / 128, 2), 256, 110592>>>(
        adjc, (const __half*)0, NN, NN / 64, h1h, HH, B2h, (const __half*)0, K2TOT,
        p2p, (const float*)0, HH, K2TOT / 128, 0, (size_t)NN * HH);
    combine_pre2_k<<<NN * HH / 256, 256>>>(p2p, bias2, pre2);
    bn_partial_k<<<256, 256>>>(pre2, psum, psq);
    bn_finalize_k<<<1, 256>>>(psum, psq, g2, be2, scale, shift);
    bn_apply_k<false><<<(NN * HH / 4) / 256, 256>>>(pre2, scale, shift, (__half*)0, (__half*)0);

    // pooling
    pool_k<<<GG, 256>>>(pre1, pre2, pool);

    // MLP head
    bn_small_k<<<1024 / 32, dim3(32, 8)>>>(pool, bn0g, bn0b, bnp, 1024);
    sgemm64_k<true, true><<<dim3(512 / 64, GG / 64), 256>>>(bnp, L1W, l1, L1b, GG, 512, 1024);
    bn_small_k<<<512 / 32, dim3(32, 8)>>>(l1, bn1g, bn1b, bn1, 512);
    sgemm64_k<true, true><<<dim3(256 / 64, GG / 64), 256>>>(bn1, L2W, l2, L2b, GG, 256, 512);
    bn_small_k<<<256 / 32, dim3(32, 8)>>>(l2, bn2g, bn2b, out_fp, 256);
    dense_small_k<<<(256 * 128 + 255) / 256, 256>>>(out_fp, L3W, L3b, out_main, 256, 128, 256);
    dense_small_k<<<(256 * 12 + 255) / 256, 256>>>(out_fp, catW, catb, out_class, 256, 12, 256);

    (void)in_sizes; (void)n_in; (void)out_size;
}